// round 1
// baseline (speedup 1.0000x reference)
#include <cuda_runtime.h>
#include <math.h>

#define Bb   128
#define Hh   1024
#define HH2  512
#define Vv   32000
#define Ll   2
#define MAXW 21
#define WSZF 10.0f

// output layout (concatenated tuple: y, o2, h_new, c_new, a)
#define Y_OFF  0
#define O2_OFF (Bb*Vv)
#define H_OFF  (O2_OFF + Bb*Hh)
#define C_OFF  (H_OFF + Ll*Bb*Hh)
#define A_OFF  (C_OFF + Ll*Bb*Hh)

// scratch (device globals — no allocation allowed)
__device__ float g_x[Bb*Hh];
__device__ float g_gates[Bb*4*Hh];
__device__ float g_t[Bb*HH2];
__device__ float g_pb[Bb];
__device__ float g_ctx[Bb*Hh];
__device__ float g_cat[Bb*2*Hh];

__device__ __forceinline__ float sigm(float x) { return 1.0f / (1.0f + expf(-x)); }

// ---------------------------------------------------------------------------
// embedding gather: x[b,h] = emb[word[b], h]
__global__ void k_embed(const float* __restrict__ emb, const int* __restrict__ word) {
    int i = blockIdx.x * blockDim.x + threadIdx.x;   // B*H
    int b = i >> 10, h = i & 1023;
    g_x[i] = emb[(long)word[b] * Hh + h];
}

// ---------------------------------------------------------------------------
// Generic fp32 GEMM: C[M,N] = act(A[M,K] @ W[N,K]^T + bias (+ C if ACCUM))
// BM=BN=64, BK=16, 256 threads, 4x4 microtile.
template<int ACT, int ACCUM>
__global__ void gemm64(const float* __restrict__ A, const float* __restrict__ W,
                       const float* __restrict__ bias, float* __restrict__ C,
                       int N, int K) {
    __shared__ float As[16][64];
    __shared__ float Bs[16][64];
    int tid = threadIdx.x;
    int m0 = blockIdx.y * 64, n0 = blockIdx.x * 64;
    int ty = tid >> 4, tx = tid & 15;
    int lr = tid >> 2;          // 0..63
    int lc = (tid & 3) * 4;     // 0,4,8,12
    float acc[4][4] = {};
    for (int kb = 0; kb < K; kb += 16) {
        float4 av = *(const float4*)&A[(long)(m0 + lr) * K + kb + lc];
        float4 wv = *(const float4*)&W[(long)(n0 + lr) * K + kb + lc];
        As[lc+0][lr] = av.x; As[lc+1][lr] = av.y; As[lc+2][lr] = av.z; As[lc+3][lr] = av.w;
        Bs[lc+0][lr] = wv.x; Bs[lc+1][lr] = wv.y; Bs[lc+2][lr] = wv.z; Bs[lc+3][lr] = wv.w;
        __syncthreads();
        #pragma unroll
        for (int k = 0; k < 16; k++) {
            float a[4], b[4];
            #pragma unroll
            for (int i = 0; i < 4; i++) a[i] = As[k][ty*4 + i];
            #pragma unroll
            for (int j = 0; j < 4; j++) b[j] = Bs[k][tx*4 + j];
            #pragma unroll
            for (int i = 0; i < 4; i++)
                #pragma unroll
                for (int j = 0; j < 4; j++)
                    acc[i][j] += a[i] * b[j];
        }
        __syncthreads();
    }
    #pragma unroll
    for (int i = 0; i < 4; i++) {
        int m = m0 + ty*4 + i;
        #pragma unroll
        for (int j = 0; j < 4; j++) {
            int n = n0 + tx*4 + j;
            float v = acc[i][j] + (bias ? bias[n] : 0.0f);
            if (ACCUM) v += C[(long)m * N + n];
            if (ACT == 1) v = tanhf(v);
            C[(long)m * N + n] = v;
        }
    }
}

// ---------------------------------------------------------------------------
// Big GEMM for fc2: 128x128 tile, BK=8, 256 threads, 8x8 microtile.
__global__ void gemm128(const float* __restrict__ A, const float* __restrict__ W,
                        const float* __restrict__ bias, float* __restrict__ C,
                        int N, int K) {
    __shared__ float As[8][128];
    __shared__ float Bs[8][128];
    int tid = threadIdx.x;
    int m0 = blockIdx.y * 128, n0 = blockIdx.x * 128;
    int ty = tid >> 4, tx = tid & 15;
    int lr = tid >> 1;          // 0..127
    int lc = (tid & 1) * 4;     // 0 or 4
    float acc[8][8] = {};
    for (int kb = 0; kb < K; kb += 8) {
        float4 av = *(const float4*)&A[(long)(m0 + lr) * K + kb + lc];
        float4 wv = *(const float4*)&W[(long)(n0 + lr) * K + kb + lc];
        As[lc+0][lr] = av.x; As[lc+1][lr] = av.y; As[lc+2][lr] = av.z; As[lc+3][lr] = av.w;
        Bs[lc+0][lr] = wv.x; Bs[lc+1][lr] = wv.y; Bs[lc+2][lr] = wv.z; Bs[lc+3][lr] = wv.w;
        __syncthreads();
        #pragma unroll
        for (int k = 0; k < 8; k++) {
            float a[8], b[8];
            #pragma unroll
            for (int i = 0; i < 8; i++) a[i] = As[k][ty*8 + i];
            #pragma unroll
            for (int j = 0; j < 8; j++) b[j] = Bs[k][tx*8 + j];
            #pragma unroll
            for (int i = 0; i < 8; i++)
                #pragma unroll
                for (int j = 0; j < 8; j++)
                    acc[i][j] += a[i] * b[j];
        }
        __syncthreads();
    }
    #pragma unroll
    for (int i = 0; i < 8; i++) {
        long m = m0 + ty*8 + i;
        #pragma unroll
        for (int j = 0; j < 8; j++) {
            int n = n0 + tx*8 + j;
            C[m * N + n] = acc[i][j] + bias[n];
        }
    }
}

// ---------------------------------------------------------------------------
// LSTM cell elementwise: gates (B,4H) + c_prev -> c,h (write into d_out regions)
__global__ void k_lstm_cell(const float* __restrict__ c_prev,
                            float* __restrict__ c_out, float* __restrict__ h_out) {
    int i = blockIdx.x * blockDim.x + threadIdx.x;   // B*H
    int b = i >> 10, h = i & 1023;
    const float* g = g_gates + (long)b * 4 * Hh;
    float ig = sigm(g[h]);
    float fg = sigm(g[Hh + h]);
    float gg = tanhf(g[2*Hh + h]);
    float og = sigm(g[3*Hh + h]);
    float c = fg * c_prev[i] + ig * gg;
    c_out[i] = c;
    h_out[i] = og * tanhf(c);
}

// ---------------------------------------------------------------------------
// pb[b] = S * sigmoid( sum_j tanh_t[b,j]*w2[j] + b2 )
__global__ void k_attn_p(const float* __restrict__ w2, const float* __restrict__ b2, int S) {
    int b = blockIdx.x, tid = threadIdx.x;
    __shared__ float red[256];
    float s = 0.0f;
    for (int j = tid; j < HH2; j += 256) s += g_t[b*HH2 + j] * w2[j];
    red[tid] = s; __syncthreads();
    for (int st = 128; st > 0; st >>= 1) {
        if (tid < st) red[tid] += red[tid + st];
        __syncthreads();
    }
    if (tid == 0) g_pb[b] = (float)S * sigm(red[0] + b2[0]);
}

// ---------------------------------------------------------------------------
// Windowed attention: scores, softmax*gauss, a (-> d_out), ctx (-> scratch)
__global__ void k_attn_ctx(const float* __restrict__ hout, const float* __restrict__ enc,
                           int S, float* __restrict__ a_out) {
    int b = blockIdx.x, tid = threadIdx.x;
    int warp = tid >> 5, lane = tid & 31;
    float pb = g_pb[b];
    int ws = (int)rintf(fmaxf(pb - WSZF, 0.0f));
    int we = (int)rintf(fminf(pb + WSZF, (float)(S - 1)));
    __shared__ float sc[MAXW], ga[MAXW], aa[MAXW];

    for (int w = warp; w < MAXW; w += 8) {
        int idx = ws + w;
        if (idx <= we) {
            int ic = min(idx, S - 1);
            const float* er = enc + ((long)ic * Bb + b) * Hh;
            const float* orow = hout + (long)b * Hh;
            float dot = 0.0f;
            for (int h = lane; h < Hh; h += 32) dot += orow[h] * er[h];
            #pragma unroll
            for (int o = 16; o > 0; o >>= 1) dot += __shfl_down_sync(0xffffffff, dot, o);
            if (lane == 0) {
                sc[w] = dot;
                ga[w] = expf(((float)idx - pb) / 50.0f);   // 2*std2 = 2*(10/2)^2 = 50
            }
        } else if (lane == 0) {
            sc[w] = 0.0f;   // h_s zeroed -> score 0, still in softmax
            ga[w] = 0.0f;
        }
    }
    __syncthreads();
    if (tid < MAXW) {
        float m = -1e30f;
        for (int w = 0; w < MAXW; w++) m = fmaxf(m, sc[w]);
        float den = 0.0f;
        for (int w = 0; w < MAXW; w++) den += expf(sc[w] - m);
        float a = expf(sc[tid] - m) / den * ga[tid];
        aa[tid] = a;
        a_out[b * MAXW + tid] = a;
    }
    __syncthreads();
    for (int h = tid; h < Hh; h += blockDim.x) {
        float s = 0.0f;
        for (int w = 0; w < MAXW; w++) {
            int idx = ws + w;
            if (idx <= we)
                s += aa[w] * enc[((long)idx * Bb + b) * Hh + h];
        }
        g_ctx[b*Hh + h] = s;
    }
}

// ---------------------------------------------------------------------------
// cat = [ctx, out]
__global__ void k_cat(const float* __restrict__ hout) {
    int i = blockIdx.x * blockDim.x + threadIdx.x;   // B*2H
    int b = i >> 11, r = i & 2047;
    g_cat[i] = (r < Hh) ? g_ctx[b*Hh + r] : hout[(long)b*Hh + r - Hh];
}

// ---------------------------------------------------------------------------
// In-place log-softmax over V per row
__global__ void k_logsoftmax(float* __restrict__ y) {
    int b = blockIdx.x, tid = threadIdx.x;
    float* row = y + (long)b * Vv;
    __shared__ float red[256];
    float m = -1e30f;
    for (int j = tid; j < Vv; j += 256) m = fmaxf(m, row[j]);
    red[tid] = m; __syncthreads();
    for (int st = 128; st > 0; st >>= 1) {
        if (tid < st) red[tid] = fmaxf(red[tid], red[tid + st]);
        __syncthreads();
    }
    m = red[0]; __syncthreads();
    float s = 0.0f;
    for (int j = tid; j < Vv; j += 256) s += expf(row[j] - m);
    red[tid] = s; __syncthreads();
    for (int st = 128; st > 0; st >>= 1) {
        if (tid < st) red[tid] += red[tid + st];
        __syncthreads();
    }
    float lse = m + logf(red[0]);
    __syncthreads();
    for (int j = tid; j < Vv; j += 256) row[j] -= lse;
}

// ---------------------------------------------------------------------------
extern "C" void kernel_launch(void* const* d_in, const int* in_sizes, int n_in,
                              void* d_out, int out_size) {
    const float* enc  = (const float*)d_in[1];
    const int*   word = (const int*)  d_in[2];
    const float* h0   = (const float*)d_in[3];
    const float* c0   = (const float*)d_in[4];
    const float* emb  = (const float*)d_in[5];
    const float* Wih  = (const float*)d_in[6];
    const float* Whh  = (const float*)d_in[7];
    const float* bih  = (const float*)d_in[8];
    const float* bhh  = (const float*)d_in[9];
    const float* aw1  = (const float*)d_in[10];
    const float* ab1  = (const float*)d_in[11];
    const float* aw2  = (const float*)d_in[12];
    const float* ab2  = (const float*)d_in[13];
    const float* f1w  = (const float*)d_in[14];
    const float* f1b  = (const float*)d_in[15];
    const float* f2w  = (const float*)d_in[16];
    const float* f2b  = (const float*)d_in[17];

    int S = in_sizes[1] / (Bb * Hh);   // robust: encoder_output is (S,B,H)

    float* out = (float*)d_out;
    float* y   = out + Y_OFF;
    float* o2  = out + O2_OFF;
    float* hN  = out + H_OFF;
    float* cN  = out + C_OFF;
    float* aO  = out + A_OFF;

    // scratch symbol addresses (host side, once)
    static float *p_x = nullptr, *p_gates = nullptr, *p_t = nullptr, *p_cat = nullptr;
    if (!p_x) {
        cudaGetSymbolAddress((void**)&p_x,     g_x);
        cudaGetSymbolAddress((void**)&p_gates, g_gates);
        cudaGetSymbolAddress((void**)&p_t,     g_t);
        cudaGetSymbolAddress((void**)&p_cat,   g_cat);
    }

    // 1. embedding
    k_embed<<<(Bb*Hh)/256, 256>>>(emb, word);

    // 2. LSTM layers
    const float* x_in = p_x;
    for (int l = 0; l < Ll; l++) {
        const float* wih = Wih + (long)l * 4*Hh*Hh;
        const float* whh = Whh + (long)l * 4*Hh*Hh;
        const float* bi  = bih + (long)l * 4*Hh;
        const float* bh  = bhh + (long)l * 4*Hh;
        dim3 g(4*Hh/64, Bb/64);
        gemm64<0,0><<<g, 256>>>(x_in,           wih, bi, p_gates, 4*Hh, Hh);
        gemm64<0,1><<<g, 256>>>(h0 + (long)l*Bb*Hh, whh, bh, p_gates, 4*Hh, Hh);
        k_lstm_cell<<<(Bb*Hh)/256, 256>>>(c0 + (long)l*Bb*Hh,
                                          cN + (long)l*Bb*Hh,
                                          hN + (long)l*Bb*Hh);
        x_in = hN + (long)l*Bb*Hh;
    }
    const float* hout = hN + (long)(Ll-1)*Bb*Hh;   // decoder output "out"

    // 3. attention position
    gemm64<1,0><<<dim3(HH2/64, Bb/64), 256>>>(hout, aw1, ab1, p_t, HH2, Hh);
    k_attn_p<<<Bb, 256>>>(aw2, ab2, S);

    // 4. windowed attention -> a, ctx
    k_attn_ctx<<<Bb, 256>>>(hout, enc, S, aO);

    // 5. fc1
    k_cat<<<(Bb*2*Hh)/256, 256>>>(hout);
    gemm64<1,0><<<dim3(Hh/64, Bb/64), 256>>>(p_cat, f1w, f1b, o2, Hh, 2*Hh);

    // 6. fc2 + log-softmax
    gemm128<<<dim3(Vv/128, Bb/128), 256>>>(o2, f2w, f2b, y, Vv, Hh);
    k_logsoftmax<<<Bb, 256>>>(y);
}

// round 3
// speedup vs baseline: 3.1276x; 3.1276x over previous
#include <cuda_runtime.h>
#include <math.h>
#include <stdint.h>

#define Bb   128
#define Hh   1024
#define HH2  512
#define Vv   32000
#define Ll   2
#define MAXW 21
#define WSZF 10.0f

// output layout (concatenated tuple: y, o2, h_new, c_new, a)
#define Y_OFF  0
#define O2_OFF (Bb*Vv)
#define H_OFF  (O2_OFF + Bb*Hh)
#define C_OFF  (H_OFF + Ll*Bb*Hh)
#define A_OFF  (C_OFF + Ll*Bb*Hh)

// scratch (device globals — no allocation allowed)
__device__ float g_x[Bb*Hh];
__device__ float g_gates[Bb*4*Hh];
__device__ float g_t[Bb*HH2];
__device__ float g_pb[Bb];
__device__ float g_ctx[Bb*Hh];
__device__ float g_cat[Bb*2*Hh];

__device__ __forceinline__ float sigm(float x) { return 1.0f / (1.0f + expf(-x)); }

// ---------------------------------------------------------------------------
// async-copy / mma helpers
__device__ __forceinline__ void cp16(uint32_t dst, const float* src) {
    asm volatile("cp.async.cg.shared.global [%0], [%1], 16;"
                 :: "r"(dst), "l"(__cvta_generic_to_global(src)));
}
__device__ __forceinline__ void ldm_x4(uint32_t* r, uint32_t addr) {
    asm volatile("ldmatrix.sync.aligned.m8n8.x4.shared.b16 {%0,%1,%2,%3}, [%4];"
                 : "=r"(r[0]), "=r"(r[1]), "=r"(r[2]), "=r"(r[3]) : "r"(addr));
}
__device__ __forceinline__ void cvt_tf32(uint32_t& x) {
    asm volatile("cvt.rna.tf32.f32 %0, %0;" : "+r"(x));
}
__device__ __forceinline__ void mma_tf32(float* d, const uint32_t* a, const uint32_t* b) {
    asm volatile("mma.sync.aligned.m16n8k8.row.col.f32.tf32.tf32.f32 "
                 "{%0,%1,%2,%3}, {%4,%5,%6,%7}, {%8,%9}, {%0,%1,%2,%3};"
                 : "+f"(d[0]), "+f"(d[1]), "+f"(d[2]), "+f"(d[3])
                 : "r"(a[0]), "r"(a[1]), "r"(a[2]), "r"(a[3]),
                   "r"(b[0]), "r"(b[1]));
}

// swizzled byte offset of 16B chunk (row stride 128B, 8 chunks/row)
__device__ __forceinline__ uint32_t swz(int row, int chunk) {
    return (uint32_t)(row * 128 + ((chunk ^ (row & 7)) << 4));
}

// ---------------------------------------------------------------------------
// Stage a K-chunk of 32 fp32 cols: A[128 rows], W[BN rows] -> swizzled SMEM.
template<int BN, int NSRC>
__device__ __forceinline__ void g_load(
    uint32_t abase, const float* __restrict__ A0, const float* __restrict__ W0,
    const float* __restrict__ A1, const float* __restrict__ W1,
    int it, int KPC, int K, int n0, int tid)
{
    const float* A = (NSRC == 2 && it >= KPC) ? A1 : A0;
    const float* W = (NSRC == 2 && it >= KPC) ? W1 : W0;
    int kb = ((NSRC == 2 && it >= KPC) ? it - KPC : it) * 32;
    uint32_t bbase = abase + 128 * 128;
    #pragma unroll
    for (int i = 0; i < 4; i++) {               // A: 128 rows x 8 chunks
        int idx = tid + i * 256;
        int r = idx >> 3, c = idx & 7;
        cp16(abase + swz(r, c), A + (long)r * K + kb + c * 4);
    }
    #pragma unroll
    for (int i = 0; i < BN * 8 / 256; i++) {    // B: BN rows x 8 chunks
        int idx = tid + i * 256;
        int r = idx >> 3, c = idx & 7;
        cp16(bbase + swz(r, c), W + (long)(n0 + r) * K + kb + c * 4);
    }
}

// ---------------------------------------------------------------------------
// tf32 mma.sync GEMM: C[128, N] = act( sum_s A_s[128,K] @ W_s[N,K]^T + biases )
// BM=128 (whole batch), BN per CTA, BK=32, 3-stage cp.async pipeline.
template<int BN, int NSRC, int ACT>
__global__ void __launch_bounds__(256, 1) k_gemm_mma(
    const float* __restrict__ A0, const float* __restrict__ W0,
    const float* __restrict__ A1, const float* __restrict__ W1,
    const float* __restrict__ bias0, const float* __restrict__ bias1,
    float* __restrict__ C, int N, int K)
{
    extern __shared__ char sm[];
    constexpr int STAGE = (128 + BN) * 32 * 4;
    constexpr int WN  = (BN == 128) ? 4 : 2;    // warps along N
    constexpr int WTM = (BN == 128) ? 64 : 32;  // warp tile M
    constexpr int MT  = WTM / 16;               // m16 tiles per warp

    uint32_t smb = (uint32_t)__cvta_generic_to_shared(sm);
    int tid = threadIdx.x, lane = tid & 31, w = tid >> 5;
    int wm = w / WN, wn = w % WN;
    int n0 = blockIdx.x * BN;
    int KPC = K / 32, NITER = NSRC * KPC;

    float acc[MT][4][4];
    #pragma unroll
    for (int i = 0; i < MT; i++)
        #pragma unroll
        for (int j = 0; j < 4; j++)
            #pragma unroll
            for (int k = 0; k < 4; k++) acc[i][j][k] = 0.0f;

    // prefetch 3 stages
    #pragma unroll
    for (int s = 0; s < 3; s++) {
        if (s < NITER) g_load<BN, NSRC>(smb + s * STAGE, A0, W0, A1, W1, s, KPC, K, n0, tid);
        asm volatile("cp.async.commit_group;" ::: "memory");
    }

    // lane-constant address pieces
    int a_lrow = lane & 15, a_lsel = lane >> 4;
    int b_lrow = (lane & 7) + ((lane >> 4) << 3);
    int b_lsel = (lane >> 3) & 1;

    for (int it = 0; it < NITER; it++) {
        asm volatile("cp.async.wait_group 2;" ::: "memory");
        __syncthreads();

        uint32_t abase = smb + (it % 3) * STAGE;
        uint32_t bbase = abase + 128 * 128;
        #pragma unroll
        for (int ks = 0; ks < 4; ks++) {
            int cb = 2 * ks;
            uint32_t a[MT][4], b[4][2];
            #pragma unroll
            for (int mt = 0; mt < MT; mt++) {
                int row = wm * WTM + mt * 16 + a_lrow;
                ldm_x4(a[mt], abase + (uint32_t)(row * 128 +
                       (((cb + a_lsel) ^ (a_lrow & 7)) << 4)));
            }
            #pragma unroll
            for (int j = 0; j < 2; j++) {
                int row = wn * 32 + j * 16 + b_lrow;
                uint32_t r4[4];
                ldm_x4(r4, bbase + (uint32_t)(row * 128 +
                       (((cb + b_lsel) ^ (b_lrow & 7)) << 4)));
                b[j*2][0] = r4[0]; b[j*2][1] = r4[1];
                b[j*2+1][0] = r4[2]; b[j*2+1][1] = r4[3];
            }
            #pragma unroll
            for (int mt = 0; mt < MT; mt++)
                #pragma unroll
                for (int q = 0; q < 4; q++) cvt_tf32(a[mt][q]);
            #pragma unroll
            for (int nt = 0; nt < 4; nt++) { cvt_tf32(b[nt][0]); cvt_tf32(b[nt][1]); }
            #pragma unroll
            for (int mt = 0; mt < MT; mt++)
                #pragma unroll
                for (int nt = 0; nt < 4; nt++)
                    mma_tf32(acc[mt][nt], a[mt], b[nt]);
        }
        __syncthreads();
        if (it + 3 < NITER)
            g_load<BN, NSRC>(smb + (it % 3) * STAGE, A0, W0, A1, W1, it + 3, KPC, K, n0, tid);
        asm volatile("cp.async.commit_group;" ::: "memory");
    }

    // epilogue
    #pragma unroll
    for (int mt = 0; mt < MT; mt++) {
        int mrow = wm * WTM + mt * 16 + (lane >> 2);
        #pragma unroll
        for (int nt = 0; nt < 4; nt++) {
            int n = n0 + wn * 32 + nt * 8 + (lane & 3) * 2;
            float b0a = bias0[n], b0b = bias0[n + 1];
            if (NSRC == 2) { b0a += bias1[n]; b0b += bias1[n + 1]; }
            float v0 = acc[mt][nt][0] + b0a;
            float v1 = acc[mt][nt][1] + b0b;
            float v2 = acc[mt][nt][2] + b0a;
            float v3 = acc[mt][nt][3] + b0b;
            if (ACT == 1) { v0 = tanhf(v0); v1 = tanhf(v1); v2 = tanhf(v2); v3 = tanhf(v3); }
            *(float2*)(C + (long)mrow * N + n)       = make_float2(v0, v1);
            *(float2*)(C + (long)(mrow + 8) * N + n) = make_float2(v2, v3);
        }
    }
}

// ---------------------------------------------------------------------------
// embedding gather: x[b,h] = emb[word[b], h]
__global__ void k_embed(const float* __restrict__ emb, const int* __restrict__ word) {
    int i = (blockIdx.x * 256 + threadIdx.x) * 4;   // B*H
    int b = i >> 10, h = i & 1023;
    float4 v = *(const float4*)(emb + (long)word[b] * Hh + h);
    *(float4*)(g_x + i) = v;
}

// ---------------------------------------------------------------------------
// LSTM cell elementwise
__global__ void k_lstm_cell(const float* __restrict__ c_prev,
                            float* __restrict__ c_out, float* __restrict__ h_out) {
    int i = (blockIdx.x * 256 + threadIdx.x) * 4;   // B*H
    int b = i >> 10, h = i & 1023;
    const float* g = g_gates + (long)b * 4 * Hh;
    float4 I = *(const float4*)(g + h);
    float4 F = *(const float4*)(g + Hh + h);
    float4 G = *(const float4*)(g + 2 * Hh + h);
    float4 O = *(const float4*)(g + 3 * Hh + h);
    float4 cp = *(const float4*)(c_prev + i);
    float4 c, hv;
    c.x = sigm(F.x) * cp.x + sigm(I.x) * tanhf(G.x); hv.x = sigm(O.x) * tanhf(c.x);
    c.y = sigm(F.y) * cp.y + sigm(I.y) * tanhf(G.y); hv.y = sigm(O.y) * tanhf(c.y);
    c.z = sigm(F.z) * cp.z + sigm(I.z) * tanhf(G.z); hv.z = sigm(O.z) * tanhf(c.z);
    c.w = sigm(F.w) * cp.w + sigm(I.w) * tanhf(G.w); hv.w = sigm(O.w) * tanhf(c.w);
    *(float4*)(c_out + i) = c;
    *(float4*)(h_out + i) = hv;
}

// ---------------------------------------------------------------------------
// pb[b] = S * sigmoid( sum_j tanh_t[b,j]*w2[j] + b2 )
__global__ void k_attn_p(const float* __restrict__ w2, const float* __restrict__ b2, int S) {
    int b = blockIdx.x, tid = threadIdx.x;
    __shared__ float red[256];
    float s = 0.0f;
    for (int j = tid; j < HH2; j += 256) s += g_t[b * HH2 + j] * w2[j];
    red[tid] = s; __syncthreads();
    for (int st = 128; st > 0; st >>= 1) {
        if (tid < st) red[tid] += red[tid + st];
        __syncthreads();
    }
    if (tid == 0) g_pb[b] = (float)S * sigm(red[0] + b2[0]);
}

// ---------------------------------------------------------------------------
// Windowed attention: scores, softmax*gauss, a (-> d_out), ctx (-> scratch)
__global__ void k_attn_ctx(const float* __restrict__ hout, const float* __restrict__ enc,
                           int S, float* __restrict__ a_out) {
    int b = blockIdx.x, tid = threadIdx.x;
    int warp = tid >> 5, lane = tid & 31;
    float pb = g_pb[b];
    int ws = (int)rintf(fmaxf(pb - WSZF, 0.0f));
    int we = (int)rintf(fminf(pb + WSZF, (float)(S - 1)));
    __shared__ float sc[MAXW], ga[MAXW], aa[MAXW];

    for (int w = warp; w < MAXW; w += 8) {
        int idx = ws + w;
        if (idx <= we) {
            int ic = min(idx, S - 1);
            const float* er = enc + ((long)ic * Bb + b) * Hh;
            const float* orow = hout + (long)b * Hh;
            float dot = 0.0f;
            for (int h = lane; h < Hh; h += 32) dot += orow[h] * er[h];
            #pragma unroll
            for (int o = 16; o > 0; o >>= 1) dot += __shfl_down_sync(0xffffffff, dot, o);
            if (lane == 0) {
                sc[w] = dot;
                ga[w] = expf(((float)idx - pb) / 50.0f);
            }
        } else if (lane == 0) {
            sc[w] = 0.0f;
            ga[w] = 0.0f;
        }
    }
    __syncthreads();
    if (tid < MAXW) {
        float m = -1e30f;
        for (int w = 0; w < MAXW; w++) m = fmaxf(m, sc[w]);
        float den = 0.0f;
        for (int w = 0; w < MAXW; w++) den += expf(sc[w] - m);
        float a = expf(sc[tid] - m) / den * ga[tid];
        aa[tid] = a;
        a_out[b * MAXW + tid] = a;
    }
    __syncthreads();
    for (int h = tid; h < Hh; h += blockDim.x) {
        float s = 0.0f;
        for (int w = 0; w < MAXW; w++) {
            int idx = ws + w;
            if (idx <= we)
                s += aa[w] * enc[((long)idx * Bb + b) * Hh + h];
        }
        g_ctx[b * Hh + h] = s;
    }
}

// ---------------------------------------------------------------------------
// cat = [ctx, out]
__global__ void k_cat(const float* __restrict__ hout) {
    int i = (blockIdx.x * 256 + threadIdx.x) * 4;   // B*2H
    int b = i >> 11, r = i & 2047;
    float4 v;
    if (r < Hh) v = *(const float4*)(g_ctx + b * Hh + r);
    else        v = *(const float4*)(hout + (long)b * Hh + r - Hh);
    *(float4*)(g_cat + i) = v;
}

// ---------------------------------------------------------------------------
// In-place log-softmax over V per row (1024 threads, float4)
__global__ void k_logsoftmax(float* __restrict__ y) {
    int b = blockIdx.x, tid = threadIdx.x;
    float* row = y + (long)b * Vv;
    __shared__ float red[32];
    float m = -1e30f;
    for (int j = tid; j < Vv / 4; j += 1024) {
        float4 v = *(const float4*)(row + j * 4);
        m = fmaxf(m, fmaxf(fmaxf(v.x, v.y), fmaxf(v.z, v.w)));
    }
    #pragma unroll
    for (int o = 16; o > 0; o >>= 1) m = fmaxf(m, __shfl_xor_sync(~0u, m, o));
    if ((tid & 31) == 0) red[tid >> 5] = m;
    __syncthreads();
    if (tid < 32) {
        m = red[tid];
        #pragma unroll
        for (int o = 16; o > 0; o >>= 1) m = fmaxf(m, __shfl_xor_sync(~0u, m, o));
        if (tid == 0) red[0] = m;
    }
    __syncthreads();
    m = red[0];
    __syncthreads();
    float s = 0.0f;
    for (int j = tid; j < Vv / 4; j += 1024) {
        float4 v = *(const float4*)(row + j * 4);
        s += expf(v.x - m) + expf(v.y - m) + expf(v.z - m) + expf(v.w - m);
    }
    #pragma unroll
    for (int o = 16; o > 0; o >>= 1) s += __shfl_xor_sync(~0u, s, o);
    if ((tid & 31) == 0) red[tid >> 5] = s;
    __syncthreads();
    if (tid < 32) {
        s = red[tid];
        #pragma unroll
        for (int o = 16; o > 0; o >>= 1) s += __shfl_xor_sync(~0u, s, o);
        if (tid == 0) red[0] = s;
    }
    __syncthreads();
    float lse = m + logf(red[0]);
    for (int j = tid; j < Vv / 4; j += 1024) {
        float4 v = *(const float4*)(row + j * 4);
        v.x -= lse; v.y -= lse; v.z -= lse; v.w -= lse;
        *(float4*)(row + j * 4) = v;
    }
}

// ---------------------------------------------------------------------------
extern "C" void kernel_launch(void* const* d_in, const int* in_sizes, int n_in,
                              void* d_out, int out_size) {
    const float* enc  = (const float*)d_in[1];
    const int*   word = (const int*)  d_in[2];
    const float* h0   = (const float*)d_in[3];
    const float* c0   = (const float*)d_in[4];
    const float* emb  = (const float*)d_in[5];
    const float* Wih  = (const float*)d_in[6];
    const float* Whh  = (const float*)d_in[7];
    const float* bih  = (const float*)d_in[8];
    const float* bhh  = (const float*)d_in[9];
    const float* aw1  = (const float*)d_in[10];
    const float* ab1  = (const float*)d_in[11];
    const float* aw2  = (const float*)d_in[12];
    const float* ab2  = (const float*)d_in[13];
    const float* f1w  = (const float*)d_in[14];
    const float* f1b  = (const float*)d_in[15];
    const float* f2w  = (const float*)d_in[16];
    const float* f2b  = (const float*)d_in[17];

    int S = in_sizes[1] / (Bb * Hh);

    float* out = (float*)d_out;
    float* y   = out + Y_OFF;
    float* o2  = out + O2_OFF;
    float* hN  = out + H_OFF;
    float* cN  = out + C_OFF;
    float* aO  = out + A_OFF;

    const int SZ64  = 3 * (128 + 64)  * 32 * 4;   // 73728
    const int SZ128 = 3 * (128 + 128) * 32 * 4;   // 98304

    static float *p_x = nullptr, *p_gates = nullptr, *p_t = nullptr, *p_cat = nullptr;
    static bool inited = false;
    if (!inited) {
        cudaGetSymbolAddress((void**)&p_x,     g_x);
        cudaGetSymbolAddress((void**)&p_gates, g_gates);
        cudaGetSymbolAddress((void**)&p_t,     g_t);
        cudaGetSymbolAddress((void**)&p_cat,   g_cat);
        cudaFuncSetAttribute(k_gemm_mma<64, 2, 0>,  cudaFuncAttributeMaxDynamicSharedMemorySize, SZ64);
        cudaFuncSetAttribute(k_gemm_mma<64, 1, 1>,  cudaFuncAttributeMaxDynamicSharedMemorySize, SZ64);
        cudaFuncSetAttribute(k_gemm_mma<128, 1, 0>, cudaFuncAttributeMaxDynamicSharedMemorySize, SZ128);
        inited = true;
    }

    // 1. embedding
    k_embed<<<Bb * Hh / 1024, 256>>>(emb, word);

    // 2. LSTM layers (fused dual-source gates GEMM: x@Wih^T + h@Whh^T)
    for (int l = 0; l < Ll; l++) {
        const float* xin = (l == 0) ? p_x : hN + (long)(l - 1) * Bb * Hh;
        k_gemm_mma<64, 2, 0><<<4 * Hh / 64, 256, SZ64>>>(
            xin, Wih + (long)l * 4 * Hh * Hh,
            h0 + (long)l * Bb * Hh, Whh + (long)l * 4 * Hh * Hh,
            bih + (long)l * 4 * Hh, bhh + (long)l * 4 * Hh,
            p_gates, 4 * Hh, Hh);
        k_lstm_cell<<<Bb * Hh / 1024, 256>>>(c0 + (long)l * Bb * Hh,
                                             cN + (long)l * Bb * Hh,
                                             hN + (long)l * Bb * Hh);
    }
    const float* hout = hN + (long)(Ll - 1) * Bb * Hh;

    // 3. attention position: tanh(out@w1^T+b1), then p
    k_gemm_mma<64, 1, 1><<<HH2 / 64, 256, SZ64>>>(
        hout, aw1, nullptr, nullptr, ab1, nullptr, p_t, HH2, Hh);
    k_attn_p<<<Bb, 256>>>(aw2, ab2, S);

    // 4. windowed attention -> a, ctx
    k_attn_ctx<<<Bb, 256>>>(hout, enc, S, aO);

    // 5. fc1 (K=2048) -> o2 (fp32, straight into d_out)
    k_cat<<<Bb * 2 * Hh / 1024, 256>>>(hout);
    k_gemm_mma<64, 1, 1><<<Hh / 64, 256, SZ64>>>(
        p_cat, f1w, nullptr, nullptr, f1b, nullptr, o2, Hh, 2 * Hh);

    // 6. fc2 + log-softmax
    k_gemm_mma<128, 1, 0><<<Vv / 128, 256, SZ128>>>(
        o2, f2w, nullptr, nullptr, f2b, nullptr, y, Vv, Hh);
    k_logsoftmax<<<Bb, 1024>>>(y);
}

// round 4
// speedup vs baseline: 3.7893x; 1.2116x over previous
#include <cuda_runtime.h>
#include <math.h>
#include <stdint.h>

#define Bb   128
#define Hh   1024
#define HH2  512
#define Vv   32000
#define Ll   2
#define MAXW 21
#define WSZF 10.0f

// output layout (concatenated tuple: y, o2, h_new, c_new, a)
#define Y_OFF  0
#define O2_OFF (Bb*Vv)
#define H_OFF  (O2_OFF + Bb*Hh)
#define C_OFF  (H_OFF + Ll*Bb*Hh)
#define A_OFF  (C_OFF + Ll*Bb*Hh)

// scratch (device globals — no allocation allowed)
__device__ float g_x[Bb*Hh];
__device__ float g_gates[Bb*4*Hh];
__device__ float g_t[Bb*HH2];
__device__ float g_pb[Bb];
__device__ float g_ctx[Bb*Hh];
__device__ float g_cat[Bb*2*Hh];

__device__ __forceinline__ float sigm(float x) { return 1.0f / (1.0f + expf(-x)); }

// ---------------------------------------------------------------------------
// async-copy / mma helpers
__device__ __forceinline__ void cp16(uint32_t dst, const float* src) {
    asm volatile("cp.async.cg.shared.global [%0], [%1], 16;"
                 :: "r"(dst), "l"(__cvta_generic_to_global(src)));
}
__device__ __forceinline__ void ldm_x4(uint32_t* r, uint32_t addr) {
    asm volatile("ldmatrix.sync.aligned.m8n8.x4.shared.b16 {%0,%1,%2,%3}, [%4];"
                 : "=r"(r[0]), "=r"(r[1]), "=r"(r[2]), "=r"(r[3]) : "r"(addr));
}
__device__ __forceinline__ void cvt_tf32(uint32_t& x) {
    asm volatile("cvt.rna.tf32.f32 %0, %0;" : "+r"(x));
}
__device__ __forceinline__ void mma_tf32(float* d, const uint32_t* a, const uint32_t* b) {
    asm volatile("mma.sync.aligned.m16n8k8.row.col.f32.tf32.tf32.f32 "
                 "{%0,%1,%2,%3}, {%4,%5,%6,%7}, {%8,%9}, {%0,%1,%2,%3};"
                 : "+f"(d[0]), "+f"(d[1]), "+f"(d[2]), "+f"(d[3])
                 : "r"(a[0]), "r"(a[1]), "r"(a[2]), "r"(a[3]),
                   "r"(b[0]), "r"(b[1]));
}

// swizzled byte offset of 16B chunk (row stride 128B, 8 chunks/row)
__device__ __forceinline__ uint32_t swz(int row, int chunk) {
    return (uint32_t)(row * 128 + ((chunk ^ (row & 7)) << 4));
}

// ---------------------------------------------------------------------------
// Stage a K-chunk of 32 fp32 cols: A[128 rows], W[BN rows] -> swizzled SMEM.
template<int BN, int NSRC>
__device__ __forceinline__ void g_load(
    uint32_t abase, const float* __restrict__ A0, const float* __restrict__ W0,
    const float* __restrict__ A1, const float* __restrict__ W1,
    int it, int KPC, int K, int n0, int tid)
{
    const float* A = (NSRC == 2 && it >= KPC) ? A1 : A0;
    const float* W = (NSRC == 2 && it >= KPC) ? W1 : W0;
    int kb = ((NSRC == 2 && it >= KPC) ? it - KPC : it) * 32;
    uint32_t bbase = abase + 128 * 128;
    #pragma unroll
    for (int i = 0; i < 4; i++) {               // A: 128 rows x 8 chunks
        int idx = tid + i * 256;
        int r = idx >> 3, c = idx & 7;
        cp16(abase + swz(r, c), A + (long)r * K + kb + c * 4);
    }
    #pragma unroll
    for (int i = 0; i < BN * 8 / 256; i++) {    // B: BN rows x 8 chunks
        int idx = tid + i * 256;
        int r = idx >> 3, c = idx & 7;
        cp16(bbase + swz(r, c), W + (long)(n0 + r) * K + kb + c * 4);
    }
}

// ---------------------------------------------------------------------------
// tf32 mma.sync GEMM: C[128, N] = act( sum_s A_s[128,K] @ W_s[N,K]^T + biases )
// BM=128 (whole batch), BN per CTA, BK=32, 4-stage cp.async pipeline.
template<int BN, int NSRC, int ACT>
__global__ void __launch_bounds__(256, 1) k_gemm_mma(
    const float* __restrict__ A0, const float* __restrict__ W0,
    const float* __restrict__ A1, const float* __restrict__ W1,
    const float* __restrict__ bias0, const float* __restrict__ bias1,
    float* __restrict__ C, int N, int K)
{
    extern __shared__ char sm[];
    constexpr int STAGE = (128 + BN) * 32 * 4;
    constexpr int NST = 4;
    constexpr int WN  = BN / 32;                // warps along N (1,2,4)
    constexpr int WM  = 8 / WN;                 // warps along M
    constexpr int WTM = 128 / WM;               // warp tile M (16/32/64)
    constexpr int MT  = WTM / 16;               // m16 tiles per warp

    uint32_t smb = (uint32_t)__cvta_generic_to_shared(sm);
    int tid = threadIdx.x, lane = tid & 31, w = tid >> 5;
    int wm = w / WN, wn = w % WN;
    int n0 = blockIdx.x * BN;
    int KPC = K / 32, NITER = NSRC * KPC;

    float acc[MT][4][4];
    #pragma unroll
    for (int i = 0; i < MT; i++)
        #pragma unroll
        for (int j = 0; j < 4; j++)
            #pragma unroll
            for (int k = 0; k < 4; k++) acc[i][j][k] = 0.0f;

    // prefetch NST stages
    #pragma unroll
    for (int s = 0; s < NST; s++) {
        if (s < NITER) g_load<BN, NSRC>(smb + s * STAGE, A0, W0, A1, W1, s, KPC, K, n0, tid);
        asm volatile("cp.async.commit_group;" ::: "memory");
    }

    // lane-constant address pieces
    int a_lrow = lane & 15, a_lsel = lane >> 4;
    int b_lrow = (lane & 7) + ((lane >> 4) << 3);
    int b_lsel = (lane >> 3) & 1;

    for (int it = 0; it < NITER; it++) {
        asm volatile("cp.async.wait_group %0;" :: "n"(NST - 1) : "memory");
        __syncthreads();

        uint32_t abase = smb + (it % NST) * STAGE;
        uint32_t bbase = abase + 128 * 128;
        #pragma unroll
        for (int ks = 0; ks < 4; ks++) {
            int cb = 2 * ks;
            uint32_t a[MT][4], b[4][2];
            #pragma unroll
            for (int mt = 0; mt < MT; mt++) {
                int row = wm * WTM + mt * 16 + a_lrow;
                ldm_x4(a[mt], abase + (uint32_t)(row * 128 +
                       (((cb + a_lsel) ^ (a_lrow & 7)) << 4)));
            }
            #pragma unroll
            for (int j = 0; j < 2; j++) {
                int row = wn * 32 + j * 16 + b_lrow;
                uint32_t r4[4];
                ldm_x4(r4, bbase + (uint32_t)(row * 128 +
                       (((cb + b_lsel) ^ (b_lrow & 7)) << 4)));
                b[j*2][0] = r4[0]; b[j*2][1] = r4[1];
                b[j*2+1][0] = r4[2]; b[j*2+1][1] = r4[3];
            }
            #pragma unroll
            for (int mt = 0; mt < MT; mt++)
                #pragma unroll
                for (int q = 0; q < 4; q++) cvt_tf32(a[mt][q]);
            #pragma unroll
            for (int nt = 0; nt < 4; nt++) { cvt_tf32(b[nt][0]); cvt_tf32(b[nt][1]); }
            #pragma unroll
            for (int mt = 0; mt < MT; mt++)
                #pragma unroll
                for (int nt = 0; nt < 4; nt++)
                    mma_tf32(acc[mt][nt], a[mt], b[nt]);
        }
        __syncthreads();
        if (it + NST < NITER)
            g_load<BN, NSRC>(smb + (it % NST) * STAGE, A0, W0, A1, W1, it + NST, KPC, K, n0, tid);
        asm volatile("cp.async.commit_group;" ::: "memory");
    }

    // epilogue
    #pragma unroll
    for (int mt = 0; mt < MT; mt++) {
        int mrow = wm * WTM + mt * 16 + (lane >> 2);
        #pragma unroll
        for (int nt = 0; nt < 4; nt++) {
            int n = n0 + wn * 32 + nt * 8 + (lane & 3) * 2;
            float b0a = bias0[n], b0b = bias0[n + 1];
            if (NSRC == 2) { b0a += bias1[n]; b0b += bias1[n + 1]; }
            float v0 = acc[mt][nt][0] + b0a;
            float v1 = acc[mt][nt][1] + b0b;
            float v2 = acc[mt][nt][2] + b0a;
            float v3 = acc[mt][nt][3] + b0b;
            if (ACT == 1) { v0 = tanhf(v0); v1 = tanhf(v1); v2 = tanhf(v2); v3 = tanhf(v3); }
            *(float2*)(C + (long)mrow * N + n)       = make_float2(v0, v1);
            *(float2*)(C + (long)(mrow + 8) * N + n) = make_float2(v2, v3);
        }
    }
}

// ---------------------------------------------------------------------------
// embedding gather: x[b,h] = emb[word[b], h]
__global__ void k_embed(const float* __restrict__ emb, const int* __restrict__ word) {
    int i = (blockIdx.x * 256 + threadIdx.x) * 4;   // B*H
    int b = i >> 10, h = i & 1023;
    float4 v = *(const float4*)(emb + (long)word[b] * Hh + h);
    *(float4*)(g_x + i) = v;
}

// ---------------------------------------------------------------------------
// LSTM cell elementwise
__global__ void k_lstm_cell(const float* __restrict__ c_prev,
                            float* __restrict__ c_out, float* __restrict__ h_out) {
    int i = (blockIdx.x * 256 + threadIdx.x) * 4;   // B*H
    int b = i >> 10, h = i & 1023;
    const float* g = g_gates + (long)b * 4 * Hh;
    float4 I = *(const float4*)(g + h);
    float4 F = *(const float4*)(g + Hh + h);
    float4 G = *(const float4*)(g + 2 * Hh + h);
    float4 O = *(const float4*)(g + 3 * Hh + h);
    float4 cp = *(const float4*)(c_prev + i);
    float4 c, hv;
    c.x = sigm(F.x) * cp.x + sigm(I.x) * tanhf(G.x); hv.x = sigm(O.x) * tanhf(c.x);
    c.y = sigm(F.y) * cp.y + sigm(I.y) * tanhf(G.y); hv.y = sigm(O.y) * tanhf(c.y);
    c.z = sigm(F.z) * cp.z + sigm(I.z) * tanhf(G.z); hv.z = sigm(O.z) * tanhf(c.z);
    c.w = sigm(F.w) * cp.w + sigm(I.w) * tanhf(G.w); hv.w = sigm(O.w) * tanhf(c.w);
    *(float4*)(c_out + i) = c;
    *(float4*)(h_out + i) = hv;
}

// ---------------------------------------------------------------------------
// pb[b] = S * sigmoid( sum_j tanh_t[b,j]*w2[j] + b2 )
__global__ void k_attn_p(const float* __restrict__ w2, const float* __restrict__ b2, int S) {
    int b = blockIdx.x, tid = threadIdx.x;
    __shared__ float red[256];
    float s = 0.0f;
    for (int j = tid; j < HH2; j += 256) s += g_t[b * HH2 + j] * w2[j];
    red[tid] = s; __syncthreads();
    for (int st = 128; st > 0; st >>= 1) {
        if (tid < st) red[tid] += red[tid + st];
        __syncthreads();
    }
    if (tid == 0) g_pb[b] = (float)S * sigm(red[0] + b2[0]);
}

// ---------------------------------------------------------------------------
// Windowed attention: scores, softmax*gauss, a (-> d_out), ctx (-> scratch)
__global__ void k_attn_ctx(const float* __restrict__ hout, const float* __restrict__ enc,
                           int S, float* __restrict__ a_out) {
    int b = blockIdx.x, tid = threadIdx.x;
    int warp = tid >> 5, lane = tid & 31;
    float pb = g_pb[b];
    int ws = (int)rintf(fmaxf(pb - WSZF, 0.0f));
    int we = (int)rintf(fminf(pb + WSZF, (float)(S - 1)));
    __shared__ float sc[MAXW], ga[MAXW], aa[MAXW];

    for (int w = warp; w < MAXW; w += 8) {
        int idx = ws + w;
        if (idx <= we) {
            int ic = min(idx, S - 1);
            const float* er = enc + ((long)ic * Bb + b) * Hh;
            const float* orow = hout + (long)b * Hh;
            float dot = 0.0f;
            for (int h = lane; h < Hh; h += 32) dot += orow[h] * er[h];
            #pragma unroll
            for (int o = 16; o > 0; o >>= 1) dot += __shfl_down_sync(0xffffffff, dot, o);
            if (lane == 0) {
                sc[w] = dot;
                ga[w] = expf(((float)idx - pb) / 50.0f);
            }
        } else if (lane == 0) {
            sc[w] = 0.0f;
            ga[w] = 0.0f;
        }
    }
    __syncthreads();
    if (tid < MAXW) {
        float m = -1e30f;
        for (int w = 0; w < MAXW; w++) m = fmaxf(m, sc[w]);
        float den = 0.0f;
        for (int w = 0; w < MAXW; w++) den += expf(sc[w] - m);
        float a = expf(sc[tid] - m) / den * ga[tid];
        aa[tid] = a;
        a_out[b * MAXW + tid] = a;
    }
    __syncthreads();
    for (int h = tid; h < Hh; h += blockDim.x) {
        float s = 0.0f;
        for (int w = 0; w < MAXW; w++) {
            int idx = ws + w;
            if (idx <= we)
                s += aa[w] * enc[((long)idx * Bb + b) * Hh + h];
        }
        g_ctx[b * Hh + h] = s;
    }
}

// ---------------------------------------------------------------------------
// cat = [ctx, out]
__global__ void k_cat(const float* __restrict__ hout) {
    int i = (blockIdx.x * 256 + threadIdx.x) * 4;   // B*2H
    int b = i >> 11, r = i & 2047;
    float4 v;
    if (r < Hh) v = *(const float4*)(g_ctx + b * Hh + r);
    else        v = *(const float4*)(hout + (long)b * Hh + r - Hh);
    *(float4*)(g_cat + i) = v;
}

// ---------------------------------------------------------------------------
// In-place log-softmax over V per row (1024 threads, float4)
__global__ void k_logsoftmax(float* __restrict__ y) {
    int b = blockIdx.x, tid = threadIdx.x;
    float* row = y + (long)b * Vv;
    __shared__ float red[32];
    float m = -1e30f;
    for (int j = tid; j < Vv / 4; j += 1024) {
        float4 v = *(const float4*)(row + j * 4);
        m = fmaxf(m, fmaxf(fmaxf(v.x, v.y), fmaxf(v.z, v.w)));
    }
    #pragma unroll
    for (int o = 16; o > 0; o >>= 1) m = fmaxf(m, __shfl_xor_sync(~0u, m, o));
    if ((tid & 31) == 0) red[tid >> 5] = m;
    __syncthreads();
    if (tid < 32) {
        m = red[tid];
        #pragma unroll
        for (int o = 16; o > 0; o >>= 1) m = fmaxf(m, __shfl_xor_sync(~0u, m, o));
        if (tid == 0) red[0] = m;
    }
    __syncthreads();
    m = red[0];
    __syncthreads();
    float s = 0.0f;
    for (int j = tid; j < Vv / 4; j += 1024) {
        float4 v = *(const float4*)(row + j * 4);
        s += expf(v.x - m) + expf(v.y - m) + expf(v.z - m) + expf(v.w - m);
    }
    #pragma unroll
    for (int o = 16; o > 0; o >>= 1) s += __shfl_xor_sync(~0u, s, o);
    if ((tid & 31) == 0) red[tid >> 5] = s;
    __syncthreads();
    if (tid < 32) {
        s = red[tid];
        #pragma unroll
        for (int o = 16; o > 0; o >>= 1) s += __shfl_xor_sync(~0u, s, o);
        if (tid == 0) red[0] = s;
    }
    __syncthreads();
    float lse = m + logf(red[0]);
    for (int j = tid; j < Vv / 4; j += 1024) {
        float4 v = *(const float4*)(row + j * 4);
        v.x -= lse; v.y -= lse; v.z -= lse; v.w -= lse;
        *(float4*)(row + j * 4) = v;
    }
}

// ---------------------------------------------------------------------------
extern "C" void kernel_launch(void* const* d_in, const int* in_sizes, int n_in,
                              void* d_out, int out_size) {
    const float* enc  = (const float*)d_in[1];
    const int*   word = (const int*)  d_in[2];
    const float* h0   = (const float*)d_in[3];
    const float* c0   = (const float*)d_in[4];
    const float* emb  = (const float*)d_in[5];
    const float* Wih  = (const float*)d_in[6];
    const float* Whh  = (const float*)d_in[7];
    const float* bih  = (const float*)d_in[8];
    const float* bhh  = (const float*)d_in[9];
    const float* aw1  = (const float*)d_in[10];
    const float* ab1  = (const float*)d_in[11];
    const float* aw2  = (const float*)d_in[12];
    const float* ab2  = (const float*)d_in[13];
    const float* f1w  = (const float*)d_in[14];
    const float* f1b  = (const float*)d_in[15];
    const float* f2w  = (const float*)d_in[16];
    const float* f2b  = (const float*)d_in[17];

    int S = in_sizes[1] / (Bb * Hh);

    float* out = (float*)d_out;
    float* y   = out + Y_OFF;
    float* o2  = out + O2_OFF;
    float* hN  = out + H_OFF;
    float* cN  = out + C_OFF;
    float* aO  = out + A_OFF;

    const int SZ32  = 4 * (128 + 32)  * 32 * 4;   // 81920
    const int SZ128 = 4 * (128 + 128) * 32 * 4;   // 131072

    static float *p_x = nullptr, *p_gates = nullptr, *p_t = nullptr, *p_cat = nullptr;
    static bool inited = false;
    if (!inited) {
        cudaGetSymbolAddress((void**)&p_x,     g_x);
        cudaGetSymbolAddress((void**)&p_gates, g_gates);
        cudaGetSymbolAddress((void**)&p_t,     g_t);
        cudaGetSymbolAddress((void**)&p_cat,   g_cat);
        cudaFuncSetAttribute(k_gemm_mma<32, 2, 0>,  cudaFuncAttributeMaxDynamicSharedMemorySize, SZ32);
        cudaFuncSetAttribute(k_gemm_mma<32, 1, 1>,  cudaFuncAttributeMaxDynamicSharedMemorySize, SZ32);
        cudaFuncSetAttribute(k_gemm_mma<128, 1, 0>, cudaFuncAttributeMaxDynamicSharedMemorySize, SZ128);
        inited = true;
    }

    // 1. embedding
    k_embed<<<Bb * Hh / 1024, 256>>>(emb, word);

    // 2. LSTM layers (fused dual-source gates GEMM: x@Wih^T + h@Whh^T), 128 CTAs
    for (int l = 0; l < Ll; l++) {
        const float* xin = (l == 0) ? p_x : hN + (long)(l - 1) * Bb * Hh;
        k_gemm_mma<32, 2, 0><<<4 * Hh / 32, 256, SZ32>>>(
            xin, Wih + (long)l * 4 * Hh * Hh,
            h0 + (long)l * Bb * Hh, Whh + (long)l * 4 * Hh * Hh,
            bih + (long)l * 4 * Hh, bhh + (long)l * 4 * Hh,
            p_gates, 4 * Hh, Hh);
        k_lstm_cell<<<Bb * Hh / 1024, 256>>>(c0 + (long)l * Bb * Hh,
                                             cN + (long)l * Bb * Hh,
                                             hN + (long)l * Bb * Hh);
    }
    const float* hout = hN + (long)(Ll - 1) * Bb * Hh;

    // 3. attention position: tanh(out@w1^T+b1), then p
    k_gemm_mma<32, 1, 1><<<HH2 / 32, 256, SZ32>>>(
        hout, aw1, nullptr, nullptr, ab1, nullptr, p_t, HH2, Hh);
    k_attn_p<<<Bb, 256>>>(aw2, ab2, S);

    // 4. windowed attention -> a, ctx
    k_attn_ctx<<<Bb, 256>>>(hout, enc, S, aO);

    // 5. fc1 (K=2048) -> o2 (fp32, straight into d_out), 32 CTAs
    k_cat<<<Bb * 2 * Hh / 1024, 256>>>(hout);
    k_gemm_mma<32, 1, 1><<<Hh / 32, 256, SZ32>>>(
        p_cat, f1w, nullptr, nullptr, f1b, nullptr, o2, Hh, 2 * Hh);

    // 6. fc2 + log-softmax
    k_gemm_mma<128, 1, 0><<<Vv / 128, 256, SZ128>>>(
        o2, f2w, nullptr, nullptr, f2b, nullptr, y, Vv, Hh);
    k_logsoftmax<<<Bb, 1024>>>(y);
}

// round 6
// speedup vs baseline: 4.4713x; 1.1800x over previous
#include <cuda_runtime.h>
#include <math.h>
#include <stdint.h>

#define Bb   128
#define Hh   1024
#define HH2  512
#define Vv   32000
#define Ll   2
#define MAXW 21
#define WSZF 10.0f

// output layout (concatenated tuple: y, o2, h_new, c_new, a)
#define Y_OFF  0
#define O2_OFF (Bb*Vv)
#define H_OFF  (O2_OFF + Bb*Hh)
#define C_OFF  (H_OFF + Ll*Bb*Hh)
#define A_OFF  (C_OFF + Ll*Bb*Hh)

// scratch (device globals — no allocation allowed)
__device__ float g_x[Bb*Hh];
__device__ float g_gates[Bb*4*Hh];     // also reused as fc1 partials
__device__ float g_gates2[Bb*4*Hh];    // source-1 partial
__device__ float g_t[Bb*HH2];
__device__ float g_pb[Bb];
__device__ float g_ctx[Bb*Hh];
__device__ float g_cat[Bb*2*Hh];

__device__ __forceinline__ float sigm(float x) { return 1.0f / (1.0f + expf(-x)); }

// ---------------------------------------------------------------------------
// async-copy / mma helpers
__device__ __forceinline__ void cp16(uint32_t dst, const float* src) {
    asm volatile("cp.async.cg.shared.global [%0], [%1], 16;"
                 :: "r"(dst), "l"(__cvta_generic_to_global(src)));
}
__device__ __forceinline__ void ldm_x4(uint32_t* r, uint32_t addr) {
    asm volatile("ldmatrix.sync.aligned.m8n8.x4.shared.b16 {%0,%1,%2,%3}, [%4];"
                 : "=r"(r[0]), "=r"(r[1]), "=r"(r[2]), "=r"(r[3]) : "r"(addr));
}
__device__ __forceinline__ void cvt_tf32(uint32_t& x) {
    asm volatile("cvt.rna.tf32.f32 %0, %0;" : "+r"(x));
}
__device__ __forceinline__ void mma_tf32(float* d, const uint32_t* a, const uint32_t* b) {
    asm volatile("mma.sync.aligned.m16n8k8.row.col.f32.tf32.tf32.f32 "
                 "{%0,%1,%2,%3}, {%4,%5,%6,%7}, {%8,%9}, {%0,%1,%2,%3};"
                 : "+f"(d[0]), "+f"(d[1]), "+f"(d[2]), "+f"(d[3])
                 : "r"(a[0]), "r"(a[1]), "r"(a[2]), "r"(a[3]),
                   "r"(b[0]), "r"(b[1]));
}

// swizzled byte offset of 16B chunk (row stride 128B, 8 chunks/row)
__device__ __forceinline__ uint32_t swz(int row, int chunk) {
    return (uint32_t)(row * 128 + ((chunk ^ (row & 7)) << 4));
}

// ---------------------------------------------------------------------------
// Stage a K-chunk of 32 fp32 cols: A[128 rows], W[BN rows] -> swizzled SMEM.
template<int BN, int NW>
__device__ __forceinline__ void g_load(
    uint32_t abase, const float* __restrict__ A, const float* __restrict__ W,
    int ld, int kb, int n0, int tid)
{
    constexpr int THREADS = NW * 32;
    uint32_t bbase = abase + 128 * 128;
    #pragma unroll
    for (int i = 0; i < 1024 / THREADS; i++) {          // A: 128 rows x 8 chunks
        int idx = tid + i * THREADS;
        int r = idx >> 3, c = idx & 7;
        cp16(abase + swz(r, c), A + (long)r * ld + kb + c * 4);
    }
    #pragma unroll
    for (int i = 0; i < BN * 8 / THREADS; i++) {        // B: BN rows x 8 chunks
        int idx = tid + i * THREADS;
        int r = idx >> 3, c = idx & 7;
        cp16(bbase + swz(r, c), W + (long)(n0 + r) * ld + kb + c * 4);
    }
}

// ---------------------------------------------------------------------------
// Core tf32 mma GEMM: C[128, N](n0..n0+BN) = act( A[128, kLen] @ W^T + bias )
// ld = leading dim of A and W (full K); kLen = this CTA's K extent.
// ACT: 0 = bias, 1 = bias+tanh, 2 = raw (no bias)
template<int BN, int NW, int WN, int NST, int ACT>
__device__ __forceinline__ void gemm_core(
    const float* __restrict__ A, const float* __restrict__ W,
    int ld, int kLen, const float* __restrict__ bias,
    float* __restrict__ C, int N, int n0, char* sm)
{
    constexpr int STAGE = (128 + BN) * 128;
    constexpr int WARPN = BN / WN, NT = WARPN / 8;
    constexpr int WM = NW / WN, WTM = 128 / WM, MT = WTM / 16;

    uint32_t smb = (uint32_t)__cvta_generic_to_shared(sm);
    int tid = threadIdx.x, lane = tid & 31, w = tid >> 5;
    int wm = w / WN, wn = w % WN;
    int NITER = kLen / 32;

    float acc[MT][NT][4] = {};

    #pragma unroll
    for (int s = 0; s < NST; s++) {
        if (s < NITER) g_load<BN, NW>(smb + s * STAGE, A, W, ld, s * 32, n0, tid);
        asm volatile("cp.async.commit_group;" ::: "memory");
    }

    int a_lrow = lane & 15, a_lsel = lane >> 4;
    int b_lrow = (lane & 7) + ((lane >> 4) << 3);
    int b_lsel = (lane >> 3) & 1;

    for (int it = 0; it < NITER; it++) {
        asm volatile("cp.async.wait_group %0;" :: "n"(NST - 1) : "memory");
        __syncthreads();

        uint32_t abase = smb + (it % NST) * STAGE;
        uint32_t bbase = abase + 128 * 128;
        #pragma unroll
        for (int ks = 0; ks < 4; ks++) {
            int cb = 2 * ks;
            uint32_t a[MT][4], b[NT][2];
            #pragma unroll
            for (int mt = 0; mt < MT; mt++) {
                int row = wm * WTM + mt * 16 + a_lrow;
                ldm_x4(a[mt], abase + (uint32_t)(row * 128 +
                       (((cb + a_lsel) ^ (a_lrow & 7)) << 4)));
            }
            #pragma unroll
            for (int j = 0; j < NT / 2; j++) {
                int row = wn * WARPN + j * 16 + b_lrow;
                uint32_t r4[4];
                ldm_x4(r4, bbase + (uint32_t)(row * 128 +
                       (((cb + b_lsel) ^ (b_lrow & 7)) << 4)));
                b[j*2][0] = r4[0]; b[j*2][1] = r4[1];
                b[j*2+1][0] = r4[2]; b[j*2+1][1] = r4[3];
            }
            #pragma unroll
            for (int mt = 0; mt < MT; mt++)
                #pragma unroll
                for (int q = 0; q < 4; q++) cvt_tf32(a[mt][q]);
            #pragma unroll
            for (int nt = 0; nt < NT; nt++) { cvt_tf32(b[nt][0]); cvt_tf32(b[nt][1]); }
            #pragma unroll
            for (int mt = 0; mt < MT; mt++)
                #pragma unroll
                for (int nt = 0; nt < NT; nt++)
                    mma_tf32(acc[mt][nt], a[mt], b[nt]);
        }
        __syncthreads();
        if (it + NST < NITER)
            g_load<BN, NW>(smb + (it % NST) * STAGE, A, W, ld, (it + NST) * 32, n0, tid);
        asm volatile("cp.async.commit_group;" ::: "memory");
    }

    // epilogue
    #pragma unroll
    for (int mt = 0; mt < MT; mt++) {
        int mrow = wm * WTM + mt * 16 + (lane >> 2);
        #pragma unroll
        for (int nt = 0; nt < NT; nt++) {
            int n = n0 + wn * WARPN + nt * 8 + (lane & 3) * 2;
            float b0a = 0.0f, b0b = 0.0f;
            if (ACT != 2) { b0a = bias[n]; b0b = bias[n + 1]; }
            float v0 = acc[mt][nt][0] + b0a;
            float v1 = acc[mt][nt][1] + b0b;
            float v2 = acc[mt][nt][2] + b0a;
            float v3 = acc[mt][nt][3] + b0b;
            if (ACT == 1) { v0 = tanhf(v0); v1 = tanhf(v1); v2 = tanhf(v2); v3 = tanhf(v3); }
            *(float2*)(C + (long)mrow * N + n)       = make_float2(v0, v1);
            *(float2*)(C + (long)(mrow + 8) * N + n) = make_float2(v2, v3);
        }
    }
}

// ---------------------------------------------------------------------------
// Wrappers
template<int BN, int NW, int WN, int NST, int ACT>
__global__ void __launch_bounds__(NW * 32, 2) k_gemm_std(
    const float* __restrict__ A, const float* __restrict__ W, int K,
    const float* __restrict__ bias, float* __restrict__ C, int N)
{
    extern __shared__ char sm[];
    gemm_core<BN, NW, WN, NST, ACT>(A, W, K, K, bias, C, N, blockIdx.x * BN, sm);
}

// dual-source: grid.x = 2 * (N/BN); first half = source0 -> C0, second -> C1
template<int BN, int NW, int WN, int NST>
__global__ void __launch_bounds__(NW * 32, 2) k_gemm_dualsrc(
    const float* __restrict__ A0, const float* __restrict__ W0,
    const float* __restrict__ A1, const float* __restrict__ W1, int K,
    float* __restrict__ C0, float* __restrict__ C1, int N)
{
    extern __shared__ char sm[];
    int ntiles = gridDim.x >> 1;
    int s = (blockIdx.x >= ntiles);
    int n0 = (blockIdx.x - s * ntiles) * BN;
    gemm_core<BN, NW, WN, NST, 2>(s ? A1 : A0, s ? W1 : W0, K, K, nullptr,
                                  s ? C1 : C0, N, n0, sm);
}

// split-K=2: grid.x = 2 * (N/BN); even/odd blocks do K halves -> partial buffers
template<int BN, int NW, int WN, int NST>
__global__ void __launch_bounds__(NW * 32, 2) k_gemm_splitk(
    const float* __restrict__ A, const float* __restrict__ W, int K,
    float* __restrict__ P, int N)
{
    extern __shared__ char sm[];
    int ks = blockIdx.x & 1;
    int n0 = (blockIdx.x >> 1) * BN;
    int half = K / 2;
    gemm_core<BN, NW, WN, NST, 2>(A + ks * half, W + ks * half, K, half, nullptr,
                                  P + (long)ks * 128 * N, N, n0, sm);
}

// ---------------------------------------------------------------------------
// embedding gather
__global__ void k_embed(const float* __restrict__ emb, const int* __restrict__ word) {
    int i = (blockIdx.x * 256 + threadIdx.x) * 4;
    int b = i >> 10, h = i & 1023;
    *(float4*)(g_x + i) = *(const float4*)(emb + (long)word[b] * Hh + h);
}

// ---------------------------------------------------------------------------
// LSTM cell: gates = p0 + p1 + bih + bhh, then cell update
__global__ void k_lstm_cell(const float* __restrict__ p0, const float* __restrict__ p1,
                            const float* __restrict__ bi, const float* __restrict__ bh,
                            const float* __restrict__ c_prev,
                            float* __restrict__ c_out, float* __restrict__ h_out) {
    int i = (blockIdx.x * 256 + threadIdx.x) * 4;   // B*H
    int b = i >> 10, h = i & 1023;
    long base = (long)b * 4 * Hh;
    float4 I, F, G, O;
    {
        float4 x0 = *(const float4*)(p0 + base + h);
        float4 x1 = *(const float4*)(p1 + base + h);
        float4 bb0 = *(const float4*)(bi + h);
        float4 bb1 = *(const float4*)(bh + h);
        I.x = x0.x + x1.x + bb0.x + bb1.x; I.y = x0.y + x1.y + bb0.y + bb1.y;
        I.z = x0.z + x1.z + bb0.z + bb1.z; I.w = x0.w + x1.w + bb0.w + bb1.w;
    }
    {
        float4 x0 = *(const float4*)(p0 + base + Hh + h);
        float4 x1 = *(const float4*)(p1 + base + Hh + h);
        float4 bb0 = *(const float4*)(bi + Hh + h);
        float4 bb1 = *(const float4*)(bh + Hh + h);
        F.x = x0.x + x1.x + bb0.x + bb1.x; F.y = x0.y + x1.y + bb0.y + bb1.y;
        F.z = x0.z + x1.z + bb0.z + bb1.z; F.w = x0.w + x1.w + bb0.w + bb1.w;
    }
    {
        float4 x0 = *(const float4*)(p0 + base + 2 * Hh + h);
        float4 x1 = *(const float4*)(p1 + base + 2 * Hh + h);
        float4 bb0 = *(const float4*)(bi + 2 * Hh + h);
        float4 bb1 = *(const float4*)(bh + 2 * Hh + h);
        G.x = x0.x + x1.x + bb0.x + bb1.x; G.y = x0.y + x1.y + bb0.y + bb1.y;
        G.z = x0.z + x1.z + bb0.z + bb1.z; G.w = x0.w + x1.w + bb0.w + bb1.w;
    }
    {
        float4 x0 = *(const float4*)(p0 + base + 3 * Hh + h);
        float4 x1 = *(const float4*)(p1 + base + 3 * Hh + h);
        float4 bb0 = *(const float4*)(bi + 3 * Hh + h);
        float4 bb1 = *(const float4*)(bh + 3 * Hh + h);
        O.x = x0.x + x1.x + bb0.x + bb1.x; O.y = x0.y + x1.y + bb0.y + bb1.y;
        O.z = x0.z + x1.z + bb0.z + bb1.z; O.w = x0.w + x1.w + bb0.w + bb1.w;
    }
    float4 cp = *(const float4*)(c_prev + i);
    float4 c, hv;
    c.x = sigm(F.x) * cp.x + sigm(I.x) * tanhf(G.x); hv.x = sigm(O.x) * tanhf(c.x);
    c.y = sigm(F.y) * cp.y + sigm(I.y) * tanhf(G.y); hv.y = sigm(O.y) * tanhf(c.y);
    c.z = sigm(F.z) * cp.z + sigm(I.z) * tanhf(G.z); hv.z = sigm(O.z) * tanhf(c.z);
    c.w = sigm(F.w) * cp.w + sigm(I.w) * tanhf(G.w); hv.w = sigm(O.w) * tanhf(c.w);
    *(float4*)(c_out + i) = c;
    *(float4*)(h_out + i) = hv;
}

// ---------------------------------------------------------------------------
// fc1 finish: o2 = tanh(p0 + p1 + bias)
__global__ void k_fc1_fin(const float* __restrict__ p0, const float* __restrict__ p1,
                          const float* __restrict__ bias, float* __restrict__ o2) {
    int i = (blockIdx.x * 256 + threadIdx.x) * 4;   // B*H
    int h = i & 1023;
    float4 x0 = *(const float4*)(p0 + i);
    float4 x1 = *(const float4*)(p1 + i);
    float4 bb = *(const float4*)(bias + h);
    float4 v;
    v.x = tanhf(x0.x + x1.x + bb.x);
    v.y = tanhf(x0.y + x1.y + bb.y);
    v.z = tanhf(x0.z + x1.z + bb.z);
    v.w = tanhf(x0.w + x1.w + bb.w);
    *(float4*)(o2 + i) = v;
}

// ---------------------------------------------------------------------------
// pb[b] = S * sigmoid( sum_j tanh_t[b,j]*w2[j] + b2 )
__global__ void k_attn_p(const float* __restrict__ w2, const float* __restrict__ b2, int S) {
    int b = blockIdx.x, tid = threadIdx.x;
    __shared__ float red[256];
    float s = 0.0f;
    for (int j = tid; j < HH2; j += 256) s += g_t[b * HH2 + j] * w2[j];
    red[tid] = s; __syncthreads();
    for (int st = 128; st > 0; st >>= 1) {
        if (tid < st) red[tid] += red[tid + st];
        __syncthreads();
    }
    if (tid == 0) g_pb[b] = (float)S * sigm(red[0] + b2[0]);
}

// ---------------------------------------------------------------------------
// Windowed attention: scores, softmax*gauss, a (-> d_out), ctx (-> scratch)
__global__ void k_attn_ctx(const float* __restrict__ hout, const float* __restrict__ enc,
                           int S, float* __restrict__ a_out) {
    int b = blockIdx.x, tid = threadIdx.x;
    int warp = tid >> 5, lane = tid & 31;
    float pb = g_pb[b];
    int ws = (int)rintf(fmaxf(pb - WSZF, 0.0f));
    int we = (int)rintf(fminf(pb + WSZF, (float)(S - 1)));
    __shared__ float sc[MAXW], ga[MAXW], aa[MAXW];

    for (int w = warp; w < MAXW; w += 8) {
        int idx = ws + w;
        if (idx <= we) {
            int ic = min(idx, S - 1);
            const float* er = enc + ((long)ic * Bb + b) * Hh;
            const float* orow = hout + (long)b * Hh;
            float dot = 0.0f;
            for (int h = lane; h < Hh; h += 32) dot += orow[h] * er[h];
            #pragma unroll
            for (int o = 16; o > 0; o >>= 1) dot += __shfl_down_sync(0xffffffff, dot, o);
            if (lane == 0) {
                sc[w] = dot;
                ga[w] = expf(((float)idx - pb) / 50.0f);
            }
        } else if (lane == 0) {
            sc[w] = 0.0f;
            ga[w] = 0.0f;
        }
    }
    __syncthreads();
    if (tid < MAXW) {
        float m = -1e30f;
        for (int w = 0; w < MAXW; w++) m = fmaxf(m, sc[w]);
        float den = 0.0f;
        for (int w = 0; w < MAXW; w++) den += expf(sc[w] - m);
        float a = expf(sc[tid] - m) / den * ga[tid];
        aa[tid] = a;
        a_out[b * MAXW + tid] = a;
    }
    __syncthreads();
    for (int h = tid; h < Hh; h += blockDim.x) {
        float s = 0.0f;
        for (int w = 0; w < MAXW; w++) {
            int idx = ws + w;
            if (idx <= we)
                s += aa[w] * enc[((long)idx * Bb + b) * Hh + h];
        }
        g_ctx[b * Hh + h] = s;
    }
}

// ---------------------------------------------------------------------------
// cat = [ctx, out]
__global__ void k_cat(const float* __restrict__ hout) {
    int i = (blockIdx.x * 256 + threadIdx.x) * 4;   // B*2H
    int b = i >> 11, r = i & 2047;
    float4 v;
    if (r < Hh) v = *(const float4*)(g_ctx + b * Hh + r);
    else        v = *(const float4*)(hout + (long)b * Hh + r - Hh);
    *(float4*)(g_cat + i) = v;
}

// ---------------------------------------------------------------------------
// In-place log-softmax over V per row (1024 threads, float4)
__global__ void k_logsoftmax(float* __restrict__ y) {
    int b = blockIdx.x, tid = threadIdx.x;
    float* row = y + (long)b * Vv;
    __shared__ float red[32];
    float m = -1e30f;
    for (int j = tid; j < Vv / 4; j += 1024) {
        float4 v = *(const float4*)(row + j * 4);
        m = fmaxf(m, fmaxf(fmaxf(v.x, v.y), fmaxf(v.z, v.w)));
    }
    #pragma unroll
    for (int o = 16; o > 0; o >>= 1) m = fmaxf(m, __shfl_xor_sync(~0u, m, o));
    if ((tid & 31) == 0) red[tid >> 5] = m;
    __syncthreads();
    if (tid < 32) {
        m = red[tid];
        #pragma unroll
        for (int o = 16; o > 0; o >>= 1) m = fmaxf(m, __shfl_xor_sync(~0u, m, o));
        if (tid == 0) red[0] = m;
    }
    __syncthreads();
    m = red[0];
    __syncthreads();
    float s = 0.0f;
    for (int j = tid; j < Vv / 4; j += 1024) {
        float4 v = *(const float4*)(row + j * 4);
        s += __expf(v.x - m) + __expf(v.y - m) + __expf(v.z - m) + __expf(v.w - m);
    }
    #pragma unroll
    for (int o = 16; o > 0; o >>= 1) s += __shfl_xor_sync(~0u, s, o);
    if ((tid & 31) == 0) red[tid >> 5] = s;
    __syncthreads();
    if (tid < 32) {
        s = red[tid];
        #pragma unroll
        for (int o = 16; o > 0; o >>= 1) s += __shfl_xor_sync(~0u, s, o);
        if (tid == 0) red[0] = s;
    }
    __syncthreads();
    float lse = m + logf(red[0]);
    for (int j = tid; j < Vv / 4; j += 1024) {
        float4 v = *(const float4*)(row + j * 4);
        v.x -= lse; v.y -= lse; v.z -= lse; v.w -= lse;
        *(float4*)(row + j * 4) = v;
    }
}

// ---------------------------------------------------------------------------
extern "C" void kernel_launch(void* const* d_in, const int* in_sizes, int n_in,
                              void* d_out, int out_size) {
    const float* enc  = (const float*)d_in[1];
    const int*   word = (const int*)  d_in[2];
    const float* h0   = (const float*)d_in[3];
    const float* c0   = (const float*)d_in[4];
    const float* emb  = (const float*)d_in[5];
    const float* Wih  = (const float*)d_in[6];
    const float* Whh  = (const float*)d_in[7];
    const float* bih  = (const float*)d_in[8];
    const float* bhh  = (const float*)d_in[9];
    const float* aw1  = (const float*)d_in[10];
    const float* ab1  = (const float*)d_in[11];
    const float* aw2  = (const float*)d_in[12];
    const float* ab2  = (const float*)d_in[13];
    const float* f1w  = (const float*)d_in[14];
    const float* f1b  = (const float*)d_in[15];
    const float* f2w  = (const float*)d_in[16];
    const float* f2b  = (const float*)d_in[17];

    int S = in_sizes[1] / (Bb * Hh);

    float* out = (float*)d_out;
    float* y   = out + Y_OFF;
    float* o2  = out + O2_OFF;
    float* hN  = out + H_OFF;
    float* cN  = out + C_OFF;
    float* aO  = out + A_OFF;

    const int SZ32  = 3 * (128 + 32)  * 128;   // 61440
    const int SZ128 = 3 * (128 + 128) * 128;   // 98304

    static float *p_x = nullptr, *p_g0 = nullptr, *p_g1 = nullptr,
                 *p_t = nullptr, *p_cat = nullptr;
    static bool inited = false;
    if (!inited) {
        cudaGetSymbolAddress((void**)&p_x,   g_x);
        cudaGetSymbolAddress((void**)&p_g0,  g_gates);
        cudaGetSymbolAddress((void**)&p_g1,  g_gates2);
        cudaGetSymbolAddress((void**)&p_t,   g_t);
        cudaGetSymbolAddress((void**)&p_cat, g_cat);
        cudaFuncSetAttribute(k_gemm_dualsrc<32, 4, 1, 3>,  cudaFuncAttributeMaxDynamicSharedMemorySize, SZ32);
        cudaFuncSetAttribute(k_gemm_std<32, 4, 1, 3, 1>,   cudaFuncAttributeMaxDynamicSharedMemorySize, SZ32);
        cudaFuncSetAttribute(k_gemm_splitk<32, 4, 1, 3>,   cudaFuncAttributeMaxDynamicSharedMemorySize, SZ32);
        cudaFuncSetAttribute(k_gemm_std<128, 8, 2, 3, 0>,  cudaFuncAttributeMaxDynamicSharedMemorySize, SZ128);
        inited = true;
    }

    // 1. embedding
    k_embed<<<Bb * Hh / 1024, 256>>>(emb, word);

    // 2. LSTM layers: dual-source grid-split gates GEMM (grid 256) + cell
    for (int l = 0; l < Ll; l++) {
        const float* xin = (l == 0) ? p_x : hN + (long)(l - 1) * Bb * Hh;
        k_gemm_dualsrc<32, 4, 1, 3><<<2 * (4 * Hh / 32), 128, SZ32>>>(
            xin, Wih + (long)l * 4 * Hh * Hh,
            h0 + (long)l * Bb * Hh, Whh + (long)l * 4 * Hh * Hh,
            Hh, p_g0, p_g1, 4 * Hh);
        k_lstm_cell<<<Bb * Hh / 1024, 256>>>(p_g0, p_g1,
                                             bih + (long)l * 4 * Hh, bhh + (long)l * 4 * Hh,
                                             c0 + (long)l * Bb * Hh,
                                             cN + (long)l * Bb * Hh,
                                             hN + (long)l * Bb * Hh);
    }
    const float* hout = hN + (long)(Ll - 1) * Bb * Hh;

    // 3. attention position: tanh(out@w1^T+b1), then p
    k_gemm_std<32, 4, 1, 3, 1><<<HH2 / 32, 128, SZ32>>>(
        hout, aw1, Hh, ab1, p_t, HH2);
    k_attn_p<<<Bb, 256>>>(aw2, ab2, S);

    // 4. windowed attention -> a, ctx
    k_attn_ctx<<<Bb, 256>>>(hout, enc, S, aO);

    // 5. fc1 (K=2048): split-K=2 -> partials in g_gates, then tanh-combine
    k_cat<<<Bb * 2 * Hh / 1024, 256>>>(hout);
    k_gemm_splitk<32, 4, 1, 3><<<2 * (Hh / 32), 128, SZ32>>>(
        p_cat, f1w, 2 * Hh, p_g0, Hh);
    k_fc1_fin<<<Bb * Hh / 1024, 256>>>(p_g0, p_g0 + (long)128 * Hh, f1b, o2);

    // 6. fc2 + log-softmax
    k_gemm_std<128, 8, 2, 3, 0><<<Vv / 128, 256, SZ128>>>(
        o2, f2w, Hh, f2b, y, Vv);
    k_logsoftmax<<<Bb, 1024>>>(y);
}

// round 7
// speedup vs baseline: 4.7483x; 1.0619x over previous
#include <cuda_runtime.h>
#include <math.h>
#include <stdint.h>

#define Bb   128
#define Hh   1024
#define HH2  512
#define Vv   32000
#define Ll   2
#define MAXW 21
#define WSZF 10.0f

// output layout (concatenated tuple: y, o2, h_new, c_new, a)
#define Y_OFF  0
#define O2_OFF (Bb*Vv)
#define H_OFF  (O2_OFF + Bb*Hh)
#define C_OFF  (H_OFF + Ll*Bb*Hh)
#define A_OFF  (C_OFF + Ll*Bb*Hh)

#define PART (Bb*4*Hh)   // one partial slab (128 x 4096)

// scratch (device globals — no allocation allowed)
__device__ float g_x[Bb*Hh];
__device__ float g_gates[2*Bb*4*Hh];    // src0 partials [2][128][4096]; fc1 partials [4][128][1024]
__device__ float g_gates2[2*Bb*4*Hh];   // src1 partials; attn partials [4][128][512]
__device__ float g_t[Bb*HH2];
__device__ float g_pb[Bb];
__device__ float g_ctx[Bb*Hh];
__device__ float g_cat[Bb*2*Hh];

__device__ __forceinline__ float sigm(float x) { return 1.0f / (1.0f + expf(-x)); }

// ---------------------------------------------------------------------------
// async-copy / mma helpers
__device__ __forceinline__ void cp16(uint32_t dst, const float* src) {
    asm volatile("cp.async.cg.shared.global [%0], [%1], 16;"
                 :: "r"(dst), "l"(__cvta_generic_to_global(src)));
}
__device__ __forceinline__ void ldm_x4(uint32_t* r, uint32_t addr) {
    asm volatile("ldmatrix.sync.aligned.m8n8.x4.shared.b16 {%0,%1,%2,%3}, [%4];"
                 : "=r"(r[0]), "=r"(r[1]), "=r"(r[2]), "=r"(r[3]) : "r"(addr));
}
__device__ __forceinline__ void cvt_tf32(uint32_t& x) {
    asm volatile("cvt.rna.tf32.f32 %0, %0;" : "+r"(x));
}
__device__ __forceinline__ void mma_tf32(float* d, const uint32_t* a, const uint32_t* b) {
    asm volatile("mma.sync.aligned.m16n8k8.row.col.f32.tf32.tf32.f32 "
                 "{%0,%1,%2,%3}, {%4,%5,%6,%7}, {%8,%9}, {%0,%1,%2,%3};"
                 : "+f"(d[0]), "+f"(d[1]), "+f"(d[2]), "+f"(d[3])
                 : "r"(a[0]), "r"(a[1]), "r"(a[2]), "r"(a[3]),
                   "r"(b[0]), "r"(b[1]));
}

// swizzled byte offset of 16B chunk (row stride 128B, 8 chunks/row)
__device__ __forceinline__ uint32_t swz(int row, int chunk) {
    return (uint32_t)(row * 128 + ((chunk ^ (row & 7)) << 4));
}

// ---------------------------------------------------------------------------
// Stage a K-chunk of 32 fp32 cols: A[128 rows], W[BN rows] -> swizzled SMEM.
template<int BN, int NW>
__device__ __forceinline__ void g_load(
    uint32_t abase, const float* __restrict__ A, const float* __restrict__ W,
    int ld, int kb, int n0, int tid)
{
    constexpr int THREADS = NW * 32;
    uint32_t bbase = abase + 128 * 128;
    #pragma unroll
    for (int i = 0; i < 1024 / THREADS; i++) {          // A: 128 rows x 8 chunks
        int idx = tid + i * THREADS;
        int r = idx >> 3, c = idx & 7;
        cp16(abase + swz(r, c), A + (long)r * ld + kb + c * 4);
    }
    #pragma unroll
    for (int i = 0; i < BN * 8 / THREADS; i++) {        // B: BN rows x 8 chunks
        int idx = tid + i * THREADS;
        int r = idx >> 3, c = idx & 7;
        cp16(bbase + swz(r, c), W + (long)(n0 + r) * ld + kb + c * 4);
    }
}

// ---------------------------------------------------------------------------
// Core tf32 mma GEMM: C[128, N](n0..n0+BN) = act( A[128, kLen] @ W^T + bias )
// ld = leading dim of A and W (full K); kLen = this CTA's K extent.
// ACT: 0 = bias, 1 = bias+tanh, 2 = raw (no bias)
template<int BN, int NW, int WN, int NST, int ACT>
__device__ __forceinline__ void gemm_core(
    const float* __restrict__ A, const float* __restrict__ W,
    int ld, int kLen, const float* __restrict__ bias,
    float* __restrict__ C, int N, int n0, char* sm)
{
    constexpr int STAGE = (128 + BN) * 128;
    constexpr int WARPN = BN / WN, NT = WARPN / 8;
    constexpr int WM = NW / WN, WTM = 128 / WM, MT = WTM / 16;

    uint32_t smb = (uint32_t)__cvta_generic_to_shared(sm);
    int tid = threadIdx.x, lane = tid & 31, w = tid >> 5;
    int wm = w / WN, wn = w % WN;
    int NITER = kLen / 32;

    float acc[MT][NT][4] = {};

    #pragma unroll
    for (int s = 0; s < NST; s++) {
        if (s < NITER) g_load<BN, NW>(smb + s * STAGE, A, W, ld, s * 32, n0, tid);
        asm volatile("cp.async.commit_group;" ::: "memory");
    }

    int a_lrow = lane & 15, a_lsel = lane >> 4;
    int b_lrow = (lane & 7) + ((lane >> 4) << 3);
    int b_lsel = (lane >> 3) & 1;

    for (int it = 0; it < NITER; it++) {
        asm volatile("cp.async.wait_group %0;" :: "n"(NST - 1) : "memory");
        __syncthreads();

        uint32_t abase = smb + (it % NST) * STAGE;
        uint32_t bbase = abase + 128 * 128;
        #pragma unroll
        for (int ks = 0; ks < 4; ks++) {
            int cb = 2 * ks;
            uint32_t a[MT][4], b[NT][2];
            #pragma unroll
            for (int mt = 0; mt < MT; mt++) {
                int row = wm * WTM + mt * 16 + a_lrow;
                ldm_x4(a[mt], abase + (uint32_t)(row * 128 +
                       (((cb + a_lsel) ^ (a_lrow & 7)) << 4)));
            }
            #pragma unroll
            for (int j = 0; j < NT / 2; j++) {
                int row = wn * WARPN + j * 16 + b_lrow;
                uint32_t r4[4];
                ldm_x4(r4, bbase + (uint32_t)(row * 128 +
                       (((cb + b_lsel) ^ (b_lrow & 7)) << 4)));
                b[j*2][0] = r4[0]; b[j*2][1] = r4[1];
                b[j*2+1][0] = r4[2]; b[j*2+1][1] = r4[3];
            }
            #pragma unroll
            for (int mt = 0; mt < MT; mt++)
                #pragma unroll
                for (int q = 0; q < 4; q++) cvt_tf32(a[mt][q]);
            #pragma unroll
            for (int nt = 0; nt < NT; nt++) { cvt_tf32(b[nt][0]); cvt_tf32(b[nt][1]); }
            #pragma unroll
            for (int mt = 0; mt < MT; mt++)
                #pragma unroll
                for (int nt = 0; nt < NT; nt++)
                    mma_tf32(acc[mt][nt], a[mt], b[nt]);
        }
        __syncthreads();
        if (it + NST < NITER)
            g_load<BN, NW>(smb + (it % NST) * STAGE, A, W, ld, (it + NST) * 32, n0, tid);
        asm volatile("cp.async.commit_group;" ::: "memory");
    }

    // epilogue
    #pragma unroll
    for (int mt = 0; mt < MT; mt++) {
        int mrow = wm * WTM + mt * 16 + (lane >> 2);
        #pragma unroll
        for (int nt = 0; nt < NT; nt++) {
            int n = n0 + wn * WARPN + nt * 8 + (lane & 3) * 2;
            float b0a = 0.0f, b0b = 0.0f;
            if (ACT != 2) { b0a = bias[n]; b0b = bias[n + 1]; }
            float v0 = acc[mt][nt][0] + b0a;
            float v1 = acc[mt][nt][1] + b0b;
            float v2 = acc[mt][nt][2] + b0a;
            float v3 = acc[mt][nt][3] + b0b;
            if (ACT == 1) { v0 = tanhf(v0); v1 = tanhf(v1); v2 = tanhf(v2); v3 = tanhf(v3); }
            *(float2*)(C + (long)mrow * N + n)       = make_float2(v0, v1);
            *(float2*)(C + (long)(mrow + 8) * N + n) = make_float2(v2, v3);
        }
    }
}

// ---------------------------------------------------------------------------
// Wrappers
template<int BN, int NW, int WN, int NST, int ACT>
__global__ void __launch_bounds__(NW * 32, 3) k_gemm_std(
    const float* __restrict__ A, const float* __restrict__ W, int K,
    const float* __restrict__ bias, float* __restrict__ C, int N)
{
    extern __shared__ char sm[];
    gemm_core<BN, NW, WN, NST, ACT>(A, W, K, K, bias, C, N, blockIdx.x * BN, sm);
}

// dual-source x split-K=2: grid.x = 4 * (N/BN)
// tile = bid>>2, src = (bid>>1)&1, ks = bid&1 -> partial (src? C1:C0)[ks]
template<int BN, int NW, int WN, int NST>
__global__ void __launch_bounds__(NW * 32, 3) k_gemm_ds_sk(
    const float* __restrict__ A0, const float* __restrict__ W0,
    const float* __restrict__ A1, const float* __restrict__ W1, int K,
    float* __restrict__ C0, float* __restrict__ C1, int N)
{
    extern __shared__ char sm[];
    int tile = blockIdx.x >> 2;
    int src  = (blockIdx.x >> 1) & 1;
    int ks   = blockIdx.x & 1;
    int half = K / 2;
    const float* A = (src ? A1 : A0) + ks * half;
    const float* W = (src ? W1 : W0) + ks * half;
    float* C = (src ? C1 : C0) + (long)ks * 128 * N;
    gemm_core<BN, NW, WN, NST, 2>(A, W, K, half, nullptr, C, N, tile * BN, sm);
}

// split-K=4: grid.x = 4 * (N/BN); partials P[ks][128][N]
template<int BN, int NW, int WN, int NST>
__global__ void __launch_bounds__(NW * 32, 3) k_gemm_sk4(
    const float* __restrict__ A, const float* __restrict__ W, int K,
    float* __restrict__ P, int N)
{
    extern __shared__ char sm[];
    int ks = blockIdx.x & 3;
    int tile = blockIdx.x >> 2;
    int q = K / 4;
    gemm_core<BN, NW, WN, NST, 2>(A + ks * q, W + ks * q, K, q, nullptr,
                                  P + (long)ks * 128 * N, N, tile * BN, sm);
}

// ---------------------------------------------------------------------------
// embedding gather
__global__ void k_embed(const float* __restrict__ emb, const int* __restrict__ word) {
    int i = (blockIdx.x * 256 + threadIdx.x) * 4;
    int b = i >> 10, h = i & 1023;
    *(float4*)(g_x + i) = *(const float4*)(emb + (long)word[b] * Hh + h);
}

// ---------------------------------------------------------------------------
// LSTM cell: gates = p0[0]+p0[1]+p1[0]+p1[1]+bih+bhh, then cell update
__global__ void k_lstm_cell(const float* __restrict__ p0, const float* __restrict__ p1,
                            const float* __restrict__ bi, const float* __restrict__ bh,
                            const float* __restrict__ c_prev,
                            float* __restrict__ c_out, float* __restrict__ h_out) {
    int i = (blockIdx.x * 256 + threadIdx.x) * 4;   // B*H
    int b = i >> 10, h = i & 1023;
    long base = (long)b * 4 * Hh;
    float4 gate[4];
    #pragma unroll
    for (int gi = 0; gi < 4; gi++) {
        long off = base + gi * Hh + h;
        float4 a0 = *(const float4*)(p0 + off);
        float4 a1 = *(const float4*)(p0 + PART + off);
        float4 b0v = *(const float4*)(p1 + off);
        float4 b1v = *(const float4*)(p1 + PART + off);
        float4 bb0 = *(const float4*)(bi + gi * Hh + h);
        float4 bb1 = *(const float4*)(bh + gi * Hh + h);
        gate[gi].x = a0.x + a1.x + b0v.x + b1v.x + bb0.x + bb1.x;
        gate[gi].y = a0.y + a1.y + b0v.y + b1v.y + bb0.y + bb1.y;
        gate[gi].z = a0.z + a1.z + b0v.z + b1v.z + bb0.z + bb1.z;
        gate[gi].w = a0.w + a1.w + b0v.w + b1v.w + bb0.w + bb1.w;
    }
    float4 cp = *(const float4*)(c_prev + i);
    float4 c, hv;
    c.x = sigm(gate[1].x) * cp.x + sigm(gate[0].x) * tanhf(gate[2].x); hv.x = sigm(gate[3].x) * tanhf(c.x);
    c.y = sigm(gate[1].y) * cp.y + sigm(gate[0].y) * tanhf(gate[2].y); hv.y = sigm(gate[3].y) * tanhf(c.y);
    c.z = sigm(gate[1].z) * cp.z + sigm(gate[0].z) * tanhf(gate[2].z); hv.z = sigm(gate[3].z) * tanhf(c.z);
    c.w = sigm(gate[1].w) * cp.w + sigm(gate[0].w) * tanhf(gate[2].w); hv.w = sigm(gate[3].w) * tanhf(c.w);
    *(float4*)(c_out + i) = c;
    *(float4*)(h_out + i) = hv;
}

// ---------------------------------------------------------------------------
// 4-partial combine with tanh: out = tanh(P[0]+P[1]+P[2]+P[3] + bias), P[k] is [128][N]
__global__ void k_comb4_tanh(const float* __restrict__ P, const float* __restrict__ bias,
                             float* __restrict__ out, int N) {
    int i = (blockIdx.x * 256 + threadIdx.x) * 4;   // over 128*N
    long s = (long)128 * N;
    int h = i % N;
    float4 a = *(const float4*)(P + i);
    float4 b = *(const float4*)(P + s + i);
    float4 c = *(const float4*)(P + 2 * s + i);
    float4 d = *(const float4*)(P + 3 * s + i);
    float4 bb = *(const float4*)(bias + h);
    float4 v;
    v.x = tanhf(a.x + b.x + c.x + d.x + bb.x);
    v.y = tanhf(a.y + b.y + c.y + d.y + bb.y);
    v.z = tanhf(a.z + b.z + c.z + d.z + bb.z);
    v.w = tanhf(a.w + b.w + c.w + d.w + bb.w);
    *(float4*)(out + i) = v;
}

// ---------------------------------------------------------------------------
// pb[b] = S * sigmoid( sum_j tanh_t[b,j]*w2[j] + b2 )
__global__ void k_attn_p(const float* __restrict__ w2, const float* __restrict__ b2, int S) {
    int b = blockIdx.x, tid = threadIdx.x;
    __shared__ float red[256];
    float s = 0.0f;
    for (int j = tid; j < HH2; j += 256) s += g_t[b * HH2 + j] * w2[j];
    red[tid] = s; __syncthreads();
    for (int st = 128; st > 0; st >>= 1) {
        if (tid < st) red[tid] += red[tid + st];
        __syncthreads();
    }
    if (tid == 0) g_pb[b] = (float)S * sigm(red[0] + b2[0]);
}

// ---------------------------------------------------------------------------
// Windowed attention: scores, softmax*gauss, a (-> d_out), ctx (-> scratch)
__global__ void k_attn_ctx(const float* __restrict__ hout, const float* __restrict__ enc,
                           int S, float* __restrict__ a_out) {
    int b = blockIdx.x, tid = threadIdx.x;
    int warp = tid >> 5, lane = tid & 31;
    float pb = g_pb[b];
    int ws = (int)rintf(fmaxf(pb - WSZF, 0.0f));
    int we = (int)rintf(fminf(pb + WSZF, (float)(S - 1)));
    __shared__ float sc[MAXW], ga[MAXW], aa[MAXW];

    for (int w = warp; w < MAXW; w += 8) {
        int idx = ws + w;
        if (idx <= we) {
            int ic = min(idx, S - 1);
            const float* er = enc + ((long)ic * Bb + b) * Hh;
            const float* orow = hout + (long)b * Hh;
            float dot = 0.0f;
            for (int h = lane; h < Hh; h += 32) dot += orow[h] * er[h];
            #pragma unroll
            for (int o = 16; o > 0; o >>= 1) dot += __shfl_down_sync(0xffffffff, dot, o);
            if (lane == 0) {
                sc[w] = dot;
                ga[w] = expf(((float)idx - pb) / 50.0f);
            }
        } else if (lane == 0) {
            sc[w] = 0.0f;
            ga[w] = 0.0f;
        }
    }
    __syncthreads();
    if (tid < MAXW) {
        float m = -1e30f;
        for (int w = 0; w < MAXW; w++) m = fmaxf(m, sc[w]);
        float den = 0.0f;
        for (int w = 0; w < MAXW; w++) den += expf(sc[w] - m);
        float a = expf(sc[tid] - m) / den * ga[tid];
        aa[tid] = a;
        a_out[b * MAXW + tid] = a;
    }
    __syncthreads();
    for (int h = tid; h < Hh; h += blockDim.x) {
        float s = 0.0f;
        for (int w = 0; w < MAXW; w++) {
            int idx = ws + w;
            if (idx <= we)
                s += aa[w] * enc[((long)idx * Bb + b) * Hh + h];
        }
        g_ctx[b * Hh + h] = s;
    }
}

// ---------------------------------------------------------------------------
// cat = [ctx, out]
__global__ void k_cat(const float* __restrict__ hout) {
    int i = (blockIdx.x * 256 + threadIdx.x) * 4;   // B*2H
    int b = i >> 11, r = i & 2047;
    float4 v;
    if (r < Hh) v = *(const float4*)(g_ctx + b * Hh + r);
    else        v = *(const float4*)(hout + (long)b * Hh + r - Hh);
    *(float4*)(g_cat + i) = v;
}

// ---------------------------------------------------------------------------
// In-place log-softmax over V per row: online (max,sum) pass + subtract pass
__global__ void k_logsoftmax(float* __restrict__ y) {
    int b = blockIdx.x, tid = threadIdx.x;
    float* row = y + (long)b * Vv;
    __shared__ float redm[32], reds[32];
    float m = -1e30f, s = 0.0f;
    for (int j = tid; j < Vv / 4; j += 1024) {
        float4 v = *(const float4*)(row + j * 4);
        float lm = fmaxf(fmaxf(v.x, v.y), fmaxf(v.z, v.w));
        if (lm > m) { s *= __expf(m - lm); m = lm; }
        s += __expf(v.x - m) + __expf(v.y - m) + __expf(v.z - m) + __expf(v.w - m);
    }
    // warp merge of (m, s)
    #pragma unroll
    for (int o = 16; o > 0; o >>= 1) {
        float om = __shfl_xor_sync(~0u, m, o);
        float os = __shfl_xor_sync(~0u, s, o);
        float nm = fmaxf(m, om);
        s = s * __expf(m - nm) + os * __expf(om - nm);
        m = nm;
    }
    if ((tid & 31) == 0) { redm[tid >> 5] = m; reds[tid >> 5] = s; }
    __syncthreads();
    if (tid < 32) {
        m = redm[tid]; s = reds[tid];
        #pragma unroll
        for (int o = 16; o > 0; o >>= 1) {
            float om = __shfl_xor_sync(~0u, m, o);
            float os = __shfl_xor_sync(~0u, s, o);
            float nm = fmaxf(m, om);
            s = s * __expf(m - nm) + os * __expf(om - nm);
            m = nm;
        }
        if (tid == 0) { redm[0] = m; reds[0] = s; }
    }
    __syncthreads();
    float lse = redm[0] + logf(reds[0]);
    for (int j = tid; j < Vv / 4; j += 1024) {
        float4 v = *(const float4*)(row + j * 4);
        v.x -= lse; v.y -= lse; v.z -= lse; v.w -= lse;
        *(float4*)(row + j * 4) = v;
    }
}

// ---------------------------------------------------------------------------
extern "C" void kernel_launch(void* const* d_in, const int* in_sizes, int n_in,
                              void* d_out, int out_size) {
    const float* enc  = (const float*)d_in[1];
    const int*   word = (const int*)  d_in[2];
    const float* h0   = (const float*)d_in[3];
    const float* c0   = (const float*)d_in[4];
    const float* emb  = (const float*)d_in[5];
    const float* Wih  = (const float*)d_in[6];
    const float* Whh  = (const float*)d_in[7];
    const float* bih  = (const float*)d_in[8];
    const float* bhh  = (const float*)d_in[9];
    const float* aw1  = (const float*)d_in[10];
    const float* ab1  = (const float*)d_in[11];
    const float* aw2  = (const float*)d_in[12];
    const float* ab2  = (const float*)d_in[13];
    const float* f1w  = (const float*)d_in[14];
    const float* f1b  = (const float*)d_in[15];
    const float* f2w  = (const float*)d_in[16];
    const float* f2b  = (const float*)d_in[17];

    int S = in_sizes[1] / (Bb * Hh);

    float* out = (float*)d_out;
    float* y   = out + Y_OFF;
    float* o2  = out + O2_OFF;
    float* hN  = out + H_OFF;
    float* cN  = out + C_OFF;
    float* aO  = out + A_OFF;

    const int SZ32 = 3 * (128 + 32) * 128;   // 61440
    const int SZ64 = 3 * (128 + 64) * 128;   // 73728

    static float *p_x = nullptr, *p_g0 = nullptr, *p_g1 = nullptr,
                 *p_t = nullptr, *p_cat = nullptr;
    static bool inited = false;
    if (!inited) {
        cudaGetSymbolAddress((void**)&p_x,   g_x);
        cudaGetSymbolAddress((void**)&p_g0,  g_gates);
        cudaGetSymbolAddress((void**)&p_g1,  g_gates2);
        cudaGetSymbolAddress((void**)&p_t,   g_t);
        cudaGetSymbolAddress((void**)&p_cat, g_cat);
        cudaFuncSetAttribute(k_gemm_ds_sk<32, 4, 1, 3>, cudaFuncAttributeMaxDynamicSharedMemorySize, SZ32);
        cudaFuncSetAttribute(k_gemm_sk4<32, 4, 1, 3>,   cudaFuncAttributeMaxDynamicSharedMemorySize, SZ32);
        cudaFuncSetAttribute(k_gemm_std<64, 4, 1, 3, 0>, cudaFuncAttributeMaxDynamicSharedMemorySize, SZ64);
        inited = true;
    }

    // 1. embedding
    k_embed<<<Bb * Hh / 1024, 256>>>(emb, word);

    // 2. LSTM layers: dual-source x split-K=2 gates GEMM (grid 512) + cell
    for (int l = 0; l < Ll; l++) {
        const float* xin = (l == 0) ? p_x : hN + (long)(l - 1) * Bb * Hh;
        k_gemm_ds_sk<32, 4, 1, 3><<<4 * (4 * Hh / 32), 128, SZ32>>>(
            xin, Wih + (long)l * 4 * Hh * Hh,
            h0 + (long)l * Bb * Hh, Whh + (long)l * 4 * Hh * Hh,
            Hh, p_g0, p_g1, 4 * Hh);
        k_lstm_cell<<<Bb * Hh / 1024, 256>>>(p_g0, p_g1,
                                             bih + (long)l * 4 * Hh, bhh + (long)l * 4 * Hh,
                                             c0 + (long)l * Bb * Hh,
                                             cN + (long)l * Bb * Hh,
                                             hN + (long)l * Bb * Hh);
    }
    const float* hout = hN + (long)(Ll - 1) * Bb * Hh;

    // 3. attention position: split-K=4 proj (grid 64) + tanh-combine, then p
    k_gemm_sk4<32, 4, 1, 3><<<4 * (HH2 / 32), 128, SZ32>>>(
        hout, aw1, Hh, p_g1, HH2);
    k_comb4_tanh<<<Bb * HH2 / 1024, 256>>>(p_g1, ab1, p_t, HH2);
    k_attn_p<<<Bb, 256>>>(aw2, ab2, S);

    // 4. windowed attention -> a, ctx
    k_attn_ctx<<<Bb, 256>>>(hout, enc, S, aO);

    // 5. fc1 (K=2048): split-K=4 (grid 128) + tanh-combine -> o2
    k_cat<<<Bb * 2 * Hh / 1024, 256>>>(hout);
    k_gemm_sk4<32, 4, 1, 3><<<4 * (Hh / 32), 128, SZ32>>>(
        p_cat, f1w, 2 * Hh, p_g0, Hh);
    k_comb4_tanh<<<Bb * Hh / 1024, 256>>>(p_g0, f1b, o2, Hh);

    // 6. fc2 (BN=64, grid 500) + log-softmax
    k_gemm_std<64, 4, 1, 3, 0><<<Vv / 64, 128, SZ64>>>(
        o2, f2w, Hh, f2b, y, Vv);
    k_logsoftmax<<<Bb, 1024>>>(y);
}

// round 8
// speedup vs baseline: 4.8200x; 1.0151x over previous
#include <cuda_runtime.h>
#include <math.h>
#include <stdint.h>

#define Bb   128
#define Hh   1024
#define HH2  512
#define Vv   32000
#define Ll   2
#define MAXW 21
#define WSZF 10.0f

// output layout (concatenated tuple: y, o2, h_new, c_new, a)
#define Y_OFF  0
#define O2_OFF (Bb*Vv)
#define H_OFF  (O2_OFF + Bb*Hh)
#define C_OFF  (H_OFF + Ll*Bb*Hh)
#define A_OFF  (C_OFF + Ll*Bb*Hh)

#define SLAB (Bb*4*Hh)   // one gates partial slab (128 x 4096)

// scratch (device globals — no allocation allowed)
__device__ float g_gates[4*Bb*4*Hh];    // L0 slabs: x-ks0, x-ks1, h-ks0, h-ks1; later fc1 partials
__device__ float g_gates2[4*Bb*4*Hh];   // L1 slabs: h-ks0, h-ks1, x-ks0, x-ks1; later attn partials
__device__ float g_pb[Bb];
__device__ float g_ctx[Bb*Hh];

__device__ __forceinline__ float sigm(float x) { return 1.0f / (1.0f + expf(-x)); }

// ---------------------------------------------------------------------------
// async-copy / mma helpers
__device__ __forceinline__ void cp16(uint32_t dst, const float* src) {
    asm volatile("cp.async.cg.shared.global [%0], [%1], 16;"
                 :: "r"(dst), "l"(__cvta_generic_to_global(src)));
}
__device__ __forceinline__ void ldm_x4(uint32_t* r, uint32_t addr) {
    asm volatile("ldmatrix.sync.aligned.m8n8.x4.shared.b16 {%0,%1,%2,%3}, [%4];"
                 : "=r"(r[0]), "=r"(r[1]), "=r"(r[2]), "=r"(r[3]) : "r"(addr));
}
__device__ __forceinline__ void cvt_tf32(uint32_t& x) {
    asm volatile("cvt.rna.tf32.f32 %0, %0;" : "+r"(x));
}
__device__ __forceinline__ void mma_tf32(float* d, const uint32_t* a, const uint32_t* b) {
    asm volatile("mma.sync.aligned.m16n8k8.row.col.f32.tf32.tf32.f32 "
                 "{%0,%1,%2,%3}, {%4,%5,%6,%7}, {%8,%9}, {%0,%1,%2,%3};"
                 : "+f"(d[0]), "+f"(d[1]), "+f"(d[2]), "+f"(d[3])
                 : "r"(a[0]), "r"(a[1]), "r"(a[2]), "r"(a[3]),
                   "r"(b[0]), "r"(b[1]));
}

// swizzled byte offset of 16B chunk (row stride 128B, 8 chunks/row)
__device__ __forceinline__ uint32_t swz(int row, int chunk) {
    return (uint32_t)(row * 128 + ((chunk ^ (row & 7)) << 4));
}

// ---------------------------------------------------------------------------
// Stage a K-chunk of 32 fp32 cols: A[128 rows] (optionally word-indirect rows),
// W[BN rows] -> swizzled SMEM.
template<int BN, int NW>
__device__ __forceinline__ void g_load(
    uint32_t abase, const float* __restrict__ A, const int* __restrict__ word,
    const float* __restrict__ W, int ldA, int ldW, int kOff,
    int kb, int n0, int tid)
{
    constexpr int THREADS = NW * 32;
    uint32_t bbase = abase + 128 * 128;
    #pragma unroll
    for (int i = 0; i < 1024 / THREADS; i++) {          // A: 128 rows x 8 chunks
        int idx = tid + i * THREADS;
        int r = idx >> 3, c = idx & 7;
        long rowoff = word ? (long)word[r] * ldA : (long)r * ldA;
        cp16(abase + swz(r, c), A + rowoff + kOff + kb + c * 4);
    }
    #pragma unroll
    for (int i = 0; i < BN * 8 / THREADS; i++) {        // B: BN rows x 8 chunks
        int idx = tid + i * THREADS;
        int r = idx >> 3, c = idx & 7;
        cp16(bbase + swz(r, c), W + (long)(n0 + r) * ldW + kb + c * 4);
    }
}

// ---------------------------------------------------------------------------
// Core tf32 mma GEMM: C[128, N](n0..n0+BN) = act( A[128, kLen] @ W^T + bias )
// ACT: 0 = bias, 1 = bias+tanh, 2 = raw (no bias)
template<int BN, int NW, int WN, int NST, int ACT>
__device__ __forceinline__ void gemm_core(
    const float* __restrict__ A, const int* __restrict__ word,
    const float* __restrict__ W, int ldA, int ldW, int kOff, int kLen,
    const float* __restrict__ bias, float* __restrict__ C, int N, int n0, char* sm)
{
    constexpr int STAGE = (128 + BN) * 128;
    constexpr int WARPN = BN / WN, NT = WARPN / 8;
    constexpr int WM = NW / WN, WTM = 128 / WM, MT = WTM / 16;

    uint32_t smb = (uint32_t)__cvta_generic_to_shared(sm);
    int tid = threadIdx.x, lane = tid & 31, w = tid >> 5;
    int wm = w / WN, wn = w % WN;
    int NITER = kLen / 32;

    float acc[MT][NT][4] = {};

    #pragma unroll
    for (int s = 0; s < NST; s++) {
        if (s < NITER)
            g_load<BN, NW>(smb + s * STAGE, A, word, W, ldA, ldW, kOff, s * 32, n0, tid);
        asm volatile("cp.async.commit_group;" ::: "memory");
    }

    int a_lrow = lane & 15, a_lsel = lane >> 4;
    int b_lrow = (lane & 7) + ((lane >> 4) << 3);
    int b_lsel = (lane >> 3) & 1;

    for (int it = 0; it < NITER; it++) {
        asm volatile("cp.async.wait_group %0;" :: "n"(NST - 1) : "memory");
        __syncthreads();

        uint32_t abase = smb + (it % NST) * STAGE;
        uint32_t bbase = abase + 128 * 128;
        #pragma unroll
        for (int ks = 0; ks < 4; ks++) {
            int cb = 2 * ks;
            uint32_t a[MT][4], b[NT][2];
            #pragma unroll
            for (int mt = 0; mt < MT; mt++) {
                int row = wm * WTM + mt * 16 + a_lrow;
                ldm_x4(a[mt], abase + (uint32_t)(row * 128 +
                       (((cb + a_lsel) ^ (a_lrow & 7)) << 4)));
            }
            #pragma unroll
            for (int j = 0; j < NT / 2; j++) {
                int row = wn * WARPN + j * 16 + b_lrow;
                uint32_t r4[4];
                ldm_x4(r4, bbase + (uint32_t)(row * 128 +
                       (((cb + b_lsel) ^ (b_lrow & 7)) << 4)));
                b[j*2][0] = r4[0]; b[j*2][1] = r4[1];
                b[j*2+1][0] = r4[2]; b[j*2+1][1] = r4[3];
            }
            #pragma unroll
            for (int mt = 0; mt < MT; mt++)
                #pragma unroll
                for (int q = 0; q < 4; q++) cvt_tf32(a[mt][q]);
            #pragma unroll
            for (int nt = 0; nt < NT; nt++) { cvt_tf32(b[nt][0]); cvt_tf32(b[nt][1]); }
            #pragma unroll
            for (int mt = 0; mt < MT; mt++)
                #pragma unroll
                for (int nt = 0; nt < NT; nt++)
                    mma_tf32(acc[mt][nt], a[mt], b[nt]);
        }
        __syncthreads();
        if (it + NST < NITER)
            g_load<BN, NW>(smb + (it % NST) * STAGE, A, word, W, ldA, ldW, kOff,
                           (it + NST) * 32, n0, tid);
        asm volatile("cp.async.commit_group;" ::: "memory");
    }

    // epilogue
    #pragma unroll
    for (int mt = 0; mt < MT; mt++) {
        int mrow = wm * WTM + mt * 16 + (lane >> 2);
        #pragma unroll
        for (int nt = 0; nt < NT; nt++) {
            int n = n0 + wn * WARPN + nt * 8 + (lane & 3) * 2;
            float b0a = 0.0f, b0b = 0.0f;
            if (ACT != 2) { b0a = bias[n]; b0b = bias[n + 1]; }
            float v0 = acc[mt][nt][0] + b0a;
            float v1 = acc[mt][nt][1] + b0b;
            float v2 = acc[mt][nt][2] + b0a;
            float v3 = acc[mt][nt][3] + b0b;
            if (ACT == 1) { v0 = tanhf(v0); v1 = tanhf(v1); v2 = tanhf(v2); v3 = tanhf(v3); }
            *(float2*)(C + (long)mrow * N + n)       = make_float2(v0, v1);
            *(float2*)(C + (long)(mrow + 8) * N + n) = make_float2(v2, v3);
        }
    }
}

// ---------------------------------------------------------------------------
// Mega gates launch: job0 = emb[word]@Wih0 (split-K2), job1 = h0[0]@Whh0,
// job2 = h0[1]@Whh1 (layer-1 h-part, independent of layer 0). grid = 768.
__global__ void __launch_bounds__(128, 4) k_mega_gates(
    const float* __restrict__ emb, const int* __restrict__ word,
    const float* __restrict__ h00, const float* __restrict__ Wih0,
    const float* __restrict__ Whh0,
    const float* __restrict__ h01, const float* __restrict__ Whh1,
    float* __restrict__ G0, float* __restrict__ G1)
{
    extern __shared__ char sm[];
    int job = blockIdx.x >> 8;
    int r = blockIdx.x & 255;
    int tile = r >> 1, ks = r & 1;
    const float* A; const int* wd = nullptr; const float* W; float* C; int kOff = 0;
    if (job == 0)      { A = emb;             wd = word; kOff = ks * 512;
                         W = Wih0 + ks * 512; C = G0 + (long)ks * SLAB; }
    else if (job == 1) { A = h00 + ks * 512;  W = Whh0 + ks * 512;
                         C = G0 + (long)(2 + ks) * SLAB; }
    else               { A = h01 + ks * 512;  W = Whh1 + ks * 512;
                         C = G1 + (long)ks * SLAB; }
    gemm_core<32, 4, 1, 2, 2>(A, wd, W, Hh, Hh, kOff, 512, nullptr, C, 4 * Hh, tile * 32, sm);
}

// Layer-1 x-part: h_l0 @ Wih1 (split-K2). grid = 256.
__global__ void __launch_bounds__(128, 4) k_gates_x1(
    const float* __restrict__ hl0, const float* __restrict__ Wih1,
    float* __restrict__ G1)
{
    extern __shared__ char sm[];
    int tile = blockIdx.x >> 1, ks = blockIdx.x & 1;
    gemm_core<32, 4, 1, 2, 2>(hl0 + ks * 512, nullptr, Wih1 + ks * 512,
                              Hh, Hh, 0, 512, nullptr,
                              G1 + (long)(2 + ks) * SLAB, 4 * Hh, tile * 32, sm);
}

// attn proj split-K=4 (K=1024, quarters of 256). grid = 64. partials in g_gates2.
__global__ void __launch_bounds__(128, 4) k_proj_sk4(
    const float* __restrict__ hout, const float* __restrict__ aw1,
    float* __restrict__ P)
{
    extern __shared__ char sm[];
    int ks = blockIdx.x & 3, tile = blockIdx.x >> 2;
    gemm_core<32, 4, 1, 2, 2>(hout + ks * 256, nullptr, aw1 + ks * 256,
                              Hh, Hh, 0, 256, nullptr,
                              P + (long)ks * 128 * HH2, HH2, tile * 32, sm);
}

// fc1 split-K=4 over cat=[ctx|hout] (K=2048): quarters 0,1 from ctx, 2,3 from hout.
// grid = 128. partials in g_gates.
__global__ void __launch_bounds__(128, 4) k_fc1_sk4(
    const float* __restrict__ ctx, const float* __restrict__ hout,
    const float* __restrict__ f1w, float* __restrict__ P)
{
    extern __shared__ char sm[];
    int ks = blockIdx.x & 3, tile = blockIdx.x >> 2;
    const float* A = (ks < 2) ? (ctx + ks * 512) : (hout + (ks - 2) * 512);
    gemm_core<32, 4, 1, 2, 2>(A, nullptr, f1w + ks * 512,
                              Hh, 2 * Hh, 0, 512, nullptr,
                              P + (long)ks * 128 * Hh, Hh, tile * 32, sm);
}

// fc2: BN=64, NST=3. grid = 500.
__global__ void __launch_bounds__(128, 3) k_fc2(
    const float* __restrict__ o2, const float* __restrict__ f2w,
    const float* __restrict__ f2b, float* __restrict__ y)
{
    extern __shared__ char sm[];
    gemm_core<64, 4, 1, 3, 0>(o2, nullptr, f2w, Hh, Hh, 0, Hh, f2b,
                              y, Vv, blockIdx.x * 64, sm);
}

// ---------------------------------------------------------------------------
// LSTM cell: gates = p0[0]+p0[1]+p1[0]+p1[1]+bih+bhh, then cell update
__global__ void k_lstm_cell(const float* __restrict__ p0, const float* __restrict__ p1,
                            const float* __restrict__ bi, const float* __restrict__ bh,
                            const float* __restrict__ c_prev,
                            float* __restrict__ c_out, float* __restrict__ h_out) {
    int i = (blockIdx.x * 256 + threadIdx.x) * 4;   // B*H
    int b = i >> 10, h = i & 1023;
    long base = (long)b * 4 * Hh;
    float4 gate[4];
    #pragma unroll
    for (int gi = 0; gi < 4; gi++) {
        long off = base + gi * Hh + h;
        float4 a0 = *(const float4*)(p0 + off);
        float4 a1 = *(const float4*)(p0 + SLAB + off);
        float4 b0v = *(const float4*)(p1 + off);
        float4 b1v = *(const float4*)(p1 + SLAB + off);
        float4 bb0 = *(const float4*)(bi + gi * Hh + h);
        float4 bb1 = *(const float4*)(bh + gi * Hh + h);
        gate[gi].x = a0.x + a1.x + b0v.x + b1v.x + bb0.x + bb1.x;
        gate[gi].y = a0.y + a1.y + b0v.y + b1v.y + bb0.y + bb1.y;
        gate[gi].z = a0.z + a1.z + b0v.z + b1v.z + bb0.z + bb1.z;
        gate[gi].w = a0.w + a1.w + b0v.w + b1v.w + bb0.w + bb1.w;
    }
    float4 cp = *(const float4*)(c_prev + i);
    float4 c, hv;
    c.x = sigm(gate[1].x) * cp.x + sigm(gate[0].x) * tanhf(gate[2].x); hv.x = sigm(gate[3].x) * tanhf(c.x);
    c.y = sigm(gate[1].y) * cp.y + sigm(gate[0].y) * tanhf(gate[2].y); hv.y = sigm(gate[3].y) * tanhf(c.y);
    c.z = sigm(gate[1].z) * cp.z + sigm(gate[0].z) * tanhf(gate[2].z); hv.z = sigm(gate[3].z) * tanhf(c.z);
    c.w = sigm(gate[1].w) * cp.w + sigm(gate[0].w) * tanhf(gate[2].w); hv.w = sigm(gate[3].w) * tanhf(c.w);
    *(float4*)(c_out + i) = c;
    *(float4*)(h_out + i) = hv;
}

// ---------------------------------------------------------------------------
// 4-partial combine with tanh: out = tanh(P[0]+P[1]+P[2]+P[3] + bias), P[k] is [128][N]
__global__ void k_comb4_tanh(const float* __restrict__ P, const float* __restrict__ bias,
                             float* __restrict__ out, int N) {
    int i = (blockIdx.x * 256 + threadIdx.x) * 4;   // over 128*N
    long s = (long)128 * N;
    int h = i % N;
    float4 a = *(const float4*)(P + i);
    float4 b = *(const float4*)(P + s + i);
    float4 c = *(const float4*)(P + 2 * s + i);
    float4 d = *(const float4*)(P + 3 * s + i);
    float4 bb = *(const float4*)(bias + h);
    float4 v;
    v.x = tanhf(a.x + b.x + c.x + d.x + bb.x);
    v.y = tanhf(a.y + b.y + c.y + d.y + bb.y);
    v.z = tanhf(a.z + b.z + c.z + d.z + bb.z);
    v.w = tanhf(a.w + b.w + c.w + d.w + bb.w);
    *(float4*)(out + i) = v;
}

// ---------------------------------------------------------------------------
// Fused attn position: per row b, combine 4 proj partials + bias, tanh, dot w2,
// sigmoid -> pb[b]. grid = 128 x 128 threads.
__global__ void k_attnpos(const float* __restrict__ P, const float* __restrict__ ab1,
                          const float* __restrict__ w2, const float* __restrict__ b2,
                          int S) {
    int b = blockIdx.x, tid = threadIdx.x;
    long s = (long)128 * HH2;
    long row = (long)b * HH2;
    __shared__ float red[4];
    float acc = 0.0f;
    #pragma unroll
    for (int jj = 0; jj < HH2 / 128; jj++) {
        int j = tid + jj * 128;
        float v = P[row + j] + P[s + row + j] + P[2 * s + row + j] + P[3 * s + row + j]
                + ab1[j];
        acc += tanhf(v) * w2[j];
    }
    #pragma unroll
    for (int o = 16; o > 0; o >>= 1) acc += __shfl_xor_sync(~0u, acc, o);
    if ((tid & 31) == 0) red[tid >> 5] = acc;
    __syncthreads();
    if (tid == 0)
        g_pb[b] = (float)S * sigm(red[0] + red[1] + red[2] + red[3] + b2[0]);
}

// ---------------------------------------------------------------------------
// Windowed attention: scores, softmax*gauss, a (-> d_out), ctx (-> scratch)
__global__ void k_attn_ctx(const float* __restrict__ hout, const float* __restrict__ enc,
                           int S, float* __restrict__ a_out) {
    int b = blockIdx.x, tid = threadIdx.x;
    int warp = tid >> 5, lane = tid & 31;
    float pb = g_pb[b];
    int ws = (int)rintf(fmaxf(pb - WSZF, 0.0f));
    int we = (int)rintf(fminf(pb + WSZF, (float)(S - 1)));
    __shared__ float sc[MAXW], ga[MAXW], aa[MAXW];

    for (int w = warp; w < MAXW; w += 8) {
        int idx = ws + w;
        if (idx <= we) {
            int ic = min(idx, S - 1);
            const float* er = enc + ((long)ic * Bb + b) * Hh;
            const float* orow = hout + (long)b * Hh;
            float dot = 0.0f;
            for (int h = lane; h < Hh; h += 32) dot += orow[h] * er[h];
            #pragma unroll
            for (int o = 16; o > 0; o >>= 1) dot += __shfl_down_sync(0xffffffff, dot, o);
            if (lane == 0) {
                sc[w] = dot;
                ga[w] = expf(((float)idx - pb) / 50.0f);
            }
        } else if (lane == 0) {
            sc[w] = 0.0f;
            ga[w] = 0.0f;
        }
    }
    __syncthreads();
    if (tid < MAXW) {
        float m = -1e30f;
        for (int w = 0; w < MAXW; w++) m = fmaxf(m, sc[w]);
        float den = 0.0f;
        for (int w = 0; w < MAXW; w++) den += expf(sc[w] - m);
        float a = expf(sc[tid] - m) / den * ga[tid];
        aa[tid] = a;
        a_out[b * MAXW + tid] = a;
    }
    __syncthreads();
    for (int h = tid; h < Hh; h += blockDim.x) {
        float s = 0.0f;
        for (int w = 0; w < MAXW; w++) {
            int idx = ws + w;
            if (idx <= we)
                s += aa[w] * enc[((long)idx * Bb + b) * Hh + h];
        }
        g_ctx[b * Hh + h] = s;
    }
}

// ---------------------------------------------------------------------------
// In-place log-softmax over V per row: online (max,sum) pass + subtract pass
__global__ void k_logsoftmax(float* __restrict__ y) {
    int b = blockIdx.x, tid = threadIdx.x;
    float* row = y + (long)b * Vv;
    __shared__ float redm[32], reds[32];
    float m = -1e30f, s = 0.0f;
    for (int j = tid; j < Vv / 4; j += 1024) {
        float4 v = *(const float4*)(row + j * 4);
        float lm = fmaxf(fmaxf(v.x, v.y), fmaxf(v.z, v.w));
        if (lm > m) { s *= __expf(m - lm); m = lm; }
        s += __expf(v.x - m) + __expf(v.y - m) + __expf(v.z - m) + __expf(v.w - m);
    }
    #pragma unroll
    for (int o = 16; o > 0; o >>= 1) {
        float om = __shfl_xor_sync(~0u, m, o);
        float os = __shfl_xor_sync(~0u, s, o);
        float nm = fmaxf(m, om);
        s = s * __expf(m - nm) + os * __expf(om - nm);
        m = nm;
    }
    if ((tid & 31) == 0) { redm[tid >> 5] = m; reds[tid >> 5] = s; }
    __syncthreads();
    if (tid < 32) {
        m = redm[tid]; s = reds[tid];
        #pragma unroll
        for (int o = 16; o > 0; o >>= 1) {
            float om = __shfl_xor_sync(~0u, m, o);
            float os = __shfl_xor_sync(~0u, s, o);
            float nm = fmaxf(m, om);
            s = s * __expf(m - nm) + os * __expf(om - nm);
            m = nm;
        }
        if (tid == 0) { redm[0] = m; reds[0] = s; }
    }
    __syncthreads();
    float lse = redm[0] + logf(reds[0]);
    for (int j = tid; j < Vv / 4; j += 1024) {
        float4 v = *(const float4*)(row + j * 4);
        v.x -= lse; v.y -= lse; v.z -= lse; v.w -= lse;
        *(float4*)(row + j * 4) = v;
    }
}

// ---------------------------------------------------------------------------
extern "C" void kernel_launch(void* const* d_in, const int* in_sizes, int n_in,
                              void* d_out, int out_size) {
    const float* enc  = (const float*)d_in[1];
    const int*   word = (const int*)  d_in[2];
    const float* h0   = (const float*)d_in[3];
    const float* c0   = (const float*)d_in[4];
    const float* emb  = (const float*)d_in[5];
    const float* Wih  = (const float*)d_in[6];
    const float* Whh  = (const float*)d_in[7];
    const float* bih  = (const float*)d_in[8];
    const float* bhh  = (const float*)d_in[9];
    const float* aw1  = (const float*)d_in[10];
    const float* ab1  = (const float*)d_in[11];
    const float* aw2  = (const float*)d_in[12];
    const float* ab2  = (const float*)d_in[13];
    const float* f1w  = (const float*)d_in[14];
    const float* f1b  = (const float*)d_in[15];
    const float* f2w  = (const float*)d_in[16];
    const float* f2b  = (const float*)d_in[17];

    int S = in_sizes[1] / (Bb * Hh);

    float* out = (float*)d_out;
    float* y   = out + Y_OFF;
    float* o2  = out + O2_OFF;
    float* hN  = out + H_OFF;
    float* cN  = out + C_OFF;
    float* aO  = out + A_OFF;

    const int SZ32 = 2 * (128 + 32) * 128;   // 40960
    const int SZ64 = 3 * (128 + 64) * 128;   // 73728

    static float *p_g0 = nullptr, *p_g1 = nullptr, *p_ctx = nullptr;
    static bool inited = false;
    if (!inited) {
        cudaGetSymbolAddress((void**)&p_g0,  g_gates);
        cudaGetSymbolAddress((void**)&p_g1,  g_gates2);
        cudaGetSymbolAddress((void**)&p_ctx, g_ctx);
        cudaFuncSetAttribute(k_mega_gates, cudaFuncAttributeMaxDynamicSharedMemorySize, SZ32);
        cudaFuncSetAttribute(k_gates_x1,   cudaFuncAttributeMaxDynamicSharedMemorySize, SZ32);
        cudaFuncSetAttribute(k_proj_sk4,   cudaFuncAttributeMaxDynamicSharedMemorySize, SZ32);
        cudaFuncSetAttribute(k_fc1_sk4,    cudaFuncAttributeMaxDynamicSharedMemorySize, SZ32);
        cudaFuncSetAttribute(k_fc2,        cudaFuncAttributeMaxDynamicSharedMemorySize, SZ64);
        inited = true;
    }

    const float* h_l0 = hN;                        // layer-0 h output
    const float* hout = hN + (long)Bb * Hh;        // layer-1 h output ("out")

    // 1. mega gates: L0-x (embed fused), L0-h, L1-h — one 768-CTA launch
    k_mega_gates<<<768, 128, SZ32>>>(emb, word,
                                     h0, Wih, Whh,
                                     h0 + (long)Bb * Hh, Whh + (long)4 * Hh * Hh,
                                     p_g0, p_g1);
    // 2. cell 0
    k_lstm_cell<<<Bb * Hh / 1024, 256>>>(p_g0, p_g0 + 2 * (long)SLAB,
                                         bih, bhh, c0, cN, hN);
    // 3. L1-x gates + cell 1
    k_gates_x1<<<256, 128, SZ32>>>(h_l0, Wih + (long)4 * Hh * Hh, p_g1);
    k_lstm_cell<<<Bb * Hh / 1024, 256>>>(p_g1, p_g1 + 2 * (long)SLAB,
                                         bih + 4 * Hh, bhh + 4 * Hh,
                                         c0 + (long)Bb * Hh,
                                         cN + (long)Bb * Hh,
                                         hN + (long)Bb * Hh);

    // 4. attention position: proj split-K4 + fused combine/dot/sigmoid
    k_proj_sk4<<<64, 128, SZ32>>>(hout, aw1, p_g1);
    k_attnpos<<<Bb, 128>>>(p_g1, ab1, aw2, ab2, S);

    // 5. windowed attention -> a, ctx
    k_attn_ctx<<<Bb, 256>>>(hout, enc, S, aO);

    // 6. fc1 split-K4 over [ctx|hout] + tanh-combine -> o2
    k_fc1_sk4<<<128, 128, SZ32>>>(p_ctx, hout, f1w, p_g0);
    k_comb4_tanh<<<Bb * Hh / 1024, 256>>>(p_g0, f1b, o2, Hh);

    // 7. fc2 + log-softmax
    k_fc2<<<Vv / 64, 128, SZ64>>>(o2, f2w, f2b, y);
    k_logsoftmax<<<Bb, 1024>>>(y);
}

// round 9
// speedup vs baseline: 4.8929x; 1.0151x over previous
#include <cuda_runtime.h>
#include <math.h>
#include <stdint.h>

#define Bb   128
#define Hh   1024
#define HH2  512
#define Vv   32000
#define Ll   2
#define MAXW 21
#define WSZF 10.0f
#define NT2  500          // fc2 tiles (Vv/64)

// output layout (concatenated tuple: y, o2, h_new, c_new, a)
#define Y_OFF  0
#define O2_OFF (Bb*Vv)
#define H_OFF  (O2_OFF + Bb*Hh)
#define C_OFF  (H_OFF + Ll*Bb*Hh)
#define A_OFF  (C_OFF + Ll*Bb*Hh)

#define SLAB (Bb*4*Hh)   // one gates partial slab (128 x 4096)

// scratch (device globals — no allocation allowed)
__device__ float g_gates[4*Bb*4*Hh];    // L0 slabs: x-ks0, x-ks1, h-ks0, h-ks1; later fc1 partials
__device__ float g_gates2[6*Bb*4*Hh];   // L1 slabs: h-ks0, h-ks1, x-ks0..3; later attn partials
__device__ float g_pb[Bb];
__device__ float g_ctx[Bb*Hh];
__device__ float g_pm[Bb*NT2];
__device__ float g_ps[Bb*NT2];
__device__ float g_lse[Bb];

__device__ __forceinline__ float sigm(float x) { return 1.0f / (1.0f + expf(-x)); }

// ---------------------------------------------------------------------------
// async-copy / mma helpers
__device__ __forceinline__ void cp16(uint32_t dst, const float* src) {
    asm volatile("cp.async.cg.shared.global [%0], [%1], 16;"
                 :: "r"(dst), "l"(__cvta_generic_to_global(src)));
}
__device__ __forceinline__ void ldm_x4(uint32_t* r, uint32_t addr) {
    asm volatile("ldmatrix.sync.aligned.m8n8.x4.shared.b16 {%0,%1,%2,%3}, [%4];"
                 : "=r"(r[0]), "=r"(r[1]), "=r"(r[2]), "=r"(r[3]) : "r"(addr));
}
__device__ __forceinline__ void cvt_tf32(uint32_t& x) {
    asm volatile("cvt.rna.tf32.f32 %0, %0;" : "+r"(x));
}
__device__ __forceinline__ void mma_tf32(float* d, const uint32_t* a, const uint32_t* b) {
    asm volatile("mma.sync.aligned.m16n8k8.row.col.f32.tf32.tf32.f32 "
                 "{%0,%1,%2,%3}, {%4,%5,%6,%7}, {%8,%9}, {%0,%1,%2,%3};"
                 : "+f"(d[0]), "+f"(d[1]), "+f"(d[2]), "+f"(d[3])
                 : "r"(a[0]), "r"(a[1]), "r"(a[2]), "r"(a[3]),
                   "r"(b[0]), "r"(b[1]));
}

// swizzled byte offset of 16B chunk (row stride 128B, 8 chunks/row)
__device__ __forceinline__ uint32_t swz(int row, int chunk) {
    return (uint32_t)(row * 128 + ((chunk ^ (row & 7)) << 4));
}

// online (m,s) merge
__device__ __forceinline__ void msmerge(float& m, float& s, float om, float os) {
    float nm = fmaxf(m, om);
    s = s * __expf(m - nm) + os * __expf(om - nm);
    m = nm;
}

// ---------------------------------------------------------------------------
// Stage a K-chunk of 32 fp32 cols: A[128 rows] (optionally word-indirect rows),
// W[BN rows] -> swizzled SMEM.
template<int BN, int NW>
__device__ __forceinline__ void g_load(
    uint32_t abase, const float* __restrict__ A, const int* __restrict__ word,
    const float* __restrict__ W, int ldA, int ldW, int kOff,
    int kb, int n0, int tid)
{
    constexpr int THREADS = NW * 32;
    uint32_t bbase = abase + 128 * 128;
    #pragma unroll
    for (int i = 0; i < 1024 / THREADS; i++) {          // A: 128 rows x 8 chunks
        int idx = tid + i * THREADS;
        int r = idx >> 3, c = idx & 7;
        long rowoff = word ? (long)word[r] * ldA : (long)r * ldA;
        cp16(abase + swz(r, c), A + rowoff + kOff + kb + c * 4);
    }
    #pragma unroll
    for (int i = 0; i < BN * 8 / THREADS; i++) {        // B: BN rows x 8 chunks
        int idx = tid + i * THREADS;
        int r = idx >> 3, c = idx & 7;
        cp16(bbase + swz(r, c), W + (long)(n0 + r) * ldW + kb + c * 4);
    }
}

// ---------------------------------------------------------------------------
// Core tf32 mma GEMM. ACT: 0 = bias, 1 = bias+tanh, 2 = raw.
// SMX: emit per-row (max, sumexp) partials for fused log-softmax.
template<int BN, int NW, int WN, int NST, int ACT, int SMX>
__device__ __forceinline__ void gemm_core(
    const float* __restrict__ A, const int* __restrict__ word,
    const float* __restrict__ W, int ldA, int ldW, int kOff, int kLen,
    const float* __restrict__ bias, float* __restrict__ C, int N, int n0, char* sm,
    float* __restrict__ Pm, float* __restrict__ Ps, int tile, int nTiles)
{
    constexpr int STAGE = (128 + BN) * 128;
    constexpr int WARPN = BN / WN, NT = WARPN / 8;
    constexpr int WM = NW / WN, WTM = 128 / WM, MT = WTM / 16;

    uint32_t smb = (uint32_t)__cvta_generic_to_shared(sm);
    int tid = threadIdx.x, lane = tid & 31, w = tid >> 5;
    int wm = w / WN, wn = w % WN;
    int NITER = kLen / 32;

    float acc[MT][NT][4] = {};

    #pragma unroll
    for (int s = 0; s < NST; s++) {
        if (s < NITER)
            g_load<BN, NW>(smb + s * STAGE, A, word, W, ldA, ldW, kOff, s * 32, n0, tid);
        asm volatile("cp.async.commit_group;" ::: "memory");
    }

    int a_lrow = lane & 15, a_lsel = lane >> 4;
    int b_lrow = (lane & 7) + ((lane >> 4) << 3);
    int b_lsel = (lane >> 3) & 1;

    for (int it = 0; it < NITER; it++) {
        asm volatile("cp.async.wait_group %0;" :: "n"(NST - 1) : "memory");
        __syncthreads();

        uint32_t abase = smb + (it % NST) * STAGE;
        uint32_t bbase = abase + 128 * 128;
        #pragma unroll
        for (int ks = 0; ks < 4; ks++) {
            int cb = 2 * ks;
            uint32_t a[MT][4], b[NT][2];
            #pragma unroll
            for (int mt = 0; mt < MT; mt++) {
                int row = wm * WTM + mt * 16 + a_lrow;
                ldm_x4(a[mt], abase + (uint32_t)(row * 128 +
                       (((cb + a_lsel) ^ (a_lrow & 7)) << 4)));
            }
            #pragma unroll
            for (int j = 0; j < NT / 2; j++) {
                int row = wn * WARPN + j * 16 + b_lrow;
                uint32_t r4[4];
                ldm_x4(r4, bbase + (uint32_t)(row * 128 +
                       (((cb + b_lsel) ^ (b_lrow & 7)) << 4)));
                b[j*2][0] = r4[0]; b[j*2][1] = r4[1];
                b[j*2+1][0] = r4[2]; b[j*2+1][1] = r4[3];
            }
            #pragma unroll
            for (int mt = 0; mt < MT; mt++)
                #pragma unroll
                for (int q = 0; q < 4; q++) cvt_tf32(a[mt][q]);
            #pragma unroll
            for (int nt = 0; nt < NT; nt++) { cvt_tf32(b[nt][0]); cvt_tf32(b[nt][1]); }
            #pragma unroll
            for (int mt = 0; mt < MT; mt++)
                #pragma unroll
                for (int nt = 0; nt < NT; nt++)
                    mma_tf32(acc[mt][nt], a[mt], b[nt]);
        }
        __syncthreads();
        if (it + NST < NITER)
            g_load<BN, NW>(smb + (it % NST) * STAGE, A, word, W, ldA, ldW, kOff,
                           (it + NST) * 32, n0, tid);
        asm volatile("cp.async.commit_group;" ::: "memory");
    }

    // epilogue
    #pragma unroll
    for (int mt = 0; mt < MT; mt++) {
        int mrow = wm * WTM + mt * 16 + (lane >> 2);
        float em0 = -1e30f, es0 = 0.0f, em1 = -1e30f, es1 = 0.0f;
        #pragma unroll
        for (int nt = 0; nt < NT; nt++) {
            int n = n0 + wn * WARPN + nt * 8 + (lane & 3) * 2;
            float b0a = 0.0f, b0b = 0.0f;
            if (ACT != 2) { b0a = bias[n]; b0b = bias[n + 1]; }
            float v0 = acc[mt][nt][0] + b0a;
            float v1 = acc[mt][nt][1] + b0b;
            float v2 = acc[mt][nt][2] + b0a;
            float v3 = acc[mt][nt][3] + b0b;
            if (ACT == 1) { v0 = tanhf(v0); v1 = tanhf(v1); v2 = tanhf(v2); v3 = tanhf(v3); }
            if (SMX) {
                float nm = fmaxf(em0, fmaxf(v0, v1));
                es0 = es0 * __expf(em0 - nm) + __expf(v0 - nm) + __expf(v1 - nm);
                em0 = nm;
                nm = fmaxf(em1, fmaxf(v2, v3));
                es1 = es1 * __expf(em1 - nm) + __expf(v2 - nm) + __expf(v3 - nm);
                em1 = nm;
            }
            *(float2*)(C + (long)mrow * N + n)       = make_float2(v0, v1);
            *(float2*)(C + (long)(mrow + 8) * N + n) = make_float2(v2, v3);
        }
        if (SMX) {
            #pragma unroll
            for (int o = 1; o <= 2; o <<= 1) {
                msmerge(em0, es0, __shfl_xor_sync(~0u, em0, o), __shfl_xor_sync(~0u, es0, o));
                msmerge(em1, es1, __shfl_xor_sync(~0u, em1, o), __shfl_xor_sync(~0u, es1, o));
            }
            if ((lane & 3) == 0) {
                Pm[(long)mrow * nTiles + tile]       = em0;
                Ps[(long)mrow * nTiles + tile]       = es0;
                Pm[(long)(mrow + 8) * nTiles + tile] = em1;
                Ps[(long)(mrow + 8) * nTiles + tile] = es1;
            }
        }
    }
}

// ---------------------------------------------------------------------------
// Mega gates: job0 = emb[word]@Wih0 (sk2), job1 = h0[0]@Whh0 (sk2),
// job2 = h0[1]@Whh1 (sk2). BN=64. grid = 384.
__global__ void __launch_bounds__(128, 4) k_mega_gates(
    const float* __restrict__ emb, const int* __restrict__ word,
    const float* __restrict__ h00, const float* __restrict__ Wih0,
    const float* __restrict__ Whh0,
    const float* __restrict__ h01, const float* __restrict__ Whh1,
    float* __restrict__ G0, float* __restrict__ G1)
{
    extern __shared__ char sm[];
    int job = blockIdx.x >> 7;
    int r = blockIdx.x & 127;
    int tile = r >> 1, ks = r & 1;
    const float* A; const int* wd = nullptr; const float* W; float* C; int kOff = 0;
    if (job == 0)      { A = emb;             wd = word; kOff = ks * 512;
                         W = Wih0 + ks * 512; C = G0 + (long)ks * SLAB; }
    else if (job == 1) { A = h00 + ks * 512;  W = Whh0 + ks * 512;
                         C = G0 + (long)(2 + ks) * SLAB; }
    else               { A = h01 + ks * 512;  W = Whh1 + ks * 512;
                         C = G1 + (long)ks * SLAB; }
    gemm_core<64, 4, 1, 2, 2, 0>(A, wd, W, Hh, Hh, kOff, 512, nullptr,
                                 C, 4 * Hh, tile * 64, sm, nullptr, nullptr, 0, 0);
}

// Layer-1 x-part: h_l0 @ Wih1 (split-K4). BN=64. grid = 256.
__global__ void __launch_bounds__(128, 4) k_gates_x1(
    const float* __restrict__ hl0, const float* __restrict__ Wih1,
    float* __restrict__ G1)
{
    extern __shared__ char sm[];
    int tile = blockIdx.x >> 2, ks = blockIdx.x & 3;
    gemm_core<64, 4, 1, 2, 2, 0>(hl0 + ks * 256, nullptr, Wih1 + ks * 256,
                                 Hh, Hh, 0, 256, nullptr,
                                 G1 + (long)(2 + ks) * SLAB, 4 * Hh, tile * 64, sm,
                                 nullptr, nullptr, 0, 0);
}

// attn proj split-K=4 (K quarters of 256). BN=32. grid = 64. partials g_gates2.
__global__ void __launch_bounds__(128, 4) k_proj_sk4(
    const float* __restrict__ hout, const float* __restrict__ aw1,
    float* __restrict__ P)
{
    extern __shared__ char sm[];
    int ks = blockIdx.x & 3, tile = blockIdx.x >> 2;
    gemm_core<32, 4, 1, 2, 2, 0>(hout + ks * 256, nullptr, aw1 + ks * 256,
                                 Hh, Hh, 0, 256, nullptr,
                                 P + (long)ks * 128 * HH2, HH2, tile * 32, sm,
                                 nullptr, nullptr, 0, 0);
}

// fc1 split-K=4 over cat=[ctx|hout]: quarters 0,1 from ctx, 2,3 from hout.
// BN=32. grid = 128. partials g_gates.
__global__ void __launch_bounds__(128, 4) k_fc1_sk4(
    const float* __restrict__ ctx, const float* __restrict__ hout,
    const float* __restrict__ f1w, float* __restrict__ P)
{
    extern __shared__ char sm[];
    int ks = blockIdx.x & 3, tile = blockIdx.x >> 2;
    const float* A = (ks < 2) ? (ctx + ks * 512) : (hout + (ks - 2) * 512);
    gemm_core<32, 4, 1, 2, 2, 0>(A, nullptr, f1w + ks * 512,
                                 Hh, 2 * Hh, 0, 512, nullptr,
                                 P + (long)ks * 128 * Hh, Hh, tile * 32, sm,
                                 nullptr, nullptr, 0, 0);
}

// fc2: BN=64, NST=3, fused softmax partials. grid = 500.
__global__ void __launch_bounds__(128, 3) k_fc2(
    const float* __restrict__ o2, const float* __restrict__ f2w,
    const float* __restrict__ f2b, float* __restrict__ y,
    float* __restrict__ Pm, float* __restrict__ Ps)
{
    extern __shared__ char sm[];
    gemm_core<64, 4, 1, 3, 0, 1>(o2, nullptr, f2w, Hh, Hh, 0, Hh, f2b,
                                 y, Vv, blockIdx.x * 64, sm, Pm, Ps, blockIdx.x, NT2);
}

// ---------------------------------------------------------------------------
// LSTM cell 0: gates = x-ks0 + x-ks1 + h-ks0 + h-ks1 + bih + bhh
__global__ void k_lstm_cell(const float* __restrict__ p0, const float* __restrict__ p1,
                            const float* __restrict__ bi, const float* __restrict__ bh,
                            const float* __restrict__ c_prev,
                            float* __restrict__ c_out, float* __restrict__ h_out) {
    int i = (blockIdx.x * 256 + threadIdx.x) * 4;   // B*H
    int b = i >> 10, h = i & 1023;
    long base = (long)b * 4 * Hh;
    float4 gate[4];
    #pragma unroll
    for (int gi = 0; gi < 4; gi++) {
        long off = base + gi * Hh + h;
        float4 a0 = *(const float4*)(p0 + off);
        float4 a1 = *(const float4*)(p0 + SLAB + off);
        float4 b0v = *(const float4*)(p1 + off);
        float4 b1v = *(const float4*)(p1 + SLAB + off);
        float4 bb0 = *(const float4*)(bi + gi * Hh + h);
        float4 bb1 = *(const float4*)(bh + gi * Hh + h);
        gate[gi].x = a0.x + a1.x + b0v.x + b1v.x + bb0.x + bb1.x;
        gate[gi].y = a0.y + a1.y + b0v.y + b1v.y + bb0.y + bb1.y;
        gate[gi].z = a0.z + a1.z + b0v.z + b1v.z + bb0.z + bb1.z;
        gate[gi].w = a0.w + a1.w + b0v.w + b1v.w + bb0.w + bb1.w;
    }
    float4 cp = *(const float4*)(c_prev + i);
    float4 c, hv;
    c.x = sigm(gate[1].x) * cp.x + sigm(gate[0].x) * tanhf(gate[2].x); hv.x = sigm(gate[3].x) * tanhf(c.x);
    c.y = sigm(gate[1].y) * cp.y + sigm(gate[0].y) * tanhf(gate[2].y); hv.y = sigm(gate[3].y) * tanhf(c.y);
    c.z = sigm(gate[1].z) * cp.z + sigm(gate[0].z) * tanhf(gate[2].z); hv.z = sigm(gate[3].z) * tanhf(c.z);
    c.w = sigm(gate[1].w) * cp.w + sigm(gate[0].w) * tanhf(gate[2].w); hv.w = sigm(gate[3].w) * tanhf(c.w);
    *(float4*)(c_out + i) = c;
    *(float4*)(h_out + i) = hv;
}

// LSTM cell 1: gates = h-ks0 + h-ks1 + x-ks0..3 + bih + bhh (6 slabs in P)
__global__ void k_lstm_cell6(const float* __restrict__ P,
                             const float* __restrict__ bi, const float* __restrict__ bh,
                             const float* __restrict__ c_prev,
                             float* __restrict__ c_out, float* __restrict__ h_out) {
    int i = (blockIdx.x * 256 + threadIdx.x) * 4;   // B*H
    int b = i >> 10, h = i & 1023;
    long base = (long)b * 4 * Hh;
    float4 gate[4];
    #pragma unroll
    for (int gi = 0; gi < 4; gi++) {
        long off = base + gi * Hh + h;
        float4 v = *(const float4*)(P + off);
        #pragma unroll
        for (int sl = 1; sl < 6; sl++) {
            float4 u = *(const float4*)(P + (long)sl * SLAB + off);
            v.x += u.x; v.y += u.y; v.z += u.z; v.w += u.w;
        }
        float4 bb0 = *(const float4*)(bi + gi * Hh + h);
        float4 bb1 = *(const float4*)(bh + gi * Hh + h);
        gate[gi].x = v.x + bb0.x + bb1.x;
        gate[gi].y = v.y + bb0.y + bb1.y;
        gate[gi].z = v.z + bb0.z + bb1.z;
        gate[gi].w = v.w + bb0.w + bb1.w;
    }
    float4 cp = *(const float4*)(c_prev + i);
    float4 c, hv;
    c.x = sigm(gate[1].x) * cp.x + sigm(gate[0].x) * tanhf(gate[2].x); hv.x = sigm(gate[3].x) * tanhf(c.x);
    c.y = sigm(gate[1].y) * cp.y + sigm(gate[0].y) * tanhf(gate[2].y); hv.y = sigm(gate[3].y) * tanhf(c.y);
    c.z = sigm(gate[1].z) * cp.z + sigm(gate[0].z) * tanhf(gate[2].z); hv.z = sigm(gate[3].z) * tanhf(c.z);
    c.w = sigm(gate[1].w) * cp.w + sigm(gate[0].w) * tanhf(gate[2].w); hv.w = sigm(gate[3].w) * tanhf(c.w);
    *(float4*)(c_out + i) = c;
    *(float4*)(h_out + i) = hv;
}

// ---------------------------------------------------------------------------
// 4-partial combine with tanh (fc1)
__global__ void k_comb4_tanh(const float* __restrict__ P, const float* __restrict__ bias,
                             float* __restrict__ out, int N) {
    int i = (blockIdx.x * 256 + threadIdx.x) * 4;   // over 128*N
    long s = (long)128 * N;
    int h = i % N;
    float4 a = *(const float4*)(P + i);
    float4 b = *(const float4*)(P + s + i);
    float4 c = *(const float4*)(P + 2 * s + i);
    float4 d = *(const float4*)(P + 3 * s + i);
    float4 bb = *(const float4*)(bias + h);
    float4 v;
    v.x = tanhf(a.x + b.x + c.x + d.x + bb.x);
    v.y = tanhf(a.y + b.y + c.y + d.y + bb.y);
    v.z = tanhf(a.z + b.z + c.z + d.z + bb.z);
    v.w = tanhf(a.w + b.w + c.w + d.w + bb.w);
    *(float4*)(out + i) = v;
}

// ---------------------------------------------------------------------------
// Fused attn position: combine 4 proj partials + bias, tanh, dot w2, sigmoid -> pb
__global__ void k_attnpos(const float* __restrict__ P, const float* __restrict__ ab1,
                          const float* __restrict__ w2, const float* __restrict__ b2,
                          int S) {
    int b = blockIdx.x, tid = threadIdx.x;
    long s = (long)128 * HH2;
    long row = (long)b * HH2;
    __shared__ float red[4];
    float acc = 0.0f;
    #pragma unroll
    for (int jj = 0; jj < HH2 / 128; jj++) {
        int j = tid + jj * 128;
        float v = P[row + j] + P[s + row + j] + P[2 * s + row + j] + P[3 * s + row + j]
                + ab1[j];
        acc += tanhf(v) * w2[j];
    }
    #pragma unroll
    for (int o = 16; o > 0; o >>= 1) acc += __shfl_xor_sync(~0u, acc, o);
    if ((tid & 31) == 0) red[tid >> 5] = acc;
    __syncthreads();
    if (tid == 0)
        g_pb[b] = (float)S * sigm(red[0] + red[1] + red[2] + red[3] + b2[0]);
}

// ---------------------------------------------------------------------------
// Windowed attention: scores, softmax*gauss, a (-> d_out), ctx (-> scratch)
__global__ void k_attn_ctx(const float* __restrict__ hout, const float* __restrict__ enc,
                           int S, float* __restrict__ a_out) {
    int b = blockIdx.x, tid = threadIdx.x;
    int warp = tid >> 5, lane = tid & 31;
    float pb = g_pb[b];
    int ws = (int)rintf(fmaxf(pb - WSZF, 0.0f));
    int we = (int)rintf(fminf(pb + WSZF, (float)(S - 1)));
    __shared__ float sc[MAXW], ga[MAXW], aa[MAXW];

    for (int w = warp; w < MAXW; w += 8) {
        int idx = ws + w;
        if (idx <= we) {
            int ic = min(idx, S - 1);
            const float* er = enc + ((long)ic * Bb + b) * Hh;
            const float* orow = hout + (long)b * Hh;
            float dot = 0.0f;
            for (int h = lane; h < Hh; h += 32) dot += orow[h] * er[h];
            #pragma unroll
            for (int o = 16; o > 0; o >>= 1) dot += __shfl_down_sync(0xffffffff, dot, o);
            if (lane == 0) {
                sc[w] = dot;
                ga[w] = expf(((float)idx - pb) / 50.0f);
            }
        } else if (lane == 0) {
            sc[w] = 0.0f;
            ga[w] = 0.0f;
        }
    }
    __syncthreads();
    if (tid < MAXW) {
        float m = -1e30f;
        for (int w = 0; w < MAXW; w++) m = fmaxf(m, sc[w]);
        float den = 0.0f;
        for (int w = 0; w < MAXW; w++) den += expf(sc[w] - m);
        float a = expf(sc[tid] - m) / den * ga[tid];
        aa[tid] = a;
        a_out[b * MAXW + tid] = a;
    }
    __syncthreads();
    for (int h = tid; h < Hh; h += blockDim.x) {
        float s = 0.0f;
        for (int w = 0; w < MAXW; w++) {
            int idx = ws + w;
            if (idx <= we)
                s += aa[w] * enc[((long)idx * Bb + b) * Hh + h];
        }
        g_ctx[b * Hh + h] = s;
    }
}

// ---------------------------------------------------------------------------
// Merge fc2 per-tile (m,s) partials -> lse[row]
__global__ void k_ls_merge() {
    int row = blockIdx.x, tid = threadIdx.x;   // 128 threads
    int lane = tid & 31, w = tid >> 5;
    __shared__ float rm[4], rs[4];
    float m = -1e30f, s = 0.0f;
    for (int t = tid; t < NT2; t += 128)
        msmerge(m, s, g_pm[(long)row * NT2 + t], g_ps[(long)row * NT2 + t]);
    #pragma unroll
    for (int o = 16; o > 0; o >>= 1)
        msmerge(m, s, __shfl_xor_sync(~0u, m, o), __shfl_xor_sync(~0u, s, o));
    if (lane == 0) { rm[w] = m; rs[w] = s; }
    __syncthreads();
    if (tid == 0) {
        m = rm[0]; s = rs[0];
        msmerge(m, s, rm[1], rs[1]);
        msmerge(m, s, rm[2], rs[2]);
        msmerge(m, s, rm[3], rs[3]);
        g_lse[row] = m + logf(s);
    }
}

// Subtract lse in-place
__global__ void k_ls_sub(float* __restrict__ y) {
    long i = ((long)blockIdx.x * 256 + threadIdx.x) * 4;
    int row = (int)(i / Vv);
    float lse = g_lse[row];
    float4 v = *(const float4*)(y + i);
    v.x -= lse; v.y -= lse; v.z -= lse; v.w -= lse;
    *(float4*)(y + i) = v;
}

// ---------------------------------------------------------------------------
extern "C" void kernel_launch(void* const* d_in, const int* in_sizes, int n_in,
                              void* d_out, int out_size) {
    const float* enc  = (const float*)d_in[1];
    const int*   word = (const int*)  d_in[2];
    const float* h0   = (const float*)d_in[3];
    const float* c0   = (const float*)d_in[4];
    const float* emb  = (const float*)d_in[5];
    const float* Wih  = (const float*)d_in[6];
    const float* Whh  = (const float*)d_in[7];
    const float* bih  = (const float*)d_in[8];
    const float* bhh  = (const float*)d_in[9];
    const float* aw1  = (const float*)d_in[10];
    const float* ab1  = (const float*)d_in[11];
    const float* aw2  = (const float*)d_in[12];
    const float* ab2  = (const float*)d_in[13];
    const float* f1w  = (const float*)d_in[14];
    const float* f1b  = (const float*)d_in[15];
    const float* f2w  = (const float*)d_in[16];
    const float* f2b  = (const float*)d_in[17];

    int S = in_sizes[1] / (Bb * Hh);

    float* out = (float*)d_out;
    float* y   = out + Y_OFF;
    float* o2  = out + O2_OFF;
    float* hN  = out + H_OFF;
    float* cN  = out + C_OFF;
    float* aO  = out + A_OFF;

    const int SZ32  = 2 * (128 + 32) * 128;   // 40960
    const int SZ64G = 2 * (128 + 64) * 128;   // 49152
    const int SZ64F = 3 * (128 + 64) * 128;   // 73728

    static float *p_g0 = nullptr, *p_g1 = nullptr, *p_ctx = nullptr,
                 *p_pm = nullptr, *p_ps = nullptr;
    static bool inited = false;
    if (!inited) {
        cudaGetSymbolAddress((void**)&p_g0,  g_gates);
        cudaGetSymbolAddress((void**)&p_g1,  g_gates2);
        cudaGetSymbolAddress((void**)&p_ctx, g_ctx);
        cudaGetSymbolAddress((void**)&p_pm,  g_pm);
        cudaGetSymbolAddress((void**)&p_ps,  g_ps);
        cudaFuncSetAttribute(k_mega_gates, cudaFuncAttributeMaxDynamicSharedMemorySize, SZ64G);
        cudaFuncSetAttribute(k_gates_x1,   cudaFuncAttributeMaxDynamicSharedMemorySize, SZ64G);
        cudaFuncSetAttribute(k_proj_sk4,   cudaFuncAttributeMaxDynamicSharedMemorySize, SZ32);
        cudaFuncSetAttribute(k_fc1_sk4,    cudaFuncAttributeMaxDynamicSharedMemorySize, SZ32);
        cudaFuncSetAttribute(k_fc2,        cudaFuncAttributeMaxDynamicSharedMemorySize, SZ64F);
        inited = true;
    }

    const float* h_l0 = hN;                        // layer-0 h output
    const float* hout = hN + (long)Bb * Hh;        // layer-1 h output ("out")

    // 1. mega gates: L0-x (embed fused), L0-h, L1-h — one 384-CTA launch
    k_mega_gates<<<384, 128, SZ64G>>>(emb, word,
                                      h0, Wih, Whh,
                                      h0 + (long)Bb * Hh, Whh + (long)4 * Hh * Hh,
                                      p_g0, p_g1);
    // 2. cell 0
    k_lstm_cell<<<Bb * Hh / 1024, 256>>>(p_g0, p_g0 + 2 * (long)SLAB,
                                         bih, bhh, c0, cN, hN);
    // 3. L1-x gates (split-K4) + cell 1 (6 partial slabs)
    k_gates_x1<<<256, 128, SZ64G>>>(h_l0, Wih + (long)4 * Hh * Hh, p_g1);
    k_lstm_cell6<<<Bb * Hh / 1024, 256>>>(p_g1,
                                          bih + 4 * Hh, bhh + 4 * Hh,
                                          c0 + (long)Bb * Hh,
                                          cN + (long)Bb * Hh,
                                          hN + (long)Bb * Hh);

    // 4. attention position: proj split-K4 + fused combine/dot/sigmoid
    k_proj_sk4<<<64, 128, SZ32>>>(hout, aw1, p_g1);
    k_attnpos<<<Bb, 128>>>(p_g1, ab1, aw2, ab2, S);

    // 5. windowed attention -> a, ctx
    k_attn_ctx<<<Bb, 256>>>(hout, enc, S, aO);

    // 6. fc1 split-K4 over [ctx|hout] + tanh-combine -> o2
    k_fc1_sk4<<<128, 128, SZ32>>>(p_ctx, hout, f1w, p_g0);
    k_comb4_tanh<<<Bb * Hh / 1024, 256>>>(p_g0, f1b, o2, Hh);

    // 7. fc2 (fused softmax partials) + merge + subtract
    k_fc2<<<NT2, 128, SZ64F>>>(o2, f2w, f2b, y, p_pm, p_ps);
    k_ls_merge<<<Bb, 128>>>();
    k_ls_sub<<<Bb * Vv / 1024, 256>>>(y);
}

// round 10
// speedup vs baseline: 4.9887x; 1.0196x over previous
#include <cuda_runtime.h>
#include <math.h>
#include <stdint.h>

#define Bb   128
#define Hh   1024
#define HH2  512
#define Vv   32000
#define Ll   2
#define MAXW 21
#define WSZF 10.0f
#define NT2  500          // fc2 softmax partial slots (250 tiles x 2 warp-cols)

// output layout (concatenated tuple: y, o2, h_new, c_new, a)
#define Y_OFF  0
#define O2_OFF (Bb*Vv)
#define H_OFF  (O2_OFF + Bb*Hh)
#define C_OFF  (H_OFF + Ll*Bb*Hh)
#define A_OFF  (C_OFF + Ll*Bb*Hh)

#define SLAB (Bb*4*Hh)   // one gates partial slab (128 x 4096)

// scratch (device globals — no allocation allowed)
__device__ float g_gates[4*Bb*4*Hh];    // L0 slabs: x-ks0, x-ks1, h-ks0, h-ks1; later fc1 partials
__device__ float g_gates2[6*Bb*4*Hh];   // L1 slabs: h-ks0, h-ks1, x-ks0..3; later attn partials
__device__ float g_pb[Bb];
__device__ float g_ctx[Bb*Hh];
__device__ float g_pm[Bb*NT2];
__device__ float g_ps[Bb*NT2];
__device__ float g_lse[Bb];

__device__ __forceinline__ float sigm(float x) { return 1.0f / (1.0f + expf(-x)); }

// ---------------------------------------------------------------------------
// async-copy / mma helpers
__device__ __forceinline__ void cp16(uint32_t dst, const float* src) {
    asm volatile("cp.async.cg.shared.global [%0], [%1], 16;"
                 :: "r"(dst), "l"(__cvta_generic_to_global(src)));
}
__device__ __forceinline__ void ldm_x4(uint32_t* r, uint32_t addr) {
    asm volatile("ldmatrix.sync.aligned.m8n8.x4.shared.b16 {%0,%1,%2,%3}, [%4];"
                 : "=r"(r[0]), "=r"(r[1]), "=r"(r[2]), "=r"(r[3]) : "r"(addr));
}
__device__ __forceinline__ void cvt_tf32(uint32_t& x) {
    asm volatile("cvt.rna.tf32.f32 %0, %0;" : "+r"(x));
}
__device__ __forceinline__ void mma_tf32(float* d, const uint32_t* a, const uint32_t* b) {
    asm volatile("mma.sync.aligned.m16n8k8.row.col.f32.tf32.tf32.f32 "
                 "{%0,%1,%2,%3}, {%4,%5,%6,%7}, {%8,%9}, {%0,%1,%2,%3};"
                 : "+f"(d[0]), "+f"(d[1]), "+f"(d[2]), "+f"(d[3])
                 : "r"(a[0]), "r"(a[1]), "r"(a[2]), "r"(a[3]),
                   "r"(b[0]), "r"(b[1]));
}

// swizzled byte offset of 16B chunk (row stride 128B, 8 chunks/row)
__device__ __forceinline__ uint32_t swz(int row, int chunk) {
    return (uint32_t)(row * 128 + ((chunk ^ (row & 7)) << 4));
}

// online (m,s) merge
__device__ __forceinline__ void msmerge(float& m, float& s, float om, float os) {
    float nm = fmaxf(m, om);
    s = s * __expf(m - nm) + os * __expf(om - nm);
    m = nm;
}

// ---------------------------------------------------------------------------
// Stage a K-chunk of 32 fp32 cols: A[128 rows] (optionally word-indirect rows),
// W[BN rows] -> swizzled SMEM.
template<int BN, int NW>
__device__ __forceinline__ void g_load(
    uint32_t abase, const float* __restrict__ A, const int* __restrict__ word,
    const float* __restrict__ W, int ldA, int ldW, int kOff,
    int kb, int n0, int tid)
{
    constexpr int THREADS = NW * 32;
    uint32_t bbase = abase + 128 * 128;
    #pragma unroll
    for (int i = 0; i < 1024 / THREADS; i++) {          // A: 128 rows x 8 chunks
        int idx = tid + i * THREADS;
        int r = idx >> 3, c = idx & 7;
        long rowoff = word ? (long)word[r] * ldA : (long)r * ldA;
        cp16(abase + swz(r, c), A + rowoff + kOff + kb + c * 4);
    }
    #pragma unroll
    for (int i = 0; i < BN * 8 / THREADS; i++) {        // B: BN rows x 8 chunks
        int idx = tid + i * THREADS;
        int r = idx >> 3, c = idx & 7;
        cp16(bbase + swz(r, c), W + (long)(n0 + r) * ldW + kb + c * 4);
    }
}

// ---------------------------------------------------------------------------
// Core tf32 mma GEMM. ACT: 0 = bias, 1 = bias+tanh, 2 = raw.
// SMX: emit per-row (max, sumexp) partials for fused log-softmax
// (slot = tile + wn so multiple N-warps don't collide).
template<int BN, int NW, int WN, int NST, int ACT, int SMX>
__device__ __forceinline__ void gemm_core(
    const float* __restrict__ A, const int* __restrict__ word,
    const float* __restrict__ W, int ldA, int ldW, int kOff, int kLen,
    const float* __restrict__ bias, float* __restrict__ C, int N, int n0, char* sm,
    float* __restrict__ Pm, float* __restrict__ Ps, int tile, int nTiles)
{
    constexpr int STAGE = (128 + BN) * 128;
    constexpr int WARPN = BN / WN, NT = WARPN / 8;
    constexpr int WM = NW / WN, WTM = 128 / WM, MT = WTM / 16;

    uint32_t smb = (uint32_t)__cvta_generic_to_shared(sm);
    int tid = threadIdx.x, lane = tid & 31, w = tid >> 5;
    int wm = w / WN, wn = w % WN;
    int NITER = kLen / 32;

    float acc[MT][NT][4] = {};

    #pragma unroll
    for (int s = 0; s < NST; s++) {
        if (s < NITER)
            g_load<BN, NW>(smb + s * STAGE, A, word, W, ldA, ldW, kOff, s * 32, n0, tid);
        asm volatile("cp.async.commit_group;" ::: "memory");
    }

    int a_lrow = lane & 15, a_lsel = lane >> 4;
    int b_lrow = (lane & 7) + ((lane >> 4) << 3);
    int b_lsel = (lane >> 3) & 1;

    for (int it = 0; it < NITER; it++) {
        asm volatile("cp.async.wait_group %0;" :: "n"(NST - 1) : "memory");
        __syncthreads();

        uint32_t abase = smb + (it % NST) * STAGE;
        uint32_t bbase = abase + 128 * 128;
        #pragma unroll
        for (int ks = 0; ks < 4; ks++) {
            int cb = 2 * ks;
            uint32_t a[MT][4], b[NT][2];
            #pragma unroll
            for (int mt = 0; mt < MT; mt++) {
                int row = wm * WTM + mt * 16 + a_lrow;
                ldm_x4(a[mt], abase + (uint32_t)(row * 128 +
                       (((cb + a_lsel) ^ (a_lrow & 7)) << 4)));
            }
            #pragma unroll
            for (int j = 0; j < NT / 2; j++) {
                int row = wn * WARPN + j * 16 + b_lrow;
                uint32_t r4[4];
                ldm_x4(r4, bbase + (uint32_t)(row * 128 +
                       (((cb + b_lsel) ^ (b_lrow & 7)) << 4)));
                b[j*2][0] = r4[0]; b[j*2][1] = r4[1];
                b[j*2+1][0] = r4[2]; b[j*2+1][1] = r4[3];
            }
            #pragma unroll
            for (int mt = 0; mt < MT; mt++)
                #pragma unroll
                for (int q = 0; q < 4; q++) cvt_tf32(a[mt][q]);
            #pragma unroll
            for (int nt = 0; nt < NT; nt++) { cvt_tf32(b[nt][0]); cvt_tf32(b[nt][1]); }
            #pragma unroll
            for (int mt = 0; mt < MT; mt++)
                #pragma unroll
                for (int nt = 0; nt < NT; nt++)
                    mma_tf32(acc[mt][nt], a[mt], b[nt]);
        }
        __syncthreads();
        if (it + NST < NITER)
            g_load<BN, NW>(smb + (it % NST) * STAGE, A, word, W, ldA, ldW, kOff,
                           (it + NST) * 32, n0, tid);
        asm volatile("cp.async.commit_group;" ::: "memory");
    }

    // epilogue
    #pragma unroll
    for (int mt = 0; mt < MT; mt++) {
        int mrow = wm * WTM + mt * 16 + (lane >> 2);
        float em0 = -1e30f, es0 = 0.0f, em1 = -1e30f, es1 = 0.0f;
        #pragma unroll
        for (int nt = 0; nt < NT; nt++) {
            int n = n0 + wn * WARPN + nt * 8 + (lane & 3) * 2;
            float b0a = 0.0f, b0b = 0.0f;
            if (ACT != 2) { b0a = bias[n]; b0b = bias[n + 1]; }
            float v0 = acc[mt][nt][0] + b0a;
            float v1 = acc[mt][nt][1] + b0b;
            float v2 = acc[mt][nt][2] + b0a;
            float v3 = acc[mt][nt][3] + b0b;
            if (ACT == 1) { v0 = tanhf(v0); v1 = tanhf(v1); v2 = tanhf(v2); v3 = tanhf(v3); }
            if (SMX) {
                float nm = fmaxf(em0, fmaxf(v0, v1));
                es0 = es0 * __expf(em0 - nm) + __expf(v0 - nm) + __expf(v1 - nm);
                em0 = nm;
                nm = fmaxf(em1, fmaxf(v2, v3));
                es1 = es1 * __expf(em1 - nm) + __expf(v2 - nm) + __expf(v3 - nm);
                em1 = nm;
            }
            *(float2*)(C + (long)mrow * N + n)       = make_float2(v0, v1);
            *(float2*)(C + (long)(mrow + 8) * N + n) = make_float2(v2, v3);
        }
        if (SMX) {
            #pragma unroll
            for (int o = 1; o <= 2; o <<= 1) {
                msmerge(em0, es0, __shfl_xor_sync(~0u, em0, o), __shfl_xor_sync(~0u, es0, o));
                msmerge(em1, es1, __shfl_xor_sync(~0u, em1, o), __shfl_xor_sync(~0u, es1, o));
            }
            if ((lane & 3) == 0) {
                int slot = tile + wn;
                Pm[(long)mrow * nTiles + slot]       = em0;
                Ps[(long)mrow * nTiles + slot]       = es0;
                Pm[(long)(mrow + 8) * nTiles + slot] = em1;
                Ps[(long)(mrow + 8) * nTiles + slot] = es1;
            }
        }
    }
}

// ---------------------------------------------------------------------------
// Mega gates: job0 = emb[word]@Wih0 (sk2), job1 = h0[0]@Whh0 (sk2),
// job2 = h0[1]@Whh1 (sk2). BN=64. grid = 384.
__global__ void __launch_bounds__(128, 4) k_mega_gates(
    const float* __restrict__ emb, const int* __restrict__ word,
    const float* __restrict__ h00, const float* __restrict__ Wih0,
    const float* __restrict__ Whh0,
    const float* __restrict__ h01, const float* __restrict__ Whh1,
    float* __restrict__ G0, float* __restrict__ G1)
{
    extern __shared__ char sm[];
    int job = blockIdx.x >> 7;
    int r = blockIdx.x & 127;
    int tile = r >> 1, ks = r & 1;
    const float* A; const int* wd = nullptr; const float* W; float* C; int kOff = 0;
    if (job == 0)      { A = emb;             wd = word; kOff = ks * 512;
                         W = Wih0 + ks * 512; C = G0 + (long)ks * SLAB; }
    else if (job == 1) { A = h00 + ks * 512;  W = Whh0 + ks * 512;
                         C = G0 + (long)(2 + ks) * SLAB; }
    else               { A = h01 + ks * 512;  W = Whh1 + ks * 512;
                         C = G1 + (long)ks * SLAB; }
    gemm_core<64, 4, 1, 2, 2, 0>(A, wd, W, Hh, Hh, kOff, 512, nullptr,
                                 C, 4 * Hh, tile * 64, sm, nullptr, nullptr, 0, 0);
}

// Layer-1 x-part: h_l0 @ Wih1 (split-K4). BN=64. grid = 256.
__global__ void __launch_bounds__(128, 4) k_gates_x1(
    const float* __restrict__ hl0, const float* __restrict__ Wih1,
    float* __restrict__ G1)
{
    extern __shared__ char sm[];
    int tile = blockIdx.x >> 2, ks = blockIdx.x & 3;
    gemm_core<64, 4, 1, 2, 2, 0>(hl0 + ks * 256, nullptr, Wih1 + ks * 256,
                                 Hh, Hh, 0, 256, nullptr,
                                 G1 + (long)(2 + ks) * SLAB, 4 * Hh, tile * 64, sm,
                                 nullptr, nullptr, 0, 0);
}

// attn proj split-K=4 (K quarters of 256). BN=32. grid = 64. partials g_gates2.
__global__ void __launch_bounds__(128, 4) k_proj_sk4(
    const float* __restrict__ hout, const float* __restrict__ aw1,
    float* __restrict__ P)
{
    extern __shared__ char sm[];
    int ks = blockIdx.x & 3, tile = blockIdx.x >> 2;
    gemm_core<32, 4, 1, 2, 2, 0>(hout + ks * 256, nullptr, aw1 + ks * 256,
                                 Hh, Hh, 0, 256, nullptr,
                                 P + (long)ks * 128 * HH2, HH2, tile * 32, sm,
                                 nullptr, nullptr, 0, 0);
}

// fc1 split-K=4 over cat=[ctx|hout]: quarters 0,1 from ctx, 2,3 from hout.
// BN=32. grid = 128. partials g_gates.
__global__ void __launch_bounds__(128, 4) k_fc1_sk4(
    const float* __restrict__ ctx, const float* __restrict__ hout,
    const float* __restrict__ f1w, float* __restrict__ P)
{
    extern __shared__ char sm[];
    int ks = blockIdx.x & 3, tile = blockIdx.x >> 2;
    const float* A = (ks < 2) ? (ctx + ks * 512) : (hout + (ks - 2) * 512);
    gemm_core<32, 4, 1, 2, 2, 0>(A, nullptr, f1w + ks * 512,
                                 Hh, 2 * Hh, 0, 512, nullptr,
                                 P + (long)ks * 128 * Hh, Hh, tile * 32, sm,
                                 nullptr, nullptr, 0, 0);
}

// fc2: BN=128, 256 threads, WN=2, NST=3, fused softmax partials. grid = 250.
__global__ void __launch_bounds__(256, 2) k_fc2(
    const float* __restrict__ o2, const float* __restrict__ f2w,
    const float* __restrict__ f2b, float* __restrict__ y,
    float* __restrict__ Pm, float* __restrict__ Ps)
{
    extern __shared__ char sm[];
    gemm_core<128, 8, 2, 3, 0, 1>(o2, nullptr, f2w, Hh, Hh, 0, Hh, f2b,
                                  y, Vv, blockIdx.x * 128, sm, Pm, Ps,
                                  blockIdx.x * 2, NT2);
}

// ---------------------------------------------------------------------------
// LSTM cell 0: gates = x-ks0 + x-ks1 + h-ks0 + h-ks1 + bih + bhh
__global__ void k_lstm_cell(const float* __restrict__ p0, const float* __restrict__ p1,
                            const float* __restrict__ bi, const float* __restrict__ bh,
                            const float* __restrict__ c_prev,
                            float* __restrict__ c_out, float* __restrict__ h_out) {
    int i = (blockIdx.x * 256 + threadIdx.x) * 4;   // B*H
    int b = i >> 10, h = i & 1023;
    long base = (long)b * 4 * Hh;
    float4 gate[4];
    #pragma unroll
    for (int gi = 0; gi < 4; gi++) {
        long off = base + gi * Hh + h;
        float4 a0 = *(const float4*)(p0 + off);
        float4 a1 = *(const float4*)(p0 + SLAB + off);
        float4 b0v = *(const float4*)(p1 + off);
        float4 b1v = *(const float4*)(p1 + SLAB + off);
        float4 bb0 = *(const float4*)(bi + gi * Hh + h);
        float4 bb1 = *(const float4*)(bh + gi * Hh + h);
        gate[gi].x = a0.x + a1.x + b0v.x + b1v.x + bb0.x + bb1.x;
        gate[gi].y = a0.y + a1.y + b0v.y + b1v.y + bb0.y + bb1.y;
        gate[gi].z = a0.z + a1.z + b0v.z + b1v.z + bb0.z + bb1.z;
        gate[gi].w = a0.w + a1.w + b0v.w + b1v.w + bb0.w + bb1.w;
    }
    float4 cp = *(const float4*)(c_prev + i);
    float4 c, hv;
    c.x = sigm(gate[1].x) * cp.x + sigm(gate[0].x) * tanhf(gate[2].x); hv.x = sigm(gate[3].x) * tanhf(c.x);
    c.y = sigm(gate[1].y) * cp.y + sigm(gate[0].y) * tanhf(gate[2].y); hv.y = sigm(gate[3].y) * tanhf(c.y);
    c.z = sigm(gate[1].z) * cp.z + sigm(gate[0].z) * tanhf(gate[2].z); hv.z = sigm(gate[3].z) * tanhf(c.z);
    c.w = sigm(gate[1].w) * cp.w + sigm(gate[0].w) * tanhf(gate[2].w); hv.w = sigm(gate[3].w) * tanhf(c.w);
    *(float4*)(c_out + i) = c;
    *(float4*)(h_out + i) = hv;
}

// LSTM cell 1: gates = h-ks0 + h-ks1 + x-ks0..3 + bih + bhh (6 slabs in P)
__global__ void k_lstm_cell6(const float* __restrict__ P,
                             const float* __restrict__ bi, const float* __restrict__ bh,
                             const float* __restrict__ c_prev,
                             float* __restrict__ c_out, float* __restrict__ h_out) {
    int i = (blockIdx.x * 256 + threadIdx.x) * 4;   // B*H
    int b = i >> 10, h = i & 1023;
    long base = (long)b * 4 * Hh;
    float4 gate[4];
    #pragma unroll
    for (int gi = 0; gi < 4; gi++) {
        long off = base + gi * Hh + h;
        float4 v = *(const float4*)(P + off);
        #pragma unroll
        for (int sl = 1; sl < 6; sl++) {
            float4 u = *(const float4*)(P + (long)sl * SLAB + off);
            v.x += u.x; v.y += u.y; v.z += u.z; v.w += u.w;
        }
        float4 bb0 = *(const float4*)(bi + gi * Hh + h);
        float4 bb1 = *(const float4*)(bh + gi * Hh + h);
        gate[gi].x = v.x + bb0.x + bb1.x;
        gate[gi].y = v.y + bb0.y + bb1.y;
        gate[gi].z = v.z + bb0.z + bb1.z;
        gate[gi].w = v.w + bb0.w + bb1.w;
    }
    float4 cp = *(const float4*)(c_prev + i);
    float4 c, hv;
    c.x = sigm(gate[1].x) * cp.x + sigm(gate[0].x) * tanhf(gate[2].x); hv.x = sigm(gate[3].x) * tanhf(c.x);
    c.y = sigm(gate[1].y) * cp.y + sigm(gate[0].y) * tanhf(gate[2].y); hv.y = sigm(gate[3].y) * tanhf(c.y);
    c.z = sigm(gate[1].z) * cp.z + sigm(gate[0].z) * tanhf(gate[2].z); hv.z = sigm(gate[3].z) * tanhf(c.z);
    c.w = sigm(gate[1].w) * cp.w + sigm(gate[0].w) * tanhf(gate[2].w); hv.w = sigm(gate[3].w) * tanhf(c.w);
    *(float4*)(c_out + i) = c;
    *(float4*)(h_out + i) = hv;
}

// ---------------------------------------------------------------------------
// 4-partial combine with tanh (fc1)
__global__ void k_comb4_tanh(const float* __restrict__ P, const float* __restrict__ bias,
                             float* __restrict__ out, int N) {
    int i = (blockIdx.x * 256 + threadIdx.x) * 4;   // over 128*N
    long s = (long)128 * N;
    int h = i % N;
    float4 a = *(const float4*)(P + i);
    float4 b = *(const float4*)(P + s + i);
    float4 c = *(const float4*)(P + 2 * s + i);
    float4 d = *(const float4*)(P + 3 * s + i);
    float4 bb = *(const float4*)(bias + h);
    float4 v;
    v.x = tanhf(a.x + b.x + c.x + d.x + bb.x);
    v.y = tanhf(a.y + b.y + c.y + d.y + bb.y);
    v.z = tanhf(a.z + b.z + c.z + d.z + bb.z);
    v.w = tanhf(a.w + b.w + c.w + d.w + bb.w);
    *(float4*)(out + i) = v;
}

// ---------------------------------------------------------------------------
// Fused attn position: combine 4 proj partials + bias, tanh, dot w2, sigmoid -> pb
__global__ void k_attnpos(const float* __restrict__ P, const float* __restrict__ ab1,
                          const float* __restrict__ w2, const float* __restrict__ b2,
                          int S) {
    int b = blockIdx.x, tid = threadIdx.x;
    long s = (long)128 * HH2;
    long row = (long)b * HH2;
    __shared__ float red[4];
    float acc = 0.0f;
    #pragma unroll
    for (int jj = 0; jj < HH2 / 128; jj++) {
        int j = tid + jj * 128;
        float v = P[row + j] + P[s + row + j] + P[2 * s + row + j] + P[3 * s + row + j]
                + ab1[j];
        acc += tanhf(v) * w2[j];
    }
    #pragma unroll
    for (int o = 16; o > 0; o >>= 1) acc += __shfl_xor_sync(~0u, acc, o);
    if ((tid & 31) == 0) red[tid >> 5] = acc;
    __syncthreads();
    if (tid == 0)
        g_pb[b] = (float)S * sigm(red[0] + red[1] + red[2] + red[3] + b2[0]);
}

// ---------------------------------------------------------------------------
// Windowed attention (512 threads): scores, softmax*gauss, a, ctx
__global__ void k_attn_ctx(const float* __restrict__ hout, const float* __restrict__ enc,
                           int S, float* __restrict__ a_out) {
    int b = blockIdx.x, tid = threadIdx.x;
    int warp = tid >> 5, lane = tid & 31;
    float pb = g_pb[b];
    int ws = (int)rintf(fmaxf(pb - WSZF, 0.0f));
    int we = (int)rintf(fminf(pb + WSZF, (float)(S - 1)));
    __shared__ float sc[MAXW], ga[MAXW], aa[MAXW];

    for (int w = warp; w < MAXW; w += 16) {
        int idx = ws + w;
        if (idx <= we) {
            int ic = min(idx, S - 1);
            const float* er = enc + ((long)ic * Bb + b) * Hh;
            const float* orow = hout + (long)b * Hh;
            float dot = 0.0f;
            for (int h = lane; h < Hh; h += 32) dot += orow[h] * er[h];
            #pragma unroll
            for (int o = 16; o > 0; o >>= 1) dot += __shfl_down_sync(0xffffffff, dot, o);
            if (lane == 0) {
                sc[w] = dot;
                ga[w] = expf(((float)idx - pb) / 50.0f);
            }
        } else if (lane == 0) {
            sc[w] = 0.0f;
            ga[w] = 0.0f;
        }
    }
    __syncthreads();
    if (tid < MAXW) {
        float m = -1e30f;
        for (int w = 0; w < MAXW; w++) m = fmaxf(m, sc[w]);
        float den = 0.0f;
        for (int w = 0; w < MAXW; w++) den += expf(sc[w] - m);
        float a = expf(sc[tid] - m) / den * ga[tid];
        aa[tid] = a;
        a_out[b * MAXW + tid] = a;
    }
    __syncthreads();
    for (int h = tid; h < Hh; h += blockDim.x) {
        float s = 0.0f;
        for (int w = 0; w < MAXW; w++) {
            int idx = ws + w;
            if (idx <= we)
                s += aa[w] * enc[((long)idx * Bb + b) * Hh + h];
        }
        g_ctx[b * Hh + h] = s;
    }
}

// ---------------------------------------------------------------------------
// Merge fc2 per-slot (m,s) partials -> lse[row]
__global__ void k_ls_merge() {
    int row = blockIdx.x, tid = threadIdx.x;   // 128 threads
    int lane = tid & 31, w = tid >> 5;
    __shared__ float rm[4], rs[4];
    float m = -1e30f, s = 0.0f;
    for (int t = tid; t < NT2; t += 128)
        msmerge(m, s, g_pm[(long)row * NT2 + t], g_ps[(long)row * NT2 + t]);
    #pragma unroll
    for (int o = 16; o > 0; o >>= 1)
        msmerge(m, s, __shfl_xor_sync(~0u, m, o), __shfl_xor_sync(~0u, s, o));
    if (lane == 0) { rm[w] = m; rs[w] = s; }
    __syncthreads();
    if (tid == 0) {
        m = rm[0]; s = rs[0];
        msmerge(m, s, rm[1], rs[1]);
        msmerge(m, s, rm[2], rs[2]);
        msmerge(m, s, rm[3], rs[3]);
        g_lse[row] = m + logf(s);
    }
}

// Subtract lse in-place
__global__ void k_ls_sub(float* __restrict__ y) {
    long i = ((long)blockIdx.x * 256 + threadIdx.x) * 4;
    int row = (int)(i / Vv);
    float lse = g_lse[row];
    float4 v = *(const float4*)(y + i);
    v.x -= lse; v.y -= lse; v.z -= lse; v.w -= lse;
    *(float4*)(y + i) = v;
}

// ---------------------------------------------------------------------------
extern "C" void kernel_launch(void* const* d_in, const int* in_sizes, int n_in,
                              void* d_out, int out_size) {
    const float* enc  = (const float*)d_in[1];
    const int*   word = (const int*)  d_in[2];
    const float* h0   = (const float*)d_in[3];
    const float* c0   = (const float*)d_in[4];
    const float* emb  = (const float*)d_in[5];
    const float* Wih  = (const float*)d_in[6];
    const float* Whh  = (const float*)d_in[7];
    const float* bih  = (const float*)d_in[8];
    const float* bhh  = (const float*)d_in[9];
    const float* aw1  = (const float*)d_in[10];
    const float* ab1  = (const float*)d_in[11];
    const float* aw2  = (const float*)d_in[12];
    const float* ab2  = (const float*)d_in[13];
    const float* f1w  = (const float*)d_in[14];
    const float* f1b  = (const float*)d_in[15];
    const float* f2w  = (const float*)d_in[16];
    const float* f2b  = (const float*)d_in[17];

    int S = in_sizes[1] / (Bb * Hh);

    float* out = (float*)d_out;
    float* y   = out + Y_OFF;
    float* o2  = out + O2_OFF;
    float* hN  = out + H_OFF;
    float* cN  = out + C_OFF;
    float* aO  = out + A_OFF;

    const int SZ32   = 2 * (128 + 32) * 128;    // 40960
    const int SZ64G  = 2 * (128 + 64) * 128;    // 49152
    const int SZ128F = 3 * (128 + 128) * 128;   // 98304

    static float *p_g0 = nullptr, *p_g1 = nullptr, *p_ctx = nullptr,
                 *p_pm = nullptr, *p_ps = nullptr;
    static bool inited = false;
    if (!inited) {
        cudaGetSymbolAddress((void**)&p_g0,  g_gates);
        cudaGetSymbolAddress((void**)&p_g1,  g_gates2);
        cudaGetSymbolAddress((void**)&p_ctx, g_ctx);
        cudaGetSymbolAddress((void**)&p_pm,  g_pm);
        cudaGetSymbolAddress((void**)&p_ps,  g_ps);
        cudaFuncSetAttribute(k_mega_gates, cudaFuncAttributeMaxDynamicSharedMemorySize, SZ64G);
        cudaFuncSetAttribute(k_gates_x1,   cudaFuncAttributeMaxDynamicSharedMemorySize, SZ64G);
        cudaFuncSetAttribute(k_proj_sk4,   cudaFuncAttributeMaxDynamicSharedMemorySize, SZ32);
        cudaFuncSetAttribute(k_fc1_sk4,    cudaFuncAttributeMaxDynamicSharedMemorySize, SZ32);
        cudaFuncSetAttribute(k_fc2,        cudaFuncAttributeMaxDynamicSharedMemorySize, SZ128F);
        inited = true;
    }

    const float* h_l0 = hN;                        // layer-0 h output
    const float* hout = hN + (long)Bb * Hh;        // layer-1 h output ("out")

    // 1. mega gates: L0-x (embed fused), L0-h, L1-h — one 384-CTA launch
    k_mega_gates<<<384, 128, SZ64G>>>(emb, word,
                                      h0, Wih, Whh,
                                      h0 + (long)Bb * Hh, Whh + (long)4 * Hh * Hh,
                                      p_g0, p_g1);
    // 2. cell 0
    k_lstm_cell<<<Bb * Hh / 1024, 256>>>(p_g0, p_g0 + 2 * (long)SLAB,
                                         bih, bhh, c0, cN, hN);
    // 3. L1-x gates (split-K4) + cell 1 (6 partial slabs)
    k_gates_x1<<<256, 128, SZ64G>>>(h_l0, Wih + (long)4 * Hh * Hh, p_g1);
    k_lstm_cell6<<<Bb * Hh / 1024, 256>>>(p_g1,
                                          bih + 4 * Hh, bhh + 4 * Hh,
                                          c0 + (long)Bb * Hh,
                                          cN + (long)Bb * Hh,
                                          hN + (long)Bb * Hh);

    // 4. attention position: proj split-K4 + fused combine/dot/sigmoid
    k_proj_sk4<<<64, 128, SZ32>>>(hout, aw1, p_g1);
    k_attnpos<<<Bb, 128>>>(p_g1, ab1, aw2, ab2, S);

    // 5. windowed attention -> a, ctx
    k_attn_ctx<<<Bb, 512>>>(hout, enc, S, aO);

    // 6. fc1 split-K4 over [ctx|hout] + tanh-combine -> o2
    k_fc1_sk4<<<128, 128, SZ32>>>(p_ctx, hout, f1w, p_g0);
    k_comb4_tanh<<<Bb * Hh / 1024, 256>>>(p_g0, f1b, o2, Hh);

    // 7. fc2 (BN=128, fused softmax partials) + merge + subtract
    k_fc2<<<Vv / 128, 256, SZ128F>>>(o2, f2w, f2b, y, p_pm, p_ps);
    k_ls_merge<<<Bb, 128>>>();
    k_ls_sub<<<Bb * Vv / 1024, 256>>>(y);
}

// round 11
// speedup vs baseline: 5.1183x; 1.0260x over previous
#include <cuda_runtime.h>
#include <math.h>
#include <stdint.h>

#define Bb   128
#define Hh   1024
#define HH2  512
#define Vv   32000
#define Ll   2
#define MAXW 21
#define WSZF 10.0f
#define NT2  500          // fc2 softmax partial slots (250 tiles x 2 warp-cols)

// output layout (concatenated tuple: y, o2, h_new, c_new, a)
#define Y_OFF  0
#define O2_OFF (Bb*Vv)
#define H_OFF  (O2_OFF + Bb*Hh)
#define C_OFF  (H_OFF + Ll*Bb*Hh)
#define A_OFF  (C_OFF + Ll*Bb*Hh)

#define SLAB (Bb*4*Hh)   // one gates partial slab (128 x 4096)

// scratch (device globals — no allocation allowed)
__device__ float g_gates[4*Bb*4*Hh];    // L0 slabs: x-ks0, x-ks1, h-ks0, h-ks1; later fc1 partials
__device__ float g_gates2[6*Bb*4*Hh];   // L1 slabs: h-ks0, h-ks1, x-ks0..3; later attn partials
__device__ float g_pb[Bb];
__device__ float g_ctx[Bb*Hh];
__device__ float g_pm[Bb*NT2];
__device__ float g_ps[Bb*NT2];
__device__ float g_lse[Bb];

__device__ __forceinline__ float sigm(float x) { return 1.0f / (1.0f + expf(-x)); }

// ---------------------------------------------------------------------------
// async-copy / mma helpers
__device__ __forceinline__ void cp16(uint32_t dst, const float* src) {
    asm volatile("cp.async.cg.shared.global [%0], [%1], 16;"
                 :: "r"(dst), "l"(__cvta_generic_to_global(src)));
}
__device__ __forceinline__ void ldm_x4(uint32_t* r, uint32_t addr) {
    asm volatile("ldmatrix.sync.aligned.m8n8.x4.shared.b16 {%0,%1,%2,%3}, [%4];"
                 : "=r"(r[0]), "=r"(r[1]), "=r"(r[2]), "=r"(r[3]) : "r"(addr));
}
__device__ __forceinline__ void cvt_tf32(uint32_t& x) {
    asm volatile("cvt.rna.tf32.f32 %0, %0;" : "+r"(x));
}
__device__ __forceinline__ void mma_tf32(float* d, const uint32_t* a, const uint32_t* b) {
    asm volatile("mma.sync.aligned.m16n8k8.row.col.f32.tf32.tf32.f32 "
                 "{%0,%1,%2,%3}, {%4,%5,%6,%7}, {%8,%9}, {%0,%1,%2,%3};"
                 : "+f"(d[0]), "+f"(d[1]), "+f"(d[2]), "+f"(d[3])
                 : "r"(a[0]), "r"(a[1]), "r"(a[2]), "r"(a[3]),
                   "r"(b[0]), "r"(b[1]));
}

// swizzled byte offset of 16B chunk (row stride 128B, 8 chunks/row)
__device__ __forceinline__ uint32_t swz(int row, int chunk) {
    return (uint32_t)(row * 128 + ((chunk ^ (row & 7)) << 4));
}

// online (m,s) merge
__device__ __forceinline__ void msmerge(float& m, float& s, float om, float os) {
    float nm = fmaxf(m, om);
    s = s * __expf(m - nm) + os * __expf(om - nm);
    m = nm;
}

// ---------------------------------------------------------------------------
// Stage a K-chunk of 32 fp32 cols: A[128 rows] (optionally word-indirect rows),
// W[BN rows] -> swizzled SMEM.
template<int BN, int NW>
__device__ __forceinline__ void g_load(
    uint32_t abase, const float* __restrict__ A, const int* __restrict__ word,
    const float* __restrict__ W, int ldA, int ldW, int kOff,
    int kb, int n0, int tid)
{
    constexpr int THREADS = NW * 32;
    uint32_t bbase = abase + 128 * 128;
    #pragma unroll
    for (int i = 0; i < 1024 / THREADS; i++) {          // A: 128 rows x 8 chunks
        int idx = tid + i * THREADS;
        int r = idx >> 3, c = idx & 7;
        long rowoff = word ? (long)word[r] * ldA : (long)r * ldA;
        cp16(abase + swz(r, c), A + rowoff + kOff + kb + c * 4);
    }
    #pragma unroll
    for (int i = 0; i < BN * 8 / THREADS; i++) {        // B: BN rows x 8 chunks
        int idx = tid + i * THREADS;
        int r = idx >> 3, c = idx & 7;
        cp16(bbase + swz(r, c), W + (long)(n0 + r) * ldW + kb + c * 4);
    }
}

// ---------------------------------------------------------------------------
// Core tf32 mma GEMM. ACT: 0 = bias, 1 = bias+tanh, 2 = raw.
// SMX: emit per-row (max, sumexp) partials for fused log-softmax
// (slot = tile + wn so multiple N-warps don't collide).
template<int BN, int NW, int WN, int NST, int ACT, int SMX>
__device__ __forceinline__ void gemm_core(
    const float* __restrict__ A, const int* __restrict__ word,
    const float* __restrict__ W, int ldA, int ldW, int kOff, int kLen,
    const float* __restrict__ bias, float* __restrict__ C, int N, int n0, char* sm,
    float* __restrict__ Pm, float* __restrict__ Ps, int tile, int nTiles)
{
    constexpr int STAGE = (128 + BN) * 128;
    constexpr int WARPN = BN / WN, NT = WARPN / 8;
    constexpr int WM = NW / WN, WTM = 128 / WM, MT = WTM / 16;

    uint32_t smb = (uint32_t)__cvta_generic_to_shared(sm);
    int tid = threadIdx.x, lane = tid & 31, w = tid >> 5;
    int wm = w / WN, wn = w % WN;
    int NITER = kLen / 32;

    float acc[MT][NT][4] = {};

    #pragma unroll
    for (int s = 0; s < NST; s++) {
        if (s < NITER)
            g_load<BN, NW>(smb + s * STAGE, A, word, W, ldA, ldW, kOff, s * 32, n0, tid);
        asm volatile("cp.async.commit_group;" ::: "memory");
    }

    int a_lrow = lane & 15, a_lsel = lane >> 4;
    int b_lrow = (lane & 7) + ((lane >> 4) << 3);
    int b_lsel = (lane >> 3) & 1;

    for (int it = 0; it < NITER; it++) {
        asm volatile("cp.async.wait_group %0;" :: "n"(NST - 1) : "memory");
        __syncthreads();

        uint32_t abase = smb + (it % NST) * STAGE;
        uint32_t bbase = abase + 128 * 128;
        #pragma unroll
        for (int ks = 0; ks < 4; ks++) {
            int cb = 2 * ks;
            uint32_t a[MT][4], b[NT][2];
            #pragma unroll
            for (int mt = 0; mt < MT; mt++) {
                int row = wm * WTM + mt * 16 + a_lrow;
                ldm_x4(a[mt], abase + (uint32_t)(row * 128 +
                       (((cb + a_lsel) ^ (a_lrow & 7)) << 4)));
            }
            #pragma unroll
            for (int j = 0; j < NT / 2; j++) {
                int row = wn * WARPN + j * 16 + b_lrow;
                uint32_t r4[4];
                ldm_x4(r4, bbase + (uint32_t)(row * 128 +
                       (((cb + b_lsel) ^ (b_lrow & 7)) << 4)));
                b[j*2][0] = r4[0]; b[j*2][1] = r4[1];
                b[j*2+1][0] = r4[2]; b[j*2+1][1] = r4[3];
            }
            #pragma unroll
            for (int mt = 0; mt < MT; mt++)
                #pragma unroll
                for (int q = 0; q < 4; q++) cvt_tf32(a[mt][q]);
            #pragma unroll
            for (int nt = 0; nt < NT; nt++) { cvt_tf32(b[nt][0]); cvt_tf32(b[nt][1]); }
            #pragma unroll
            for (int mt = 0; mt < MT; mt++)
                #pragma unroll
                for (int nt = 0; nt < NT; nt++)
                    mma_tf32(acc[mt][nt], a[mt], b[nt]);
        }
        __syncthreads();
        if (it + NST < NITER)
            g_load<BN, NW>(smb + (it % NST) * STAGE, A, word, W, ldA, ldW, kOff,
                           (it + NST) * 32, n0, tid);
        asm volatile("cp.async.commit_group;" ::: "memory");
    }

    // epilogue
    #pragma unroll
    for (int mt = 0; mt < MT; mt++) {
        int mrow = wm * WTM + mt * 16 + (lane >> 2);
        float em0 = -1e30f, es0 = 0.0f, em1 = -1e30f, es1 = 0.0f;
        #pragma unroll
        for (int nt = 0; nt < NT; nt++) {
            int n = n0 + wn * WARPN + nt * 8 + (lane & 3) * 2;
            float b0a = 0.0f, b0b = 0.0f;
            if (ACT != 2) { b0a = bias[n]; b0b = bias[n + 1]; }
            float v0 = acc[mt][nt][0] + b0a;
            float v1 = acc[mt][nt][1] + b0b;
            float v2 = acc[mt][nt][2] + b0a;
            float v3 = acc[mt][nt][3] + b0b;
            if (ACT == 1) { v0 = tanhf(v0); v1 = tanhf(v1); v2 = tanhf(v2); v3 = tanhf(v3); }
            if (SMX) {
                float nm = fmaxf(em0, fmaxf(v0, v1));
                es0 = es0 * __expf(em0 - nm) + __expf(v0 - nm) + __expf(v1 - nm);
                em0 = nm;
                nm = fmaxf(em1, fmaxf(v2, v3));
                es1 = es1 * __expf(em1 - nm) + __expf(v2 - nm) + __expf(v3 - nm);
                em1 = nm;
            }
            *(float2*)(C + (long)mrow * N + n)       = make_float2(v0, v1);
            *(float2*)(C + (long)(mrow + 8) * N + n) = make_float2(v2, v3);
        }
        if (SMX) {
            #pragma unroll
            for (int o = 1; o <= 2; o <<= 1) {
                msmerge(em0, es0, __shfl_xor_sync(~0u, em0, o), __shfl_xor_sync(~0u, es0, o));
                msmerge(em1, es1, __shfl_xor_sync(~0u, em1, o), __shfl_xor_sync(~0u, es1, o));
            }
            if ((lane & 3) == 0) {
                int slot = tile + wn;
                Pm[(long)mrow * nTiles + slot]       = em0;
                Ps[(long)mrow * nTiles + slot]       = es0;
                Pm[(long)(mrow + 8) * nTiles + slot] = em1;
                Ps[(long)(mrow + 8) * nTiles + slot] = es1;
            }
        }
    }
}

// ---------------------------------------------------------------------------
// Mega gates: job0 = emb[word]@Wih0 (sk2), job1 = h0[0]@Whh0 (sk2),
// job2 = h0[1]@Whh1 (sk2). BN=64. grid = 384.
__global__ void __launch_bounds__(128, 4) k_mega_gates(
    const float* __restrict__ emb, const int* __restrict__ word,
    const float* __restrict__ h00, const float* __restrict__ Wih0,
    const float* __restrict__ Whh0,
    const float* __restrict__ h01, const float* __restrict__ Whh1,
    float* __restrict__ G0, float* __restrict__ G1)
{
    extern __shared__ char sm[];
    int job = blockIdx.x >> 7;
    int r = blockIdx.x & 127;
    int tile = r >> 1, ks = r & 1;
    const float* A; const int* wd = nullptr; const float* W; float* C; int kOff = 0;
    if (job == 0)      { A = emb;             wd = word; kOff = ks * 512;
                         W = Wih0 + ks * 512; C = G0 + (long)ks * SLAB; }
    else if (job == 1) { A = h00 + ks * 512;  W = Whh0 + ks * 512;
                         C = G0 + (long)(2 + ks) * SLAB; }
    else               { A = h01 + ks * 512;  W = Whh1 + ks * 512;
                         C = G1 + (long)ks * SLAB; }
    gemm_core<64, 4, 1, 2, 2, 0>(A, wd, W, Hh, Hh, kOff, 512, nullptr,
                                 C, 4 * Hh, tile * 64, sm, nullptr, nullptr, 0, 0);
}

// Layer-1 x-part: h_l0 @ Wih1 (split-K4). BN=64. grid = 256.
__global__ void __launch_bounds__(128, 4) k_gates_x1(
    const float* __restrict__ hl0, const float* __restrict__ Wih1,
    float* __restrict__ G1)
{
    extern __shared__ char sm[];
    int tile = blockIdx.x >> 2, ks = blockIdx.x & 3;
    gemm_core<64, 4, 1, 2, 2, 0>(hl0 + ks * 256, nullptr, Wih1 + ks * 256,
                                 Hh, Hh, 0, 256, nullptr,
                                 G1 + (long)(2 + ks) * SLAB, 4 * Hh, tile * 64, sm,
                                 nullptr, nullptr, 0, 0);
}

// attn proj split-K=4 (K quarters of 256). BN=32. grid = 64. partials g_gates2.
__global__ void __launch_bounds__(128, 4) k_proj_sk4(
    const float* __restrict__ hout, const float* __restrict__ aw1,
    float* __restrict__ P)
{
    extern __shared__ char sm[];
    int ks = blockIdx.x & 3, tile = blockIdx.x >> 2;
    gemm_core<32, 4, 1, 2, 2, 0>(hout + ks * 256, nullptr, aw1 + ks * 256,
                                 Hh, Hh, 0, 256, nullptr,
                                 P + (long)ks * 128 * HH2, HH2, tile * 32, sm,
                                 nullptr, nullptr, 0, 0);
}

// fc1 split-K=4 over cat=[ctx|hout]: quarters 0,1 from ctx, 2,3 from hout.
// BN=32. grid = 128. partials g_gates.
__global__ void __launch_bounds__(128, 4) k_fc1_sk4(
    const float* __restrict__ ctx, const float* __restrict__ hout,
    const float* __restrict__ f1w, float* __restrict__ P)
{
    extern __shared__ char sm[];
    int ks = blockIdx.x & 3, tile = blockIdx.x >> 2;
    const float* A = (ks < 2) ? (ctx + ks * 512) : (hout + (ks - 2) * 512);
    gemm_core<32, 4, 1, 2, 2, 0>(A, nullptr, f1w + ks * 512,
                                 Hh, 2 * Hh, 0, 512, nullptr,
                                 P + (long)ks * 128 * Hh, Hh, tile * 32, sm,
                                 nullptr, nullptr, 0, 0);
}

// fc2: BN=128, 256 threads, WN=2, NST=3, fused softmax partials. grid = 250.
__global__ void __launch_bounds__(256, 2) k_fc2(
    const float* __restrict__ o2, const float* __restrict__ f2w,
    const float* __restrict__ f2b, float* __restrict__ y,
    float* __restrict__ Pm, float* __restrict__ Ps)
{
    extern __shared__ char sm[];
    gemm_core<128, 8, 2, 3, 0, 1>(o2, nullptr, f2w, Hh, Hh, 0, Hh, f2b,
                                  y, Vv, blockIdx.x * 128, sm, Pm, Ps,
                                  blockIdx.x * 2, NT2);
}

// ---------------------------------------------------------------------------
// LSTM cell 0 (scalar, 4x warps): gates = x-ks0 + x-ks1 + h-ks0 + h-ks1 + bih + bhh
__global__ void k_lstm_cell(const float* __restrict__ p0, const float* __restrict__ p1,
                            const float* __restrict__ bi, const float* __restrict__ bh,
                            const float* __restrict__ c_prev,
                            float* __restrict__ c_out, float* __restrict__ h_out) {
    int i = blockIdx.x * 256 + threadIdx.x;   // B*H (131072 threads)
    int b = i >> 10, h = i & 1023;
    long base = (long)b * 4 * Hh + h;
    float gate[4];
    #pragma unroll
    for (int gi = 0; gi < 4; gi++) {
        long off = base + gi * Hh;
        gate[gi] = p0[off] + p0[SLAB + off] + p1[off] + p1[SLAB + off]
                 + bi[gi * Hh + h] + bh[gi * Hh + h];
    }
    float cp = c_prev[i];
    float c = sigm(gate[1]) * cp + sigm(gate[0]) * tanhf(gate[2]);
    c_out[i] = c;
    h_out[i] = sigm(gate[3]) * tanhf(c);
}

// LSTM cell 1 (scalar, 4x warps): gates = sum of 6 slabs + bih + bhh
__global__ void k_lstm_cell6(const float* __restrict__ P,
                             const float* __restrict__ bi, const float* __restrict__ bh,
                             const float* __restrict__ c_prev,
                             float* __restrict__ c_out, float* __restrict__ h_out) {
    int i = blockIdx.x * 256 + threadIdx.x;   // B*H
    int b = i >> 10, h = i & 1023;
    long base = (long)b * 4 * Hh + h;
    float gate[4];
    #pragma unroll
    for (int gi = 0; gi < 4; gi++) {
        long off = base + gi * Hh;
        float v = P[off];
        #pragma unroll
        for (int sl = 1; sl < 6; sl++) v += P[(long)sl * SLAB + off];
        gate[gi] = v + bi[gi * Hh + h] + bh[gi * Hh + h];
    }
    float cp = c_prev[i];
    float c = sigm(gate[1]) * cp + sigm(gate[0]) * tanhf(gate[2]);
    c_out[i] = c;
    h_out[i] = sigm(gate[3]) * tanhf(c);
}

// ---------------------------------------------------------------------------
// 4-partial combine with tanh (fc1), scalar
__global__ void k_comb4_tanh(const float* __restrict__ P, const float* __restrict__ bias,
                             float* __restrict__ out, int N) {
    int i = blockIdx.x * 256 + threadIdx.x;   // over 128*N
    long s = (long)128 * N;
    int h = i % N;
    out[i] = tanhf(P[i] + P[s + i] + P[2 * s + i] + P[3 * s + i] + bias[h]);
}

// ---------------------------------------------------------------------------
// Fused attn position: combine 4 proj partials + bias, tanh, dot w2, sigmoid -> pb
__global__ void k_attnpos(const float* __restrict__ P, const float* __restrict__ ab1,
                          const float* __restrict__ w2, const float* __restrict__ b2,
                          int S) {
    int b = blockIdx.x, tid = threadIdx.x;
    long s = (long)128 * HH2;
    long row = (long)b * HH2;
    __shared__ float red[4];
    float acc = 0.0f;
    #pragma unroll
    for (int jj = 0; jj < HH2 / 128; jj++) {
        int j = tid + jj * 128;
        float v = P[row + j] + P[s + row + j] + P[2 * s + row + j] + P[3 * s + row + j]
                + ab1[j];
        acc += tanhf(v) * w2[j];
    }
    #pragma unroll
    for (int o = 16; o > 0; o >>= 1) acc += __shfl_xor_sync(~0u, acc, o);
    if ((tid & 31) == 0) red[tid >> 5] = acc;
    __syncthreads();
    if (tid == 0)
        g_pb[b] = (float)S * sigm(red[0] + red[1] + red[2] + red[3] + b2[0]);
}

// ---------------------------------------------------------------------------
// Windowed attention (512 threads): scores, softmax*gauss, a, ctx
__global__ void k_attn_ctx(const float* __restrict__ hout, const float* __restrict__ enc,
                           int S, float* __restrict__ a_out) {
    int b = blockIdx.x, tid = threadIdx.x;
    int warp = tid >> 5, lane = tid & 31;
    float pb = g_pb[b];
    int ws = (int)rintf(fmaxf(pb - WSZF, 0.0f));
    int we = (int)rintf(fminf(pb + WSZF, (float)(S - 1)));
    __shared__ float sc[MAXW], ga[MAXW], aa[MAXW];

    for (int w = warp; w < MAXW; w += 16) {
        int idx = ws + w;
        if (idx <= we) {
            int ic = min(idx, S - 1);
            const float* er = enc + ((long)ic * Bb + b) * Hh;
            const float* orow = hout + (long)b * Hh;
            float dot = 0.0f;
            for (int h = lane; h < Hh; h += 32) dot += orow[h] * er[h];
            #pragma unroll
            for (int o = 16; o > 0; o >>= 1) dot += __shfl_down_sync(0xffffffff, dot, o);
            if (lane == 0) {
                sc[w] = dot;
                ga[w] = expf(((float)idx - pb) / 50.0f);
            }
        } else if (lane == 0) {
            sc[w] = 0.0f;
            ga[w] = 0.0f;
        }
    }
    __syncthreads();
    if (tid < MAXW) {
        float m = -1e30f;
        for (int w = 0; w < MAXW; w++) m = fmaxf(m, sc[w]);
        float den = 0.0f;
        for (int w = 0; w < MAXW; w++) den += expf(sc[w] - m);
        float a = expf(sc[tid] - m) / den * ga[tid];
        aa[tid] = a;
        a_out[b * MAXW + tid] = a;
    }
    __syncthreads();
    for (int h = tid; h < Hh; h += blockDim.x) {
        float s = 0.0f;
        for (int w = 0; w < MAXW; w++) {
            int idx = ws + w;
            if (idx <= we)
                s += aa[w] * enc[((long)idx * Bb + b) * Hh + h];
        }
        g_ctx[b * Hh + h] = s;
    }
}

// ---------------------------------------------------------------------------
// Merge fc2 per-slot (m,s) partials -> lse[row]
__global__ void k_ls_merge() {
    int row = blockIdx.x, tid = threadIdx.x;   // 128 threads
    int lane = tid & 31, w = tid >> 5;
    __shared__ float rm[4], rs[4];
    float m = -1e30f, s = 0.0f;
    for (int t = tid; t < NT2; t += 128)
        msmerge(m, s, g_pm[(long)row * NT2 + t], g_ps[(long)row * NT2 + t]);
    #pragma unroll
    for (int o = 16; o > 0; o >>= 1)
        msmerge(m, s, __shfl_xor_sync(~0u, m, o), __shfl_xor_sync(~0u, s, o));
    if (lane == 0) { rm[w] = m; rs[w] = s; }
    __syncthreads();
    if (tid == 0) {
        m = rm[0]; s = rs[0];
        msmerge(m, s, rm[1], rs[1]);
        msmerge(m, s, rm[2], rs[2]);
        msmerge(m, s, rm[3], rs[3]);
        g_lse[row] = m + logf(s);
    }
}

// Subtract lse in-place
__global__ void k_ls_sub(float* __restrict__ y) {
    long i = ((long)blockIdx.x * 256 + threadIdx.x) * 4;
    int row = (int)(i / Vv);
    float lse = g_lse[row];
    float4 v = *(const float4*)(y + i);
    v.x -= lse; v.y -= lse; v.z -= lse; v.w -= lse;
    *(float4*)(y + i) = v;
}

// ---------------------------------------------------------------------------
extern "C" void kernel_launch(void* const* d_in, const int* in_sizes, int n_in,
                              void* d_out, int out_size) {
    const float* enc  = (const float*)d_in[1];
    const int*   word = (const int*)  d_in[2];
    const float* h0   = (const float*)d_in[3];
    const float* c0   = (const float*)d_in[4];
    const float* emb  = (const float*)d_in[5];
    const float* Wih  = (const float*)d_in[6];
    const float* Whh  = (const float*)d_in[7];
    const float* bih  = (const float*)d_in[8];
    const float* bhh  = (const float*)d_in[9];
    const float* aw1  = (const float*)d_in[10];
    const float* ab1  = (const float*)d_in[11];
    const float* aw2  = (const float*)d_in[12];
    const float* ab2  = (const float*)d_in[13];
    const float* f1w  = (const float*)d_in[14];
    const float* f1b  = (const float*)d_in[15];
    const float* f2w  = (const float*)d_in[16];
    const float* f2b  = (const float*)d_in[17];

    int S = in_sizes[1] / (Bb * Hh);

    float* out = (float*)d_out;
    float* y   = out + Y_OFF;
    float* o2  = out + O2_OFF;
    float* hN  = out + H_OFF;
    float* cN  = out + C_OFF;
    float* aO  = out + A_OFF;

    const int SZ32   = 2 * (128 + 32) * 128;    // 40960
    const int SZ64G  = 2 * (128 + 64) * 128;    // 49152
    const int SZ128F = 3 * (128 + 128) * 128;   // 98304

    static float *p_g0 = nullptr, *p_g1 = nullptr, *p_ctx = nullptr,
                 *p_pm = nullptr, *p_ps = nullptr;
    static bool inited = false;
    if (!inited) {
        cudaGetSymbolAddress((void**)&p_g0,  g_gates);
        cudaGetSymbolAddress((void**)&p_g1,  g_gates2);
        cudaGetSymbolAddress((void**)&p_ctx, g_ctx);
        cudaGetSymbolAddress((void**)&p_pm,  g_pm);
        cudaGetSymbolAddress((void**)&p_ps,  g_ps);
        cudaFuncSetAttribute(k_mega_gates, cudaFuncAttributeMaxDynamicSharedMemorySize, SZ64G);
        cudaFuncSetAttribute(k_gates_x1,   cudaFuncAttributeMaxDynamicSharedMemorySize, SZ64G);
        cudaFuncSetAttribute(k_proj_sk4,   cudaFuncAttributeMaxDynamicSharedMemorySize, SZ32);
        cudaFuncSetAttribute(k_fc1_sk4,    cudaFuncAttributeMaxDynamicSharedMemorySize, SZ32);
        cudaFuncSetAttribute(k_fc2,        cudaFuncAttributeMaxDynamicSharedMemorySize, SZ128F);
        inited = true;
    }

    const float* h_l0 = hN;                        // layer-0 h output
    const float* hout = hN + (long)Bb * Hh;        // layer-1 h output ("out")

    // 1. mega gates: L0-x (embed fused), L0-h, L1-h — one 384-CTA launch
    k_mega_gates<<<384, 128, SZ64G>>>(emb, word,
                                      h0, Wih, Whh,
                                      h0 + (long)Bb * Hh, Whh + (long)4 * Hh * Hh,
                                      p_g0, p_g1);
    // 2. cell 0 (scalar, 512 CTAs)
    k_lstm_cell<<<Bb * Hh / 256, 256>>>(p_g0, p_g0 + 2 * (long)SLAB,
                                        bih, bhh, c0, cN, hN);
    // 3. L1-x gates (split-K4) + cell 1 (6 partial slabs, scalar)
    k_gates_x1<<<256, 128, SZ64G>>>(h_l0, Wih + (long)4 * Hh * Hh, p_g1);
    k_lstm_cell6<<<Bb * Hh / 256, 256>>>(p_g1,
                                         bih + 4 * Hh, bhh + 4 * Hh,
                                         c0 + (long)Bb * Hh,
                                         cN + (long)Bb * Hh,
                                         hN + (long)Bb * Hh);

    // 4. attention position: proj split-K4 + fused combine/dot/sigmoid
    k_proj_sk4<<<64, 128, SZ32>>>(hout, aw1, p_g1);
    k_attnpos<<<Bb, 128>>>(p_g1, ab1, aw2, ab2, S);

    // 5. windowed attention -> a, ctx
    k_attn_ctx<<<Bb, 512>>>(hout, enc, S, aO);

    // 6. fc1 split-K4 over [ctx|hout] + tanh-combine (scalar) -> o2
    k_fc1_sk4<<<128, 128, SZ32>>>(p_ctx, hout, f1w, p_g0);
    k_comb4_tanh<<<Bb * Hh / 256, 256>>>(p_g0, f1b, o2, Hh);

    // 7. fc2 (BN=128, fused softmax partials) + merge + subtract
    k_fc2<<<Vv / 128, 256, SZ128F>>>(o2, f2w, f2b, y, p_pm, p_ps);
    k_ls_merge<<<Bb, 128>>>();
    k_ls_sub<<<Bb * Vv / 1024, 256>>>(y);
}